// round 1
// baseline (speedup 1.0000x reference)
#include <cuda_runtime.h>
#include <math.h>

#define S_LEN 1024
#define BATCH 2
#define HIDV  2048
#define NH    16
#define HD    128
#define RR    64
#define KVC   512
#define QCV   1536
#define NTOK  (BATCH*S_LEN)   /* 2048 */

// ---------------- scratch (static device globals; no allocation) ----------------
__device__ float g_K [NTOK*(size_t)HIDV];             // 16 MB  [tok, h*128+d]
__device__ float g_V [NTOK*(size_t)HIDV];             // 16 MB
__device__ float g_CQ[NTOK*(size_t)QCV];              // 12 MB
__device__ float g_Q [NTOK*(size_t)HIDV];             // 16 MB
__device__ float g_S [(size_t)BATCH*NH*S_LEN*S_LEN];  // 128 MB scores/probs
__device__ float g_A [NTOK*(size_t)HIDV];             // 16 MB  attn output pre-W_O

// ---------------------------------------------------------------------------
// Generic tiled SGEMM:  C = alpha * A @ op(B) + bias
//   A: M x K, row-major, leading dim lda
//   op(B): bTrans=1 -> B is N x K (weights, x@W^T);  bTrans=0 -> B is K x N
//   batched over blockIdx.z: z -> (b = z/nH, h = z%nH); per-(b,h) pointer offsets.
// Tile: 64x64, BK=16, 256 threads, 4x4 per thread. All dims multiples of 64/16.
// ---------------------------------------------------------------------------
__global__ void __launch_bounds__(256)
gemm64(const float* __restrict__ A, const float* __restrict__ B,
       const float* __restrict__ bias, float* __restrict__ C,
       int M, int N, int K, int lda, int ldb, int ldc,
       int nH, long strA_b, long strA_h, long strB_b, long strB_h,
       long strC_b, long strC_h, int bTrans, float alpha)
{
    int z  = blockIdx.z;
    int bb = z / nH, hh = z % nH;
    A += (long)bb*strA_b + (long)hh*strA_h;
    B += (long)bb*strB_b + (long)hh*strB_h;
    C += (long)bb*strC_b + (long)hh*strC_h;

    __shared__ float As[16][64];
    __shared__ float Bs[16][64];

    int tid = threadIdx.x;
    int tx = tid & 15, ty = tid >> 4;
    int m0 = blockIdx.y * 64, n0 = blockIdx.x * 64;

    float acc[4][4] = {};

    for (int k0 = 0; k0 < K; k0 += 16) {
        // A tile -> As[kk][m]   (each thread: 4 consecutive kk of one m row)
        #pragma unroll
        for (int i = 0; i < 4; i++) {
            int e = tid * 4 + i;
            int m = e >> 4, kk = e & 15;
            As[kk][m] = A[(long)(m0 + m) * lda + k0 + kk];
        }
        // B tile -> Bs[kk][n]
        if (bTrans) {
            #pragma unroll
            for (int i = 0; i < 4; i++) {
                int e = tid * 4 + i;
                int n = e >> 4, kk = e & 15;
                Bs[kk][n] = B[(long)(n0 + n) * ldb + k0 + kk];
            }
        } else {
            #pragma unroll
            for (int i = 0; i < 4; i++) {
                int e = tid + 256 * i;
                int kk = e >> 6, n = e & 63;
                Bs[kk][n] = B[(long)(k0 + kk) * ldb + n0 + n];
            }
        }
        __syncthreads();

        #pragma unroll
        for (int kk = 0; kk < 16; kk++) {
            float a[4], bv[4];
            #pragma unroll
            for (int i = 0; i < 4; i++) a[i]  = As[kk][ty * 4 + i];
            #pragma unroll
            for (int j = 0; j < 4; j++) bv[j] = Bs[kk][tx * 4 + j];
            #pragma unroll
            for (int i = 0; i < 4; i++)
                #pragma unroll
                for (int j = 0; j < 4; j++)
                    acc[i][j] += a[i] * bv[j];
        }
        __syncthreads();
    }

    #pragma unroll
    for (int i = 0; i < 4; i++) {
        int m = m0 + ty * 4 + i;
        #pragma unroll
        for (int j = 0; j < 4; j++) {
            int n = n0 + tx * 4 + j;
            float v = acc[i][j] * alpha;
            if (bias) v += bias[n];
            C[(long)m * ldc + n] = v;
        }
    }
}

// ---------------------------------------------------------------------------
// k_r = RoPE( k[t,h,:] @ W_KR^T + b_KR )   -> out[t, h, 0..63]
// One block per (token, head), 64 threads (one per R output).
// ---------------------------------------------------------------------------
__global__ void __launch_bounds__(64)
kr_rope(const float* __restrict__ Kbuf, const float* __restrict__ Wkr,
        const float* __restrict__ bkr, float* __restrict__ out)
{
    int bid = blockIdx.x;
    int t = bid / NH, h = bid % NH;
    int s = t % S_LEN;                     // position within sequence
    __shared__ float kv[128];
    __shared__ float kr[64];
    int tid = threadIdx.x;

    kv[tid]      = Kbuf[(long)t * HIDV + h * HD + tid];
    kv[tid + 64] = Kbuf[(long)t * HIDV + h * HD + tid + 64];
    __syncthreads();

    float acc = bkr[tid];
    #pragma unroll 4
    for (int c = 0; c < 128; c++)
        acc += Wkr[tid * 128 + c] * kv[c];
    kr[tid] = acc;
    __syncthreads();

    // RoPE: cos/sin tables are concat([half, half]) -> freq index j = tid % 32
    int j = tid & 31;
    float inv_freq = expf(-(float)j * 0.28782313662425573f); // ln(10000)/32
    float f = (float)s * inv_freq;
    float sn, cs;
    sincosf(f, &sn, &cs);
    float rot = (tid < 32) ? -kr[tid + 32] : kr[tid - 32];
    out[(long)t * (NH * RR) + h * RR + tid] = kr[tid] * cs + rot * sn;
}

// ---------------------------------------------------------------------------
// Row softmax in place. One block (256 threads) per row of length ncols.
// ---------------------------------------------------------------------------
__global__ void __launch_bounds__(256)
softmax_rows(float* __restrict__ X, int ncols)
{
    long row = blockIdx.x;
    float* x = X + row * (long)ncols;
    __shared__ float red[256];
    int tid = threadIdx.x;

    float m = -1e30f;
    for (int c = tid; c < ncols; c += 256) m = fmaxf(m, x[c]);
    red[tid] = m; __syncthreads();
    for (int st = 128; st > 0; st >>= 1) {
        if (tid < st) red[tid] = fmaxf(red[tid], red[tid + st]);
        __syncthreads();
    }
    m = red[0]; __syncthreads();

    float sum = 0.f;
    for (int c = tid; c < ncols; c += 256) {
        float e = __expf(x[c] - m);
        x[c] = e;
        sum += e;
    }
    red[tid] = sum; __syncthreads();
    for (int st = 128; st > 0; st >>= 1) {
        if (tid < st) red[tid] += red[tid + st];
        __syncthreads();
    }
    float inv = 1.0f / red[0];
    for (int c = tid; c < ncols; c += 256) x[c] *= inv;
}

// ---------------------------------------------------------------------------
extern "C" void kernel_launch(void* const* d_in, const int* in_sizes, int n_in,
                              void* d_out, int out_size)
{
    const float* hid  = (const float*)d_in[0];
    const float* Wdkv = (const float*)d_in[1];
    const float* bdkv = (const float*)d_in[2];
    const float* Wuk  = (const float*)d_in[3];
    const float* buk  = (const float*)d_in[4];
    const float* Wuv  = (const float*)d_in[5];
    const float* buv  = (const float*)d_in[6];
    const float* Wkr  = (const float*)d_in[7];
    const float* bkr  = (const float*)d_in[8];
    const float* Wdq  = (const float*)d_in[9];
    const float* bdq  = (const float*)d_in[10];
    const float* Wuq  = (const float*)d_in[11];
    const float* buq  = (const float*)d_in[12];
    // d_in[13], d_in[14] = W_QR — dead in the reference (q_r unused), skipped.
    const float* Wo   = (const float*)d_in[15];
    const float* bo   = (const float*)d_in[16];

    float* out  = (float*)d_out;                       // [2048, 2048]
    float* c_kv = out  + (long)NTOK * HIDV;            // [2048, 512]
    float* kr   = c_kv + (long)NTOK * KVC;             // [2048, 16*64]

    float *pK, *pV, *pCQ, *pQ, *pS, *pA;
    cudaGetSymbolAddress((void**)&pK,  g_K);
    cudaGetSymbolAddress((void**)&pV,  g_V);
    cudaGetSymbolAddress((void**)&pCQ, g_CQ);
    cudaGetSymbolAddress((void**)&pQ,  g_Q);
    cudaGetSymbolAddress((void**)&pS,  g_S);
    cudaGetSymbolAddress((void**)&pA,  g_A);

    const float scale = 0.08838834764831845f;  // 1/sqrt(128)

    // 1. c_kv = hidden @ W_DKV^T + b    (2048 x 512, K=2048) -> directly into d_out
    gemm64<<<dim3(KVC/64, NTOK/64, 1), 256>>>(hid, Wdkv, bdkv, c_kv,
        NTOK, KVC, HIDV, HIDV, HIDV, KVC, 1,0,0,0,0,0,0, 1, 1.0f);

    // 2. k = c_kv @ W_UK^T + b          (2048 x 2048, K=512)
    gemm64<<<dim3(HIDV/64, NTOK/64, 1), 256>>>(c_kv, Wuk, buk, pK,
        NTOK, HIDV, KVC, KVC, KVC, HIDV, 1,0,0,0,0,0,0, 1, 1.0f);

    // 3. v = c_kv @ W_UV^T + b
    gemm64<<<dim3(HIDV/64, NTOK/64, 1), 256>>>(c_kv, Wuv, buv, pV,
        NTOK, HIDV, KVC, KVC, KVC, HIDV, 1,0,0,0,0,0,0, 1, 1.0f);

    // 4. c_q = hidden @ W_DQ^T + b      (2048 x 1536, K=2048)
    gemm64<<<dim3(QCV/64, NTOK/64, 1), 256>>>(hid, Wdq, bdq, pCQ,
        NTOK, QCV, HIDV, HIDV, HIDV, QCV, 1,0,0,0,0,0,0, 1, 1.0f);

    // 5. q = c_q @ W_UQ^T + b           (2048 x 2048, K=1536)
    gemm64<<<dim3(HIDV/64, NTOK/64, 1), 256>>>(pCQ, Wuq, buq, pQ,
        NTOK, HIDV, QCV, QCV, QCV, HIDV, 1,0,0,0,0,0,0, 1, 1.0f);

    // 6. k_r (+RoPE) -> d_out section
    kr_rope<<<NTOK * NH, 64>>>(pK, Wkr, bkr, kr);

    // 7. scores[b,h] = scale * q[b,:,h,:] @ k[b,:,h,:]^T   (32 batches of 1024x1024, K=128)
    gemm64<<<dim3(S_LEN/64, S_LEN/64, BATCH*NH), 256>>>(pQ, pK, nullptr, pS,
        S_LEN, S_LEN, HD, HIDV, HIDV, S_LEN,
        NH, (long)S_LEN*HIDV, (long)HD,
            (long)S_LEN*HIDV, (long)HD,
            (long)NH*S_LEN*S_LEN, (long)S_LEN*S_LEN, 1, scale);

    // 8. softmax rows
    softmax_rows<<<BATCH*NH*S_LEN, 256>>>(pS, S_LEN);

    // 9. attn[b,:,h,:] = probs[b,h] @ v[b,:,h,:]   (32 batches of 1024x128, K=1024)
    gemm64<<<dim3(HD/64, S_LEN/64, BATCH*NH), 256>>>(pS, pV, nullptr, pA,
        S_LEN, HD, S_LEN, S_LEN, HIDV, HIDV,
        NH, (long)NH*S_LEN*S_LEN, (long)S_LEN*S_LEN,
            (long)S_LEN*HIDV, (long)HD,
            (long)S_LEN*HIDV, (long)HD, 0, 1.0f);

    // 10. output = attn @ W_O^T + b  -> d_out[0:]
    gemm64<<<dim3(HIDV/64, NTOK/64, 1), 256>>>(pA, Wo, bo, out,
        NTOK, HIDV, HIDV, HIDV, HIDV, HIDV, 1,0,0,0,0,0,0, 1, 1.0f);
}

// round 2
// speedup vs baseline: 2.3368x; 2.3368x over previous
#include <cuda_runtime.h>
#include <math.h>

#define S_LEN 1024
#define BATCH 2
#define HIDV  2048
#define NH    16
#define HD    128
#define RR    64
#define KVC   512
#define QCV   1536
#define NTOK  (BATCH*S_LEN)   /* 2048 */

// ---------------- scratch (static device globals; no allocation) ----------------
__device__ float g_K [NTOK*(size_t)HIDV];             // 16 MB  [tok, h*128+d]
__device__ float g_V [NTOK*(size_t)HIDV];             // 16 MB
__device__ float g_CQ[NTOK*(size_t)QCV];              // 12 MB
__device__ float g_Q [NTOK*(size_t)HIDV];             // 16 MB
__device__ float g_S [(size_t)BATCH*NH*S_LEN*S_LEN];  // 128 MB scores/probs
__device__ float g_A [NTOK*(size_t)HIDV];             // 16 MB  attn output pre-W_O

__device__ __forceinline__ unsigned f2tf(float x) {
    unsigned u;
    asm("cvt.rna.tf32.f32 %0, %1;" : "=r"(u) : "f"(x));
    return u;
}

// ---------------------------------------------------------------------------
// Tensor-core TF32 GEMM:  C = alpha * A @ op(B) + bias
//   A: M x K row-major (lda). bTrans=1: B is N x K (x@W^T). bTrans=0: B is K x N.
//   Batched over blockIdx.z -> (b,h) with per-operand strides.
// Tile: 128x128x32, 256 threads (8 warps as 2x4), warp tile 64m x 32n.
// mma.sync.aligned.m16n8k8.row.col.f32.tf32.tf32.f32
// ---------------------------------------------------------------------------
#define BM 128
#define BN 128
#define BK 32
#define PAD 36   /* smem row stride in floats: (4*row+col)%32 hits all banks */

__global__ void __launch_bounds__(256)
gemm_tc(const float* __restrict__ A, const float* __restrict__ B,
        const float* __restrict__ bias, float* __restrict__ C,
        int M, int N, int K, int lda, int ldb, int ldc,
        int nH, long strA_b, long strA_h, long strB_b, long strB_h,
        long strC_b, long strC_h, int bTrans, float alpha)
{
    int z  = blockIdx.z;
    int bb = z / nH, hh = z % nH;
    A += (long)bb*strA_b + (long)hh*strA_h;
    B += (long)bb*strB_b + (long)hh*strB_h;
    C += (long)bb*strC_b + (long)hh*strC_h;

    __shared__ unsigned As[BM * PAD];
    __shared__ unsigned Bs[BN * PAD];

    int tid  = threadIdx.x;
    int warp = tid >> 5, lane = tid & 31;
    int wm = (warp >> 2) * 64;      // warp m-offset (2 rows of warps)
    int wn = (warp & 3) * 32;       // warp n-offset (4 cols of warps)
    int g  = lane >> 2, tg = lane & 3;

    int m0 = blockIdx.y * BM, n0 = blockIdx.x * BN;

    float acc[4][4][4];             // [m-frag][n-frag][c0..c3]
    #pragma unroll
    for (int i = 0; i < 4; i++)
        #pragma unroll
        for (int j = 0; j < 4; j++)
            #pragma unroll
            for (int r = 0; r < 4; r++) acc[i][j][r] = 0.f;

    int arow = tid >> 3;            // 0..31
    int ac4  = (tid & 7) * 4;       // 0..28

    for (int k0 = 0; k0 < K; k0 += BK) {
        // ---- A tile: 128x32, row-major, float4 loads, cvt->tf32, STS ----
        #pragma unroll
        for (int r = 0; r < 4; r++) {
            int row = arow + r * 32;
            float4 v = *(const float4*)&A[(long)(m0 + row) * lda + k0 + ac4];
            unsigned* d = &As[row * PAD + ac4];
            d[0] = f2tf(v.x); d[1] = f2tf(v.y); d[2] = f2tf(v.z); d[3] = f2tf(v.w);
        }
        // ---- B tile -> Bs[n][k] ----
        if (bTrans) {
            #pragma unroll
            for (int r = 0; r < 4; r++) {
                int row = arow + r * 32;   // n index
                float4 v = *(const float4*)&B[(long)(n0 + row) * ldb + k0 + ac4];
                unsigned* d = &Bs[row * PAD + ac4];
                d[0] = f2tf(v.x); d[1] = f2tf(v.y); d[2] = f2tf(v.z); d[3] = f2tf(v.w);
            }
        } else {
            int bn4 = (tid & 31) * 4;      // n group
            int bk  = tid >> 5;            // k row 0..7
            #pragma unroll
            for (int r = 0; r < 4; r++) {
                int kk = bk + r * 8;
                float4 v = *(const float4*)&B[(long)(k0 + kk) * ldb + n0 + bn4];
                Bs[(bn4 + 0) * PAD + kk] = f2tf(v.x);
                Bs[(bn4 + 1) * PAD + kk] = f2tf(v.y);
                Bs[(bn4 + 2) * PAD + kk] = f2tf(v.z);
                Bs[(bn4 + 3) * PAD + kk] = f2tf(v.w);
            }
        }
        __syncthreads();

        // ---- 4 k-steps of 8, 16 mmas each ----
        #pragma unroll
        for (int ks = 0; ks < 4; ks++) {
            int kb = ks * 8;
            unsigned a[4][4], b[4][2];
            #pragma unroll
            for (int i = 0; i < 4; i++) {
                int r0 = wm + i * 16 + g;
                a[i][0] = As[r0 * PAD + kb + tg];
                a[i][1] = As[(r0 + 8) * PAD + kb + tg];
                a[i][2] = As[r0 * PAD + kb + tg + 4];
                a[i][3] = As[(r0 + 8) * PAD + kb + tg + 4];
            }
            #pragma unroll
            for (int j = 0; j < 4; j++) {
                int c0 = wn + j * 8 + g;
                b[j][0] = Bs[c0 * PAD + kb + tg];
                b[j][1] = Bs[c0 * PAD + kb + tg + 4];
            }
            #pragma unroll
            for (int i = 0; i < 4; i++)
                #pragma unroll
                for (int j = 0; j < 4; j++) {
                    asm volatile(
                        "mma.sync.aligned.m16n8k8.row.col.f32.tf32.tf32.f32 "
                        "{%0,%1,%2,%3}, {%4,%5,%6,%7}, {%8,%9}, {%0,%1,%2,%3};"
                        : "+f"(acc[i][j][0]), "+f"(acc[i][j][1]),
                          "+f"(acc[i][j][2]), "+f"(acc[i][j][3])
                        : "r"(a[i][0]), "r"(a[i][1]), "r"(a[i][2]), "r"(a[i][3]),
                          "r"(b[j][0]), "r"(b[j][1]));
                }
        }
        __syncthreads();
    }

    // ---- epilogue ----
    #pragma unroll
    for (int i = 0; i < 4; i++) {
        int row0 = m0 + wm + i * 16 + g;
        #pragma unroll
        for (int j = 0; j < 4; j++) {
            int col = n0 + wn + j * 8 + tg * 2;
            float b0 = 0.f, b1 = 0.f;
            if (bias) { b0 = bias[col]; b1 = bias[col + 1]; }
            float2 v0 = make_float2(acc[i][j][0] * alpha + b0,
                                    acc[i][j][1] * alpha + b1);
            float2 v1 = make_float2(acc[i][j][2] * alpha + b0,
                                    acc[i][j][3] * alpha + b1);
            *(float2*)&C[(long)row0 * ldc + col]       = v0;
            *(float2*)&C[(long)(row0 + 8) * ldc + col] = v1;
        }
    }
}

// ---------------------------------------------------------------------------
// k_r = RoPE( k[t,h,:] @ W_KR^T + b_KR )   -> out[t, h, 0..63]
// ---------------------------------------------------------------------------
__global__ void __launch_bounds__(64)
kr_rope(const float* __restrict__ Kbuf, const float* __restrict__ Wkr,
        const float* __restrict__ bkr, float* __restrict__ out)
{
    int bid = blockIdx.x;
    int t = bid / NH, h = bid % NH;
    int s = t % S_LEN;
    __shared__ float kv[128];
    __shared__ float kr[64];
    int tid = threadIdx.x;

    kv[tid]      = Kbuf[(long)t * HIDV + h * HD + tid];
    kv[tid + 64] = Kbuf[(long)t * HIDV + h * HD + tid + 64];
    __syncthreads();

    float acc = bkr[tid];
    #pragma unroll 4
    for (int c = 0; c < 128; c++)
        acc += Wkr[tid * 128 + c] * kv[c];
    kr[tid] = acc;
    __syncthreads();

    int j = tid & 31;
    float inv_freq = expf(-(float)j * 0.28782313662425573f); // ln(10000)/32
    float f = (float)s * inv_freq;
    float sn, cs;
    sincosf(f, &sn, &cs);
    float rot = (tid < 32) ? -kr[tid + 32] : kr[tid - 32];
    out[(long)t * (NH * RR) + h * RR + tid] = kr[tid] * cs + rot * sn;
}

// ---------------------------------------------------------------------------
// Row softmax in place. One block (256 threads) per row.
// ---------------------------------------------------------------------------
__global__ void __launch_bounds__(256)
softmax_rows(float* __restrict__ X, int ncols)
{
    long row = blockIdx.x;
    float* x = X + row * (long)ncols;
    __shared__ float red[256];
    int tid = threadIdx.x;

    float m = -1e30f;
    for (int c = tid; c < ncols; c += 256) m = fmaxf(m, x[c]);
    red[tid] = m; __syncthreads();
    for (int st = 128; st > 0; st >>= 1) {
        if (tid < st) red[tid] = fmaxf(red[tid], red[tid + st]);
        __syncthreads();
    }
    m = red[0]; __syncthreads();

    float sum = 0.f;
    for (int c = tid; c < ncols; c += 256) {
        float e = __expf(x[c] - m);
        x[c] = e;
        sum += e;
    }
    red[tid] = sum; __syncthreads();
    for (int st = 128; st > 0; st >>= 1) {
        if (tid < st) red[tid] += red[tid + st];
        __syncthreads();
    }
    float inv = 1.0f / red[0];
    for (int c = tid; c < ncols; c += 256) x[c] *= inv;
}

// ---------------------------------------------------------------------------
extern "C" void kernel_launch(void* const* d_in, const int* in_sizes, int n_in,
                              void* d_out, int out_size)
{
    const float* hid  = (const float*)d_in[0];
    const float* Wdkv = (const float*)d_in[1];
    const float* bdkv = (const float*)d_in[2];
    const float* Wuk  = (const float*)d_in[3];
    const float* buk  = (const float*)d_in[4];
    const float* Wuv  = (const float*)d_in[5];
    const float* buv  = (const float*)d_in[6];
    const float* Wkr  = (const float*)d_in[7];
    const float* bkr  = (const float*)d_in[8];
    const float* Wdq  = (const float*)d_in[9];
    const float* bdq  = (const float*)d_in[10];
    const float* Wuq  = (const float*)d_in[11];
    const float* buq  = (const float*)d_in[12];
    // d_in[13], d_in[14] = W_QR — dead in the reference (q_r unused), skipped.
    const float* Wo   = (const float*)d_in[15];
    const float* bo   = (const float*)d_in[16];

    float* out  = (float*)d_out;                       // [2048, 2048]
    float* c_kv = out  + (long)NTOK * HIDV;            // [2048, 512]
    float* kr   = c_kv + (long)NTOK * KVC;             // [2048, 16*64]

    float *pK, *pV, *pCQ, *pQ, *pS, *pA;
    cudaGetSymbolAddress((void**)&pK,  g_K);
    cudaGetSymbolAddress((void**)&pV,  g_V);
    cudaGetSymbolAddress((void**)&pCQ, g_CQ);
    cudaGetSymbolAddress((void**)&pQ,  g_Q);
    cudaGetSymbolAddress((void**)&pS,  g_S);
    cudaGetSymbolAddress((void**)&pA,  g_A);

    const float scale = 0.08838834764831845f;  // 1/sqrt(128)

    // 1. c_kv = hidden @ W_DKV^T + b    (2048 x 512, K=2048) -> d_out section
    gemm_tc<<<dim3(KVC/BN, NTOK/BM, 1), 256>>>(hid, Wdkv, bdkv, c_kv,
        NTOK, KVC, HIDV, HIDV, HIDV, KVC, 1,0,0,0,0,0,0, 1, 1.0f);

    // 2. k = c_kv @ W_UK^T + b          (2048 x 2048, K=512)
    gemm_tc<<<dim3(HIDV/BN, NTOK/BM, 1), 256>>>(c_kv, Wuk, buk, pK,
        NTOK, HIDV, KVC, KVC, KVC, HIDV, 1,0,0,0,0,0,0, 1, 1.0f);

    // 3. v = c_kv @ W_UV^T + b
    gemm_tc<<<dim3(HIDV/BN, NTOK/BM, 1), 256>>>(c_kv, Wuv, buv, pV,
        NTOK, HIDV, KVC, KVC, KVC, HIDV, 1,0,0,0,0,0,0, 1, 1.0f);

    // 4. c_q = hidden @ W_DQ^T + b      (2048 x 1536, K=2048)
    gemm_tc<<<dim3(QCV/BN, NTOK/BM, 1), 256>>>(hid, Wdq, bdq, pCQ,
        NTOK, QCV, HIDV, HIDV, HIDV, QCV, 1,0,0,0,0,0,0, 1, 1.0f);

    // 5. q = c_q @ W_UQ^T + b           (2048 x 2048, K=1536)
    gemm_tc<<<dim3(HIDV/BN, NTOK/BM, 1), 256>>>(pCQ, Wuq, buq, pQ,
        NTOK, HIDV, QCV, QCV, QCV, HIDV, 1,0,0,0,0,0,0, 1, 1.0f);

    // 6. k_r (+RoPE) -> d_out section
    kr_rope<<<NTOK * NH, 64>>>(pK, Wkr, bkr, kr);

    // 7. scores[b,h] = scale * q[b,:,h,:] @ k[b,:,h,:]^T  (32 x [1024x1024], K=128)
    gemm_tc<<<dim3(S_LEN/BN, S_LEN/BM, BATCH*NH), 256>>>(pQ, pK, nullptr, pS,
        S_LEN, S_LEN, HD, HIDV, HIDV, S_LEN,
        NH, (long)S_LEN*HIDV, (long)HD,
            (long)S_LEN*HIDV, (long)HD,
            (long)NH*S_LEN*S_LEN, (long)S_LEN*S_LEN, 1, scale);

    // 8. softmax rows
    softmax_rows<<<BATCH*NH*S_LEN, 256>>>(pS, S_LEN);

    // 9. attn[b,:,h,:] = probs[b,h] @ v[b,:,h,:]   (32 x [1024x128], K=1024)
    gemm_tc<<<dim3(HD/BN, S_LEN/BM, BATCH*NH), 256>>>(pS, pV, nullptr, pA,
        S_LEN, HD, S_LEN, S_LEN, HIDV, HIDV,
        NH, (long)NH*S_LEN*S_LEN, (long)S_LEN*S_LEN,
            (long)S_LEN*HIDV, (long)HD,
            (long)S_LEN*HIDV, (long)HD, 0, 1.0f);

    // 10. output = attn @ W_O^T + b  -> d_out[0:]
    gemm_tc<<<dim3(HIDV/BN, NTOK/BM, 1), 256>>>(pA, Wo, bo, out,
        NTOK, HIDV, HIDV, HIDV, HIDV, HIDV, 1,0,0,0,0,0,0, 1, 1.0f);
}

// round 3
// speedup vs baseline: 2.4054x; 1.0294x over previous
#include <cuda_runtime.h>
#include <math.h>

#define S_LEN 1024
#define BATCH 2
#define HIDV  2048
#define NH    16
#define HD    128
#define RR    64
#define KVC   512
#define QCV   1536
#define NTOK  (BATCH*S_LEN)   /* 2048 */

// ---------------- scratch (static device globals; no allocation) ----------------
__device__ float g_K [NTOK*(size_t)HIDV];             // 16 MB
__device__ float g_V [NTOK*(size_t)HIDV];             // 16 MB
__device__ float g_CQ[NTOK*(size_t)QCV];              // 12 MB
__device__ float g_Q [NTOK*(size_t)HIDV];             // 16 MB
__device__ float g_A [NTOK*(size_t)HIDV];             // 16 MB  attn out pre-W_O

__device__ __forceinline__ unsigned f2tf(float x) {
    unsigned u;
    asm("cvt.rna.tf32.f32 %0, %1;" : "=r"(u) : "f"(x));
    return u;
}

#define MMA_TF32(d, a, b) \
    asm volatile("mma.sync.aligned.m16n8k8.row.col.f32.tf32.tf32.f32 " \
        "{%0,%1,%2,%3}, {%4,%5,%6,%7}, {%8,%9}, {%0,%1,%2,%3};" \
        : "+f"(d[0]), "+f"(d[1]), "+f"(d[2]), "+f"(d[3]) \
        : "r"(a[0]), "r"(a[1]), "r"(a[2]), "r"(a[3]), "r"(b[0]), "r"(b[1]))

// ---------------------------------------------------------------------------
// Tensor-core TF32 GEMM with register-prefetch double buffering.
// C = alpha * A @ op(B) + bias.  Tile 128x128x32, 256 thr, warp tile 64x32.
// ---------------------------------------------------------------------------
#define BM 128
#define BN 128
#define BK 32
#define PAD 36

__global__ void __launch_bounds__(256)
gemm_tc(const float* __restrict__ A, const float* __restrict__ B,
        const float* __restrict__ bias, float* __restrict__ C,
        int M, int N, int K, int lda, int ldb, int ldc,
        int nH, long strA_b, long strA_h, long strB_b, long strB_h,
        long strC_b, long strC_h, int bTrans, float alpha)
{
    int z  = blockIdx.z;
    int bb = z / nH, hh = z % nH;
    A += (long)bb*strA_b + (long)hh*strA_h;
    B += (long)bb*strB_b + (long)hh*strB_h;
    C += (long)bb*strC_b + (long)hh*strC_h;

    __shared__ unsigned As[BM * PAD];
    __shared__ unsigned Bs[BN * PAD];

    int tid  = threadIdx.x;
    int warp = tid >> 5, lane = tid & 31;
    int wm = (warp >> 2) * 64;
    int wn = (warp & 3) * 32;
    int g  = lane >> 2, tg = lane & 3;

    int m0 = blockIdx.y * BM, n0 = blockIdx.x * BN;

    float acc[4][4][4];
    #pragma unroll
    for (int i = 0; i < 4; i++)
        #pragma unroll
        for (int j = 0; j < 4; j++)
            #pragma unroll
            for (int r = 0; r < 4; r++) acc[i][j][r] = 0.f;

    int arow = tid >> 3;
    int ac4  = (tid & 7) * 4;
    int bn4  = (tid & 31) * 4;
    int bk   = tid >> 5;

    float4 pa[4], pb[4];
    // prefetch tile 0
    #pragma unroll
    for (int r = 0; r < 4; r++)
        pa[r] = *(const float4*)&A[(long)(m0 + arow + r*32) * lda + ac4];
    if (bTrans) {
        #pragma unroll
        for (int r = 0; r < 4; r++)
            pb[r] = *(const float4*)&B[(long)(n0 + arow + r*32) * ldb + ac4];
    } else {
        #pragma unroll
        for (int r = 0; r < 4; r++)
            pb[r] = *(const float4*)&B[(long)(bk + r*8) * ldb + n0 + bn4];
    }

    for (int k0 = 0; k0 < K; k0 += BK) {
        // commit prefetched tile to smem
        #pragma unroll
        for (int r = 0; r < 4; r++) {
            unsigned* d = &As[(arow + r*32) * PAD + ac4];
            d[0]=f2tf(pa[r].x); d[1]=f2tf(pa[r].y); d[2]=f2tf(pa[r].z); d[3]=f2tf(pa[r].w);
        }
        if (bTrans) {
            #pragma unroll
            for (int r = 0; r < 4; r++) {
                unsigned* d = &Bs[(arow + r*32) * PAD + ac4];
                d[0]=f2tf(pb[r].x); d[1]=f2tf(pb[r].y); d[2]=f2tf(pb[r].z); d[3]=f2tf(pb[r].w);
            }
        } else {
            #pragma unroll
            for (int r = 0; r < 4; r++) {
                int kk = bk + r*8;
                Bs[(bn4+0)*PAD + kk]=f2tf(pb[r].x);
                Bs[(bn4+1)*PAD + kk]=f2tf(pb[r].y);
                Bs[(bn4+2)*PAD + kk]=f2tf(pb[r].z);
                Bs[(bn4+3)*PAD + kk]=f2tf(pb[r].w);
            }
        }
        __syncthreads();

        // issue next tile's loads (overlap with MMAs)
        int kn = k0 + BK;
        if (kn < K) {
            #pragma unroll
            for (int r = 0; r < 4; r++)
                pa[r] = *(const float4*)&A[(long)(m0 + arow + r*32) * lda + kn + ac4];
            if (bTrans) {
                #pragma unroll
                for (int r = 0; r < 4; r++)
                    pb[r] = *(const float4*)&B[(long)(n0 + arow + r*32) * ldb + kn + ac4];
            } else {
                #pragma unroll
                for (int r = 0; r < 4; r++)
                    pb[r] = *(const float4*)&B[(long)(kn + bk + r*8) * ldb + n0 + bn4];
            }
        }

        #pragma unroll
        for (int ks = 0; ks < 4; ks++) {
            int kb = ks * 8;
            unsigned a[4][4], b[4][2];
            #pragma unroll
            for (int i = 0; i < 4; i++) {
                int r0 = wm + i * 16 + g;
                a[i][0] = As[r0 * PAD + kb + tg];
                a[i][1] = As[(r0 + 8) * PAD + kb + tg];
                a[i][2] = As[r0 * PAD + kb + tg + 4];
                a[i][3] = As[(r0 + 8) * PAD + kb + tg + 4];
            }
            #pragma unroll
            for (int j = 0; j < 4; j++) {
                int c0 = wn + j * 8 + g;
                b[j][0] = Bs[c0 * PAD + kb + tg];
                b[j][1] = Bs[c0 * PAD + kb + tg + 4];
            }
            #pragma unroll
            for (int i = 0; i < 4; i++)
                #pragma unroll
                for (int j = 0; j < 4; j++)
                    MMA_TF32(acc[i][j], a[i], b[j]);
        }
        __syncthreads();
    }

    #pragma unroll
    for (int i = 0; i < 4; i++) {
        int row0 = m0 + wm + i * 16 + g;
        #pragma unroll
        for (int j = 0; j < 4; j++) {
            int col = n0 + wn + j * 8 + tg * 2;
            float b0 = 0.f, b1 = 0.f;
            if (bias) { b0 = bias[col]; b1 = bias[col + 1]; }
            *(float2*)&C[(long)row0 * ldc + col] =
                make_float2(acc[i][j][0]*alpha + b0, acc[i][j][1]*alpha + b1);
            *(float2*)&C[(long)(row0 + 8) * ldc + col] =
                make_float2(acc[i][j][2]*alpha + b0, acc[i][j][3]*alpha + b1);
        }
    }
}

// ---------------------------------------------------------------------------
// Fused flash attention: per block = 128 q rows of one (b,h).
// S = (Q*scale) @ K^T (tiles of 64 kv), online softmax, O += P @ V.
// Non-causal, exact softmax over full S_LEN.
// smem (dynamic): Qs[128][132] | Ks[64][132] | Vs[64][132] | Ps[128][68]  (tf32)
// ---------------------------------------------------------------------------
#define QS_STR 132
#define PS_STR 68
#define FK 64
#define SM_Q 0
#define SM_K (SM_Q + 128*QS_STR)
#define SM_V (SM_K + FK*QS_STR)
#define SM_P (SM_V + FK*QS_STR)
#define SM_WORDS (SM_P + 128*PS_STR)   /* 42496 words = 169984 B */

__global__ void __launch_bounds__(256)
flash_attn(const float* __restrict__ Qg, const float* __restrict__ Kg,
           const float* __restrict__ Vg, float* __restrict__ Og, float scale)
{
    extern __shared__ unsigned sm[];
    unsigned* Qs = sm + SM_Q;
    unsigned* Ks = sm + SM_K;
    unsigned* Vs = sm + SM_V;
    unsigned* Ps = sm + SM_P;

    int tid = threadIdx.x;
    int warp = tid >> 5, lane = tid & 31;
    int g = lane >> 2, tg = lane & 3;
    int wm = warp * 16;

    int z  = blockIdx.y;
    int bb = z / NH, hh = z % NH;
    long tok0 = (long)bb * S_LEN + blockIdx.x * 128;   // first q token
    const float* Qb = Qg + tok0 * HIDV + hh * HD;
    const float* Kb = Kg + (long)bb * S_LEN * HIDV + hh * HD;
    const float* Vb = Vg + (long)bb * S_LEN * HIDV + hh * HD;

    // load Q tile (scaled) : 128 x 128
    #pragma unroll
    for (int i = 0; i < 16; i++) {
        int s = tid + i * 256;           // 4096 float4 slots
        int row = s >> 5, c4 = (s & 31) * 4;
        float4 v = *(const float4*)&Qb[(long)row * HIDV + c4];
        unsigned* d = &Qs[row * QS_STR + c4];
        d[0]=f2tf(v.x*scale); d[1]=f2tf(v.y*scale); d[2]=f2tf(v.z*scale); d[3]=f2tf(v.w*scale);
    }

    float m0 = -1e30f, m1 = -1e30f, l0 = 0.f, l1 = 0.f;
    float o[16][4];
    #pragma unroll
    for (int j = 0; j < 16; j++)
        #pragma unroll
        for (int r = 0; r < 4; r++) o[j][r] = 0.f;

    for (int kt = 0; kt < S_LEN / FK; kt++) {
        __syncthreads();   // prev iter done with Ks/Vs (also covers Q store, iter 0)
        // load K,V tiles (64 x 128 each)
        #pragma unroll
        for (int i = 0; i < 8; i++) {
            int s = tid + i * 256;       // 2048 slots
            int row = s >> 5, c4 = (s & 31) * 4;
            long goff = (long)(kt * FK + row) * HIDV + c4;
            float4 kv = *(const float4*)&Kb[goff];
            float4 vv = *(const float4*)&Vb[goff];
            unsigned* dk = &Ks[row * QS_STR + c4];
            unsigned* dv = &Vs[row * QS_STR + c4];
            dk[0]=f2tf(kv.x); dk[1]=f2tf(kv.y); dk[2]=f2tf(kv.z); dk[3]=f2tf(kv.w);
            dv[0]=f2tf(vv.x); dv[1]=f2tf(vv.y); dv[2]=f2tf(vv.z); dv[3]=f2tf(vv.w);
        }
        __syncthreads();

        // ---- S = Q @ K^T : warp rows wm..wm+15, cols 0..63 ----
        float s_acc[8][4];
        #pragma unroll
        for (int j = 0; j < 8; j++)
            #pragma unroll
            for (int r = 0; r < 4; r++) s_acc[j][r] = 0.f;

        #pragma unroll
        for (int ks = 0; ks < 16; ks++) {
            int kb = ks * 8;
            unsigned a[4];
            a[0] = Qs[(wm + g) * QS_STR + kb + tg];
            a[1] = Qs[(wm + 8 + g) * QS_STR + kb + tg];
            a[2] = Qs[(wm + g) * QS_STR + kb + tg + 4];
            a[3] = Qs[(wm + 8 + g) * QS_STR + kb + tg + 4];
            #pragma unroll
            for (int j = 0; j < 8; j++) {
                unsigned b[2];
                b[0] = Ks[(j * 8 + g) * QS_STR + kb + tg];
                b[1] = Ks[(j * 8 + g) * QS_STR + kb + tg + 4];
                MMA_TF32(s_acc[j], a, b);
            }
        }

        // ---- online softmax (rows wm+g, wm+8+g) ----
        float mx0 = -1e30f, mx1 = -1e30f;
        #pragma unroll
        for (int j = 0; j < 8; j++) {
            mx0 = fmaxf(mx0, fmaxf(s_acc[j][0], s_acc[j][1]));
            mx1 = fmaxf(mx1, fmaxf(s_acc[j][2], s_acc[j][3]));
        }
        mx0 = fmaxf(mx0, __shfl_xor_sync(0xffffffffu, mx0, 1));
        mx0 = fmaxf(mx0, __shfl_xor_sync(0xffffffffu, mx0, 2));
        mx1 = fmaxf(mx1, __shfl_xor_sync(0xffffffffu, mx1, 1));
        mx1 = fmaxf(mx1, __shfl_xor_sync(0xffffffffu, mx1, 2));

        float mn0 = fmaxf(m0, mx0), mn1 = fmaxf(m1, mx1);
        float al0 = __expf(m0 - mn0), al1 = __expf(m1 - mn1);
        float sum0 = 0.f, sum1 = 0.f;
        #pragma unroll
        for (int j = 0; j < 8; j++) {
            float p00 = __expf(s_acc[j][0] - mn0);
            float p01 = __expf(s_acc[j][1] - mn0);
            float p10 = __expf(s_acc[j][2] - mn1);
            float p11 = __expf(s_acc[j][3] - mn1);
            sum0 += p00 + p01; sum1 += p10 + p11;
            int col = j * 8 + tg * 2;
            Ps[(wm + g) * PS_STR + col]     = f2tf(p00);
            Ps[(wm + g) * PS_STR + col + 1] = f2tf(p01);
            Ps[(wm + 8 + g) * PS_STR + col]     = f2tf(p10);
            Ps[(wm + 8 + g) * PS_STR + col + 1] = f2tf(p11);
        }
        sum0 += __shfl_xor_sync(0xffffffffu, sum0, 1);
        sum0 += __shfl_xor_sync(0xffffffffu, sum0, 2);
        sum1 += __shfl_xor_sync(0xffffffffu, sum1, 1);
        sum1 += __shfl_xor_sync(0xffffffffu, sum1, 2);
        l0 = l0 * al0 + sum0;
        l1 = l1 * al1 + sum1;
        m0 = mn0; m1 = mn1;
        #pragma unroll
        for (int j = 0; j < 16; j++) {
            o[j][0] *= al0; o[j][1] *= al0;
            o[j][2] *= al1; o[j][3] *= al1;
        }
        __syncwarp();   // Ps visibility (warp-local rows)

        // ---- O += P @ V : k = 64 seq, n = 128 d ----
        #pragma unroll
        for (int ks = 0; ks < 8; ks++) {
            int kb = ks * 8;
            unsigned a[4];
            a[0] = Ps[(wm + g) * PS_STR + kb + tg];
            a[1] = Ps[(wm + 8 + g) * PS_STR + kb + tg];
            a[2] = Ps[(wm + g) * PS_STR + kb + tg + 4];
            a[3] = Ps[(wm + 8 + g) * PS_STR + kb + tg + 4];
            #pragma unroll
            for (int j = 0; j < 16; j++) {
                unsigned b[2];
                b[0] = Vs[(kb + tg) * QS_STR + j * 8 + g];
                b[1] = Vs[(kb + tg + 4) * QS_STR + j * 8 + g];
                MMA_TF32(o[j], a, b);
            }
        }
    }

    // ---- finalize & write to g_A [tok][h*128+d] ----
    float inv0 = 1.0f / l0, inv1 = 1.0f / l1;
    float* Ob = Og + tok0 * HIDV + hh * HD;
    #pragma unroll
    for (int j = 0; j < 16; j++) {
        int col = j * 8 + tg * 2;
        *(float2*)&Ob[(long)(wm + g) * HIDV + col] =
            make_float2(o[j][0] * inv0, o[j][1] * inv0);
        *(float2*)&Ob[(long)(wm + 8 + g) * HIDV + col] =
            make_float2(o[j][2] * inv1, o[j][3] * inv1);
    }
}

// ---------------------------------------------------------------------------
__global__ void __launch_bounds__(64)
kr_rope(const float* __restrict__ Kbuf, const float* __restrict__ Wkr,
        const float* __restrict__ bkr, float* __restrict__ out)
{
    int bid = blockIdx.x;
    int t = bid / NH, h = bid % NH;
    int s = t % S_LEN;
    __shared__ float kv[128];
    __shared__ float kr[64];
    int tid = threadIdx.x;

    kv[tid]      = Kbuf[(long)t * HIDV + h * HD + tid];
    kv[tid + 64] = Kbuf[(long)t * HIDV + h * HD + tid + 64];
    __syncthreads();

    float acc = bkr[tid];
    #pragma unroll 4
    for (int c = 0; c < 128; c++)
        acc += Wkr[tid * 128 + c] * kv[c];
    kr[tid] = acc;
    __syncthreads();

    int j = tid & 31;
    float inv_freq = expf(-(float)j * 0.28782313662425573f); // ln(10000)/32
    float f = (float)s * inv_freq;
    float sn, cs;
    sincosf(f, &sn, &cs);
    float rot = (tid < 32) ? -kr[tid + 32] : kr[tid - 32];
    out[(long)t * (NH * RR) + h * RR + tid] = kr[tid] * cs + rot * sn;
}

// ---------------------------------------------------------------------------
extern "C" void kernel_launch(void* const* d_in, const int* in_sizes, int n_in,
                              void* d_out, int out_size)
{
    const float* hid  = (const float*)d_in[0];
    const float* Wdkv = (const float*)d_in[1];
    const float* bdkv = (const float*)d_in[2];
    const float* Wuk  = (const float*)d_in[3];
    const float* buk  = (const float*)d_in[4];
    const float* Wuv  = (const float*)d_in[5];
    const float* buv  = (const float*)d_in[6];
    const float* Wkr  = (const float*)d_in[7];
    const float* bkr  = (const float*)d_in[8];
    const float* Wdq  = (const float*)d_in[9];
    const float* bdq  = (const float*)d_in[10];
    const float* Wuq  = (const float*)d_in[11];
    const float* buq  = (const float*)d_in[12];
    // d_in[13..14] = W_QR — dead in the reference (q_r unused)
    const float* Wo   = (const float*)d_in[15];
    const float* bo   = (const float*)d_in[16];

    float* out  = (float*)d_out;
    float* c_kv = out  + (long)NTOK * HIDV;
    float* kr   = c_kv + (long)NTOK * KVC;

    float *pK, *pV, *pCQ, *pQ, *pA;
    cudaGetSymbolAddress((void**)&pK,  g_K);
    cudaGetSymbolAddress((void**)&pV,  g_V);
    cudaGetSymbolAddress((void**)&pCQ, g_CQ);
    cudaGetSymbolAddress((void**)&pQ,  g_Q);
    cudaGetSymbolAddress((void**)&pA,  g_A);

    const float scale = 0.08838834764831845f;  // 1/sqrt(128)
    static int smem_set = 0;
    if (!smem_set) {
        cudaFuncSetAttribute(flash_attn,
            cudaFuncAttributeMaxDynamicSharedMemorySize, SM_WORDS * 4);
        smem_set = 1;
    }

    // 1. c_kv = hidden @ W_DKV^T + b
    gemm_tc<<<dim3(KVC/BN, NTOK/BM, 1), 256>>>(hid, Wdkv, bdkv, c_kv,
        NTOK, KVC, HIDV, HIDV, HIDV, KVC, 1,0,0,0,0,0,0, 1, 1.0f);

    // 2. k = c_kv @ W_UK^T + b
    gemm_tc<<<dim3(HIDV/BN, NTOK/BM, 1), 256>>>(c_kv, Wuk, buk, pK,
        NTOK, HIDV, KVC, KVC, KVC, HIDV, 1,0,0,0,0,0,0, 1, 1.0f);

    // 3. v = c_kv @ W_UV^T + b
    gemm_tc<<<dim3(HIDV/BN, NTOK/BM, 1), 256>>>(c_kv, Wuv, buv, pV,
        NTOK, HIDV, KVC, KVC, KVC, HIDV, 1,0,0,0,0,0,0, 1, 1.0f);

    // 4. c_q = hidden @ W_DQ^T + b
    gemm_tc<<<dim3(QCV/BN, NTOK/BM, 1), 256>>>(hid, Wdq, bdq, pCQ,
        NTOK, QCV, HIDV, HIDV, HIDV, QCV, 1,0,0,0,0,0,0, 1, 1.0f);

    // 5. q = c_q @ W_UQ^T + b
    gemm_tc<<<dim3(HIDV/BN, NTOK/BM, 1), 256>>>(pCQ, Wuq, buq, pQ,
        NTOK, HIDV, QCV, QCV, QCV, HIDV, 1,0,0,0,0,0,0, 1, 1.0f);

    // 6. k_r (+RoPE)
    kr_rope<<<NTOK * NH, 64>>>(pK, Wkr, bkr, kr);

    // 7-9. fused flash attention -> g_A
    flash_attn<<<dim3(S_LEN/128, BATCH*NH), 256, SM_WORDS * 4>>>(
        pQ, pK, pV, pA, scale);

    // 10. output = attn @ W_O^T + b
    gemm_tc<<<dim3(HIDV/BN, NTOK/BM, 1), 256>>>(pA, Wo, bo, out,
        NTOK, HIDV, HIDV, HIDV, HIDV, HIDV, 1,0,0,0,0,0,0, 1, 1.0f);
}

// round 4
// speedup vs baseline: 2.4605x; 1.0229x over previous
#include <cuda_runtime.h>
#include <math.h>

#define S_LEN 1024
#define BATCH 2
#define HIDV  2048
#define NH    16
#define HD    128
#define RR    64
#define KVC   512
#define QCV   1536
#define NTOK  (BATCH*S_LEN)   /* 2048 */

// ---------------- scratch (static device globals; no allocation) ----------------
__device__ float g_K [NTOK*(size_t)HIDV];
__device__ float g_V [NTOK*(size_t)HIDV];
__device__ float g_CQ[NTOK*(size_t)QCV];
__device__ float g_Q [NTOK*(size_t)HIDV];
__device__ float g_A [NTOK*(size_t)HIDV];

__device__ __forceinline__ unsigned f2tf(float x) {
    unsigned u;
    asm("cvt.rna.tf32.f32 %0, %1;" : "=r"(u) : "f"(x));
    return u;
}

#define MMA_TF32(d, a, b) \
    asm volatile("mma.sync.aligned.m16n8k8.row.col.f32.tf32.tf32.f32 " \
        "{%0,%1,%2,%3}, {%4,%5,%6,%7}, {%8,%9}, {%0,%1,%2,%3};" \
        : "+f"(d[0]), "+f"(d[1]), "+f"(d[2]), "+f"(d[3]) \
        : "r"(a[0]), "r"(a[1]), "r"(a[2]), "r"(a[3]), "r"(b[0]), "r"(b[1]))

#define CP_ASYNC16(dst_sm, src) \
    asm volatile("cp.async.cg.shared.global [%0], [%1], 16;" \
        :: "r"(dst_sm), "l"(src))
#define CP_COMMIT() asm volatile("cp.async.commit_group;" ::: "memory")
#define CP_WAIT(n)  asm volatile("cp.async.wait_group %0;" :: "n"(n) : "memory")

// ---------------------------------------------------------------------------
// TF32 GEMM, weights transposed only:  C = A @ B^T + bias
//   A: M x K (lda), B: N x K (ldb), C: M x N (ldc).
// Tile 128x128x32, 256 threads, warp tile 64x32, cp.async 3-stage pipeline.
// smem holds raw fp32; cvt->tf32 at fragment load.
// ---------------------------------------------------------------------------
#define BM 128
#define BN 128
#define BK 32
#define TPAD 36
#define TILE_WORDS (128*TPAD)                 /* per operand per stage */
#define GEMM_SMEM  (3*2*TILE_WORDS*4)         /* 110592 B */

__global__ void __launch_bounds__(256, 2)
gemm_tc(const float* __restrict__ A, const float* __restrict__ B,
        const float* __restrict__ bias, float* __restrict__ C,
        int K, int lda, int ldb, int ldc)
{
    extern __shared__ float smf[];

    int tid  = threadIdx.x;
    int warp = tid >> 5, lane = tid & 31;
    int wm = (warp >> 2) * 64;
    int wn = (warp & 3) * 32;
    int g  = lane >> 2, tg = lane & 3;

    int m0 = blockIdx.y * BM, n0 = blockIdx.x * BN;
    int arow = tid >> 3;            // 0..31
    int ac4  = (tid & 7) * 4;       // 0..28

    const float* Ag = A + (long)(m0 + arow) * lda + ac4;
    const float* Bg = B + (long)(n0 + arow) * ldb + ac4;

    float acc[4][4][4];
    #pragma unroll
    for (int i = 0; i < 4; i++)
        #pragma unroll
        for (int j = 0; j < 4; j++)
            #pragma unroll
            for (int r = 0; r < 4; r++) acc[i][j][r] = 0.f;

    int nk = K / BK;

    // stage issue: 8 cp.asyncs (4 A rows + 4 B rows), one commit group
    auto issue = [&](int stage, int k0) {
        float* dA = smf + stage * 2 * TILE_WORDS;
        float* dB = dA + TILE_WORDS;
        #pragma unroll
        for (int r = 0; r < 4; r++) {
            unsigned da = (unsigned)__cvta_generic_to_shared(
                &dA[(arow + r*32) * TPAD + ac4]);
            CP_ASYNC16(da, Ag + (long)r*32*lda + k0);
            unsigned db = (unsigned)__cvta_generic_to_shared(
                &dB[(arow + r*32) * TPAD + ac4]);
            CP_ASYNC16(db, Bg + (long)r*32*ldb + k0);
        }
        CP_COMMIT();
    };

    issue(0, 0);
    if (nk > 1) issue(1, BK);
    if (nk > 1) CP_WAIT(1); else CP_WAIT(0);
    __syncthreads();

    for (int t = 0; t < nk; t++) {
        // prefetch stage t+2 (overlaps with MMAs below)
        bool more = (t + 2 < nk);
        if (more) issue((t + 2) % 3, (t + 2) * BK);

        const float* sA = smf + (t % 3) * 2 * TILE_WORDS;
        const float* sB = sA + TILE_WORDS;

        #pragma unroll
        for (int ks = 0; ks < 4; ks++) {
            int kb = ks * 8;
            unsigned a[4][4], b[4][2];
            #pragma unroll
            for (int i = 0; i < 4; i++) {
                int r0 = wm + i * 16 + g;
                a[i][0] = f2tf(sA[r0 * TPAD + kb + tg]);
                a[i][1] = f2tf(sA[(r0 + 8) * TPAD + kb + tg]);
                a[i][2] = f2tf(sA[r0 * TPAD + kb + tg + 4]);
                a[i][3] = f2tf(sA[(r0 + 8) * TPAD + kb + tg + 4]);
            }
            #pragma unroll
            for (int j = 0; j < 4; j++) {
                int c0 = wn + j * 8 + g;
                b[j][0] = f2tf(sB[c0 * TPAD + kb + tg]);
                b[j][1] = f2tf(sB[c0 * TPAD + kb + tg + 4]);
            }
            #pragma unroll
            for (int i = 0; i < 4; i++)
                #pragma unroll
                for (int j = 0; j < 4; j++)
                    MMA_TF32(acc[i][j], a[i], b[j]);
        }

        if (more) CP_WAIT(1); else CP_WAIT(0);
        __syncthreads();
    }

    #pragma unroll
    for (int i = 0; i < 4; i++) {
        int row0 = m0 + wm + i * 16 + g;
        #pragma unroll
        for (int j = 0; j < 4; j++) {
            int col = n0 + wn + j * 8 + tg * 2;
            float b0 = bias ? bias[col] : 0.f;
            float b1 = bias ? bias[col + 1] : 0.f;
            *(float2*)&C[(long)row0 * ldc + col] =
                make_float2(acc[i][j][0] + b0, acc[i][j][1] + b1);
            *(float2*)&C[(long)(row0 + 8) * ldc + col] =
                make_float2(acc[i][j][2] + b0, acc[i][j][3] + b1);
        }
    }
}

// ---------------------------------------------------------------------------
// Fused flash attention (unchanged from R3 — passed).
// ---------------------------------------------------------------------------
#define QS_STR 132
#define PS_STR 68
#define FK 64
#define SM_Q 0
#define SM_K (SM_Q + 128*QS_STR)
#define SM_V (SM_K + FK*QS_STR)
#define SM_P (SM_V + FK*QS_STR)
#define SM_WORDS (SM_P + 128*PS_STR)

__global__ void __launch_bounds__(256)
flash_attn(const float* __restrict__ Qg, const float* __restrict__ Kg,
           const float* __restrict__ Vg, float* __restrict__ Og, float scale)
{
    extern __shared__ unsigned sm[];
    unsigned* Qs = sm + SM_Q;
    unsigned* Ks = sm + SM_K;
    unsigned* Vs = sm + SM_V;
    unsigned* Ps = sm + SM_P;

    int tid = threadIdx.x;
    int warp = tid >> 5, lane = tid & 31;
    int g = lane >> 2, tg = lane & 3;
    int wm = warp * 16;

    int z  = blockIdx.y;
    int bb = z / NH, hh = z % NH;
    long tok0 = (long)bb * S_LEN + blockIdx.x * 128;
    const float* Qb = Qg + tok0 * HIDV + hh * HD;
    const float* Kb = Kg + (long)bb * S_LEN * HIDV + hh * HD;
    const float* Vb = Vg + (long)bb * S_LEN * HIDV + hh * HD;

    #pragma unroll
    for (int i = 0; i < 16; i++) {
        int s = tid + i * 256;
        int row = s >> 5, c4 = (s & 31) * 4;
        float4 v = *(const float4*)&Qb[(long)row * HIDV + c4];
        unsigned* d = &Qs[row * QS_STR + c4];
        d[0]=f2tf(v.x*scale); d[1]=f2tf(v.y*scale); d[2]=f2tf(v.z*scale); d[3]=f2tf(v.w*scale);
    }

    float m0 = -1e30f, m1 = -1e30f, l0 = 0.f, l1 = 0.f;
    float o[16][4];
    #pragma unroll
    for (int j = 0; j < 16; j++)
        #pragma unroll
        for (int r = 0; r < 4; r++) o[j][r] = 0.f;

    for (int kt = 0; kt < S_LEN / FK; kt++) {
        __syncthreads();
        #pragma unroll
        for (int i = 0; i < 8; i++) {
            int s = tid + i * 256;
            int row = s >> 5, c4 = (s & 31) * 4;
            long goff = (long)(kt * FK + row) * HIDV + c4;
            float4 kv = *(const float4*)&Kb[goff];
            float4 vv = *(const float4*)&Vb[goff];
            unsigned* dk = &Ks[row * QS_STR + c4];
            unsigned* dv = &Vs[row * QS_STR + c4];
            dk[0]=f2tf(kv.x); dk[1]=f2tf(kv.y); dk[2]=f2tf(kv.z); dk[3]=f2tf(kv.w);
            dv[0]=f2tf(vv.x); dv[1]=f2tf(vv.y); dv[2]=f2tf(vv.z); dv[3]=f2tf(vv.w);
        }
        __syncthreads();

        float s_acc[8][4];
        #pragma unroll
        for (int j = 0; j < 8; j++)
            #pragma unroll
            for (int r = 0; r < 4; r++) s_acc[j][r] = 0.f;

        #pragma unroll
        for (int ks = 0; ks < 16; ks++) {
            int kb = ks * 8;
            unsigned a[4];
            a[0] = Qs[(wm + g) * QS_STR + kb + tg];
            a[1] = Qs[(wm + 8 + g) * QS_STR + kb + tg];
            a[2] = Qs[(wm + g) * QS_STR + kb + tg + 4];
            a[3] = Qs[(wm + 8 + g) * QS_STR + kb + tg + 4];
            #pragma unroll
            for (int j = 0; j < 8; j++) {
                unsigned b[2];
                b[0] = Ks[(j * 8 + g) * QS_STR + kb + tg];
                b[1] = Ks[(j * 8 + g) * QS_STR + kb + tg + 4];
                MMA_TF32(s_acc[j], a, b);
            }
        }

        float mx0 = -1e30f, mx1 = -1e30f;
        #pragma unroll
        for (int j = 0; j < 8; j++) {
            mx0 = fmaxf(mx0, fmaxf(s_acc[j][0], s_acc[j][1]));
            mx1 = fmaxf(mx1, fmaxf(s_acc[j][2], s_acc[j][3]));
        }
        mx0 = fmaxf(mx0, __shfl_xor_sync(0xffffffffu, mx0, 1));
        mx0 = fmaxf(mx0, __shfl_xor_sync(0xffffffffu, mx0, 2));
        mx1 = fmaxf(mx1, __shfl_xor_sync(0xffffffffu, mx1, 1));
        mx1 = fmaxf(mx1, __shfl_xor_sync(0xffffffffu, mx1, 2));

        float mn0 = fmaxf(m0, mx0), mn1 = fmaxf(m1, mx1);
        float al0 = __expf(m0 - mn0), al1 = __expf(m1 - mn1);
        float sum0 = 0.f, sum1 = 0.f;
        #pragma unroll
        for (int j = 0; j < 8; j++) {
            float p00 = __expf(s_acc[j][0] - mn0);
            float p01 = __expf(s_acc[j][1] - mn0);
            float p10 = __expf(s_acc[j][2] - mn1);
            float p11 = __expf(s_acc[j][3] - mn1);
            sum0 += p00 + p01; sum1 += p10 + p11;
            int col = j * 8 + tg * 2;
            Ps[(wm + g) * PS_STR + col]     = f2tf(p00);
            Ps[(wm + g) * PS_STR + col + 1] = f2tf(p01);
            Ps[(wm + 8 + g) * PS_STR + col]     = f2tf(p10);
            Ps[(wm + 8 + g) * PS_STR + col + 1] = f2tf(p11);
        }
        sum0 += __shfl_xor_sync(0xffffffffu, sum0, 1);
        sum0 += __shfl_xor_sync(0xffffffffu, sum0, 2);
        sum1 += __shfl_xor_sync(0xffffffffu, sum1, 1);
        sum1 += __shfl_xor_sync(0xffffffffu, sum1, 2);
        l0 = l0 * al0 + sum0;
        l1 = l1 * al1 + sum1;
        m0 = mn0; m1 = mn1;
        #pragma unroll
        for (int j = 0; j < 16; j++) {
            o[j][0] *= al0; o[j][1] *= al0;
            o[j][2] *= al1; o[j][3] *= al1;
        }
        __syncwarp();

        #pragma unroll
        for (int ks = 0; ks < 8; ks++) {
            int kb = ks * 8;
            unsigned a[4];
            a[0] = Ps[(wm + g) * PS_STR + kb + tg];
            a[1] = Ps[(wm + 8 + g) * PS_STR + kb + tg];
            a[2] = Ps[(wm + g) * PS_STR + kb + tg + 4];
            a[3] = Ps[(wm + 8 + g) * PS_STR + kb + tg + 4];
            #pragma unroll
            for (int j = 0; j < 16; j++) {
                unsigned b[2];
                b[0] = Vs[(kb + tg) * QS_STR + j * 8 + g];
                b[1] = Vs[(kb + tg + 4) * QS_STR + j * 8 + g];
                MMA_TF32(o[j], a, b);
            }
        }
    }

    float inv0 = 1.0f / l0, inv1 = 1.0f / l1;
    float* Ob = Og + tok0 * HIDV + hh * HD;
    #pragma unroll
    for (int j = 0; j < 16; j++) {
        int col = j * 8 + tg * 2;
        *(float2*)&Ob[(long)(wm + g) * HIDV + col] =
            make_float2(o[j][0] * inv0, o[j][1] * inv0);
        *(float2*)&Ob[(long)(wm + 8 + g) * HIDV + col] =
            make_float2(o[j][2] * inv1, o[j][3] * inv1);
    }
}

// ---------------------------------------------------------------------------
__global__ void __launch_bounds__(64)
kr_rope(const float* __restrict__ Kbuf, const float* __restrict__ Wkr,
        const float* __restrict__ bkr, float* __restrict__ out)
{
    int bid = blockIdx.x;
    int t = bid / NH, h = bid % NH;
    int s = t % S_LEN;
    __shared__ float kv[128];
    __shared__ float kr[64];
    int tid = threadIdx.x;

    kv[tid]      = Kbuf[(long)t * HIDV + h * HD + tid];
    kv[tid + 64] = Kbuf[(long)t * HIDV + h * HD + tid + 64];
    __syncthreads();

    float acc = bkr[tid];
    #pragma unroll 4
    for (int c = 0; c < 128; c++)
        acc += Wkr[tid * 128 + c] * kv[c];
    kr[tid] = acc;
    __syncthreads();

    int j = tid & 31;
    float inv_freq = expf(-(float)j * 0.28782313662425573f);
    float f = (float)s * inv_freq;
    float sn, cs;
    sincosf(f, &sn, &cs);
    float rot = (tid < 32) ? -kr[tid + 32] : kr[tid - 32];
    out[(long)t * (NH * RR) + h * RR + tid] = kr[tid] * cs + rot * sn;
}

// ---------------------------------------------------------------------------
extern "C" void kernel_launch(void* const* d_in, const int* in_sizes, int n_in,
                              void* d_out, int out_size)
{
    const float* hid  = (const float*)d_in[0];
    const float* Wdkv = (const float*)d_in[1];
    const float* bdkv = (const float*)d_in[2];
    const float* Wuk  = (const float*)d_in[3];
    const float* buk  = (const float*)d_in[4];
    const float* Wuv  = (const float*)d_in[5];
    const float* buv  = (const float*)d_in[6];
    const float* Wkr  = (const float*)d_in[7];
    const float* bkr  = (const float*)d_in[8];
    const float* Wdq  = (const float*)d_in[9];
    const float* bdq  = (const float*)d_in[10];
    const float* Wuq  = (const float*)d_in[11];
    const float* buq  = (const float*)d_in[12];
    // d_in[13..14] = W_QR — dead (q_r unused in reference)
    const float* Wo   = (const float*)d_in[15];
    const float* bo   = (const float*)d_in[16];

    float* out  = (float*)d_out;
    float* c_kv = out  + (long)NTOK * HIDV;
    float* kr   = c_kv + (long)NTOK * KVC;

    float *pK, *pV, *pCQ, *pQ, *pA;
    cudaGetSymbolAddress((void**)&pK,  g_K);
    cudaGetSymbolAddress((void**)&pV,  g_V);
    cudaGetSymbolAddress((void**)&pCQ, g_CQ);
    cudaGetSymbolAddress((void**)&pQ,  g_Q);
    cudaGetSymbolAddress((void**)&pA,  g_A);

    const float scale = 0.08838834764831845f;
    static int attr_set = 0;
    if (!attr_set) {
        cudaFuncSetAttribute(gemm_tc,
            cudaFuncAttributeMaxDynamicSharedMemorySize, GEMM_SMEM);
        cudaFuncSetAttribute(flash_attn,
            cudaFuncAttributeMaxDynamicSharedMemorySize, SM_WORDS * 4);
        attr_set = 1;
    }

    // 1. c_kv = hidden @ W_DKV^T + b
    gemm_tc<<<dim3(KVC/BN, NTOK/BM), 256, GEMM_SMEM>>>(hid, Wdkv, bdkv, c_kv,
        HIDV, HIDV, HIDV, KVC);

    // 2. k = c_kv @ W_UK^T + b
    gemm_tc<<<dim3(HIDV/BN, NTOK/BM), 256, GEMM_SMEM>>>(c_kv, Wuk, buk, pK,
        KVC, KVC, KVC, HIDV);

    // 3. v = c_kv @ W_UV^T + b
    gemm_tc<<<dim3(HIDV/BN, NTOK/BM), 256, GEMM_SMEM>>>(c_kv, Wuv, buv, pV,
        KVC, KVC, KVC, HIDV);

    // 4. c_q = hidden @ W_DQ^T + b
    gemm_tc<<<dim3(QCV/BN, NTOK/BM), 256, GEMM_SMEM>>>(hid, Wdq, bdq, pCQ,
        HIDV, HIDV, HIDV, QCV);

    // 5. q = c_q @ W_UQ^T + b
    gemm_tc<<<dim3(HIDV/BN, NTOK/BM), 256, GEMM_SMEM>>>(pCQ, Wuq, buq, pQ,
        QCV, QCV, QCV, HIDV);

    // 6. k_r (+RoPE)
    kr_rope<<<NTOK * NH, 64>>>(pK, Wkr, bkr, kr);

    // 7-9. fused flash attention -> g_A
    flash_attn<<<dim3(S_LEN/128, BATCH*NH), 256, SM_WORDS * 4>>>(
        pQ, pK, pV, pA, scale);

    // 10. output = attn @ W_O^T + b
    gemm_tc<<<dim3(HIDV/BN, NTOK/BM), 256, GEMM_SMEM>>>(pA, Wo, bo, out,
        HIDV, HIDV, HIDV, HIDV);
}

// round 5
// speedup vs baseline: 2.6123x; 1.0617x over previous
#include <cuda_runtime.h>
#include <math.h>

#define S_LEN 1024
#define BATCH 2
#define HIDV  2048
#define NH    16
#define HD    128
#define RR    64
#define KVC   512
#define QCV   1536
#define NTOK  (BATCH*S_LEN)   /* 2048 */

// ---------------- scratch (static device globals; no allocation) ----------------
__device__ float g_K [NTOK*(size_t)HIDV];
__device__ float g_V [NTOK*(size_t)HIDV];
__device__ float g_CQ[NTOK*(size_t)QCV];
__device__ float g_Q [NTOK*(size_t)HIDV];
__device__ float g_A [NTOK*(size_t)HIDV];

__device__ __forceinline__ unsigned f2tf(float x) {
    unsigned u;
    asm("cvt.rna.tf32.f32 %0, %1;" : "=r"(u) : "f"(x));
    return u;
}

#define MMA_TF32(d, a, b) \
    asm volatile("mma.sync.aligned.m16n8k8.row.col.f32.tf32.tf32.f32 " \
        "{%0,%1,%2,%3}, {%4,%5,%6,%7}, {%8,%9}, {%0,%1,%2,%3};" \
        : "+f"(d[0]), "+f"(d[1]), "+f"(d[2]), "+f"(d[3]) \
        : "r"(a[0]), "r"(a[1]), "r"(a[2]), "r"(a[3]), "r"(b[0]), "r"(b[1]))

#define CP_ASYNC16(dst_sm, src) \
    asm volatile("cp.async.cg.shared.global [%0], [%1], 16;" \
        :: "r"(dst_sm), "l"(src))
#define CP_COMMIT() asm volatile("cp.async.commit_group;" ::: "memory")
#define CP_WAIT(n)  asm volatile("cp.async.wait_group %0;" :: "n"(n) : "memory")

// ---------------------------------------------------------------------------
// Multi-job TF32 GEMM (weights transposed):  C = A @ B^T + bias
// 128x128x32 tile, 128 threads (4 warps, warp tile 64x64), 3-stage cp.async.
// Up to 3 sub-GEMMs per launch, selected by n-tile index (blockIdx.x).
// All jobs share M = NTOK (grid.y covers m-tiles).
// ---------------------------------------------------------------------------
#define BM 128
#define BN 128
#define BK 32
#define TPAD 36
#define TILE_WORDS (128*TPAD)
#define GEMM_SMEM  (3*2*TILE_WORDS*4)   /* 110592 B -> 2 CTAs/SM */

struct Job {
    const float* A; const float* B; const float* bias; float* C;
    int K, lda, ldb, ldc;
};

__global__ void __launch_bounds__(128, 2)
gemm_tc(Job j0, Job j1, Job j2, int b1, int b2)
{
    extern __shared__ float smf[];

    int bx = blockIdx.x;
    Job jb;
    int nOff;
    if (bx < b1)      { jb = j0; nOff = 0;  }
    else if (bx < b2) { jb = j1; nOff = b1; }
    else              { jb = j2; nOff = b2; }

    const float* A = jb.A;
    const float* B = jb.B;
    const float* bias = jb.bias;
    float* C = jb.C;
    int K = jb.K, lda = jb.lda, ldb = jb.ldb, ldc = jb.ldc;

    int tid  = threadIdx.x;
    int warp = tid >> 5, lane = tid & 31;
    int wm = (warp >> 1) * 64;
    int wn = (warp & 1) * 64;
    int g  = lane >> 2, tg = lane & 3;

    int m0 = blockIdx.y * BM, n0 = (bx - nOff) * BN;

    // cp.async mapping: 8 chunks/thread per operand (128 rows x 8 float4)
    int crow = tid >> 3;            // 0..15 base row
    int cc4  = (tid & 7) * 4;       // 0..28

    const float* Ag = A + (long)(m0 + crow) * lda + cc4;
    const float* Bg = B + (long)(n0 + crow) * ldb + cc4;

    float acc[4][8][4];
    #pragma unroll
    for (int i = 0; i < 4; i++)
        #pragma unroll
        for (int j = 0; j < 8; j++)
            #pragma unroll
            for (int r = 0; r < 4; r++) acc[i][j][r] = 0.f;

    int nk = K / BK;

    auto issue = [&](int stage, int k0) {
        float* dA = smf + stage * 2 * TILE_WORDS;
        float* dB = dA + TILE_WORDS;
        #pragma unroll
        for (int r = 0; r < 8; r++) {
            unsigned da = (unsigned)__cvta_generic_to_shared(
                &dA[(crow + r*16) * TPAD + cc4]);
            CP_ASYNC16(da, Ag + (long)r*16*lda + k0);
            unsigned db = (unsigned)__cvta_generic_to_shared(
                &dB[(crow + r*16) * TPAD + cc4]);
            CP_ASYNC16(db, Bg + (long)r*16*ldb + k0);
        }
        CP_COMMIT();
    };

    issue(0, 0);
    if (nk > 1) issue(1, BK);
    if (nk > 1) CP_WAIT(1); else CP_WAIT(0);
    __syncthreads();

    for (int t = 0; t < nk; t++) {
        bool more = (t + 2 < nk);
        if (more) issue((t + 2) % 3, (t + 2) * BK);

        const float* sA = smf + (t % 3) * 2 * TILE_WORDS;
        const float* sB = sA + TILE_WORDS;

        #pragma unroll
        for (int ks = 0; ks < 4; ks++) {
            int kb = ks * 8;
            unsigned a[4][4], b[8][2];
            #pragma unroll
            for (int i = 0; i < 4; i++) {
                int r0 = wm + i * 16 + g;
                a[i][0] = f2tf(sA[r0 * TPAD + kb + tg]);
                a[i][1] = f2tf(sA[(r0 + 8) * TPAD + kb + tg]);
                a[i][2] = f2tf(sA[r0 * TPAD + kb + tg + 4]);
                a[i][3] = f2tf(sA[(r0 + 8) * TPAD + kb + tg + 4]);
            }
            #pragma unroll
            for (int j = 0; j < 8; j++) {
                int c0 = wn + j * 8 + g;
                b[j][0] = f2tf(sB[c0 * TPAD + kb + tg]);
                b[j][1] = f2tf(sB[c0 * TPAD + kb + tg + 4]);
            }
            #pragma unroll
            for (int i = 0; i < 4; i++)
                #pragma unroll
                for (int j = 0; j < 8; j++)
                    MMA_TF32(acc[i][j], a[i], b[j]);
        }

        if (more) CP_WAIT(1); else CP_WAIT(0);
        __syncthreads();
    }

    #pragma unroll
    for (int i = 0; i < 4; i++) {
        int row0 = m0 + wm + i * 16 + g;
        #pragma unroll
        for (int j = 0; j < 8; j++) {
            int col = n0 + wn + j * 8 + tg * 2;
            float b0 = bias ? bias[col] : 0.f;
            float b1 = bias ? bias[col + 1] : 0.f;
            *(float2*)&C[(long)row0 * ldc + col] =
                make_float2(acc[i][j][0] + b0, acc[i][j][1] + b1);
            *(float2*)&C[(long)(row0 + 8) * ldc + col] =
                make_float2(acc[i][j][2] + b0, acc[i][j][3] + b1);
        }
    }
}

// ---------------------------------------------------------------------------
// Fused flash attention (unchanged from R3/R4 — passing).
// ---------------------------------------------------------------------------
#define QS_STR 132
#define PS_STR 68
#define FK 64
#define SM_Q 0
#define SM_K (SM_Q + 128*QS_STR)
#define SM_V (SM_K + FK*QS_STR)
#define SM_P (SM_V + FK*QS_STR)
#define SM_WORDS (SM_P + 128*PS_STR)

__global__ void __launch_bounds__(256)
flash_attn(const float* __restrict__ Qg, const float* __restrict__ Kg,
           const float* __restrict__ Vg, float* __restrict__ Og, float scale)
{
    extern __shared__ unsigned sm[];
    unsigned* Qs = sm + SM_Q;
    unsigned* Ks = sm + SM_K;
    unsigned* Vs = sm + SM_V;
    unsigned* Ps = sm + SM_P;

    int tid = threadIdx.x;
    int warp = tid >> 5, lane = tid & 31;
    int g = lane >> 2, tg = lane & 3;
    int wm = warp * 16;

    int z  = blockIdx.y;
    int bb = z / NH, hh = z % NH;
    long tok0 = (long)bb * S_LEN + blockIdx.x * 128;
    const float* Qb = Qg + tok0 * HIDV + hh * HD;
    const float* Kb = Kg + (long)bb * S_LEN * HIDV + hh * HD;
    const float* Vb = Vg + (long)bb * S_LEN * HIDV + hh * HD;

    #pragma unroll
    for (int i = 0; i < 16; i++) {
        int s = tid + i * 256;
        int row = s >> 5, c4 = (s & 31) * 4;
        float4 v = *(const float4*)&Qb[(long)row * HIDV + c4];
        unsigned* d = &Qs[row * QS_STR + c4];
        d[0]=f2tf(v.x*scale); d[1]=f2tf(v.y*scale); d[2]=f2tf(v.z*scale); d[3]=f2tf(v.w*scale);
    }

    float m0 = -1e30f, m1 = -1e30f, l0 = 0.f, l1 = 0.f;
    float o[16][4];
    #pragma unroll
    for (int j = 0; j < 16; j++)
        #pragma unroll
        for (int r = 0; r < 4; r++) o[j][r] = 0.f;

    for (int kt = 0; kt < S_LEN / FK; kt++) {
        __syncthreads();
        #pragma unroll
        for (int i = 0; i < 8; i++) {
            int s = tid + i * 256;
            int row = s >> 5, c4 = (s & 31) * 4;
            long goff = (long)(kt * FK + row) * HIDV + c4;
            float4 kv = *(const float4*)&Kb[goff];
            float4 vv = *(const float4*)&Vb[goff];
            unsigned* dk = &Ks[row * QS_STR + c4];
            unsigned* dv = &Vs[row * QS_STR + c4];
            dk[0]=f2tf(kv.x); dk[1]=f2tf(kv.y); dk[2]=f2tf(kv.z); dk[3]=f2tf(kv.w);
            dv[0]=f2tf(vv.x); dv[1]=f2tf(vv.y); dv[2]=f2tf(vv.z); dv[3]=f2tf(vv.w);
        }
        __syncthreads();

        float s_acc[8][4];
        #pragma unroll
        for (int j = 0; j < 8; j++)
            #pragma unroll
            for (int r = 0; r < 4; r++) s_acc[j][r] = 0.f;

        #pragma unroll
        for (int ks = 0; ks < 16; ks++) {
            int kb = ks * 8;
            unsigned a[4];
            a[0] = Qs[(wm + g) * QS_STR + kb + tg];
            a[1] = Qs[(wm + 8 + g) * QS_STR + kb + tg];
            a[2] = Qs[(wm + g) * QS_STR + kb + tg + 4];
            a[3] = Qs[(wm + 8 + g) * QS_STR + kb + tg + 4];
            #pragma unroll
            for (int j = 0; j < 8; j++) {
                unsigned b[2];
                b[0] = Ks[(j * 8 + g) * QS_STR + kb + tg];
                b[1] = Ks[(j * 8 + g) * QS_STR + kb + tg + 4];
                MMA_TF32(s_acc[j], a, b);
            }
        }

        float mx0 = -1e30f, mx1 = -1e30f;
        #pragma unroll
        for (int j = 0; j < 8; j++) {
            mx0 = fmaxf(mx0, fmaxf(s_acc[j][0], s_acc[j][1]));
            mx1 = fmaxf(mx1, fmaxf(s_acc[j][2], s_acc[j][3]));
        }
        mx0 = fmaxf(mx0, __shfl_xor_sync(0xffffffffu, mx0, 1));
        mx0 = fmaxf(mx0, __shfl_xor_sync(0xffffffffu, mx0, 2));
        mx1 = fmaxf(mx1, __shfl_xor_sync(0xffffffffu, mx1, 1));
        mx1 = fmaxf(mx1, __shfl_xor_sync(0xffffffffu, mx1, 2));

        float mn0 = fmaxf(m0, mx0), mn1 = fmaxf(m1, mx1);
        float al0 = __expf(m0 - mn0), al1 = __expf(m1 - mn1);
        float sum0 = 0.f, sum1 = 0.f;
        #pragma unroll
        for (int j = 0; j < 8; j++) {
            float p00 = __expf(s_acc[j][0] - mn0);
            float p01 = __expf(s_acc[j][1] - mn0);
            float p10 = __expf(s_acc[j][2] - mn1);
            float p11 = __expf(s_acc[j][3] - mn1);
            sum0 += p00 + p01; sum1 += p10 + p11;
            int col = j * 8 + tg * 2;
            Ps[(wm + g) * PS_STR + col]     = f2tf(p00);
            Ps[(wm + g) * PS_STR + col + 1] = f2tf(p01);
            Ps[(wm + 8 + g) * PS_STR + col]     = f2tf(p10);
            Ps[(wm + 8 + g) * PS_STR + col + 1] = f2tf(p11);
        }
        sum0 += __shfl_xor_sync(0xffffffffu, sum0, 1);
        sum0 += __shfl_xor_sync(0xffffffffu, sum0, 2);
        sum1 += __shfl_xor_sync(0xffffffffu, sum1, 1);
        sum1 += __shfl_xor_sync(0xffffffffu, sum1, 2);
        l0 = l0 * al0 + sum0;
        l1 = l1 * al1 + sum1;
        m0 = mn0; m1 = mn1;
        #pragma unroll
        for (int j = 0; j < 16; j++) {
            o[j][0] *= al0; o[j][1] *= al0;
            o[j][2] *= al1; o[j][3] *= al1;
        }
        __syncwarp();

        #pragma unroll
        for (int ks = 0; ks < 8; ks++) {
            int kb = ks * 8;
            unsigned a[4];
            a[0] = Ps[(wm + g) * PS_STR + kb + tg];
            a[1] = Ps[(wm + 8 + g) * PS_STR + kb + tg];
            a[2] = Ps[(wm + g) * PS_STR + kb + tg + 4];
            a[3] = Ps[(wm + 8 + g) * PS_STR + kb + tg + 4];
            #pragma unroll
            for (int j = 0; j < 16; j++) {
                unsigned b[2];
                b[0] = Vs[(kb + tg) * QS_STR + j * 8 + g];
                b[1] = Vs[(kb + tg + 4) * QS_STR + j * 8 + g];
                MMA_TF32(o[j], a, b);
            }
        }
    }

    float inv0 = 1.0f / l0, inv1 = 1.0f / l1;
    float* Ob = Og + tok0 * HIDV + hh * HD;
    #pragma unroll
    for (int j = 0; j < 16; j++) {
        int col = j * 8 + tg * 2;
        *(float2*)&Ob[(long)(wm + g) * HIDV + col] =
            make_float2(o[j][0] * inv0, o[j][1] * inv0);
        *(float2*)&Ob[(long)(wm + 8 + g) * HIDV + col] =
            make_float2(o[j][2] * inv1, o[j][3] * inv1);
    }
}

// ---------------------------------------------------------------------------
__global__ void __launch_bounds__(64)
kr_rope(const float* __restrict__ Kbuf, const float* __restrict__ Wkr,
        const float* __restrict__ bkr, float* __restrict__ out)
{
    int bid = blockIdx.x;
    int t = bid / NH, h = bid % NH;
    int s = t % S_LEN;
    __shared__ float kv[128];
    __shared__ float kr[64];
    int tid = threadIdx.x;

    kv[tid]      = Kbuf[(long)t * HIDV + h * HD + tid];
    kv[tid + 64] = Kbuf[(long)t * HIDV + h * HD + tid + 64];
    __syncthreads();

    float acc = bkr[tid];
    #pragma unroll 4
    for (int c = 0; c < 128; c++)
        acc += Wkr[tid * 128 + c] * kv[c];
    kr[tid] = acc;
    __syncthreads();

    int j = tid & 31;
    float inv_freq = expf(-(float)j * 0.28782313662425573f);
    float f = (float)s * inv_freq;
    float sn, cs;
    sincosf(f, &sn, &cs);
    float rot = (tid < 32) ? -kr[tid + 32] : kr[tid - 32];
    out[(long)t * (NH * RR) + h * RR + tid] = kr[tid] * cs + rot * sn;
}

// ---------------------------------------------------------------------------
extern "C" void kernel_launch(void* const* d_in, const int* in_sizes, int n_in,
                              void* d_out, int out_size)
{
    const float* hid  = (const float*)d_in[0];
    const float* Wdkv = (const float*)d_in[1];
    const float* bdkv = (const float*)d_in[2];
    const float* Wuk  = (const float*)d_in[3];
    const float* buk  = (const float*)d_in[4];
    const float* Wuv  = (const float*)d_in[5];
    const float* buv  = (const float*)d_in[6];
    const float* Wkr  = (const float*)d_in[7];
    const float* bkr  = (const float*)d_in[8];
    const float* Wdq  = (const float*)d_in[9];
    const float* bdq  = (const float*)d_in[10];
    const float* Wuq  = (const float*)d_in[11];
    const float* buq  = (const float*)d_in[12];
    // d_in[13..14] = W_QR — dead (q_r unused in reference)
    const float* Wo   = (const float*)d_in[15];
    const float* bo   = (const float*)d_in[16];

    float* out  = (float*)d_out;
    float* c_kv = out  + (long)NTOK * HIDV;
    float* kr   = c_kv + (long)NTOK * KVC;

    float *pK, *pV, *pCQ, *pQ, *pA;
    cudaGetSymbolAddress((void**)&pK,  g_K);
    cudaGetSymbolAddress((void**)&pV,  g_V);
    cudaGetSymbolAddress((void**)&pCQ, g_CQ);
    cudaGetSymbolAddress((void**)&pQ,  g_Q);
    cudaGetSymbolAddress((void**)&pA,  g_A);

    const float scale = 0.08838834764831845f;
    static int attr_set = 0;
    if (!attr_set) {
        cudaFuncSetAttribute(gemm_tc,
            cudaFuncAttributeMaxDynamicSharedMemorySize, GEMM_SMEM);
        cudaFuncSetAttribute(flash_attn,
            cudaFuncAttributeMaxDynamicSharedMemorySize, SM_WORDS * 4);
        attr_set = 1;
    }

    // L1: c_kv (N=512) + c_q (N=1536), both A=hid, K=2048.  grid.x = 4+12
    {
        Job ja = { hid, Wdkv, bdkv, c_kv, HIDV, HIDV, HIDV, KVC };
        Job jb = { hid, Wdq,  bdq,  pCQ,  HIDV, HIDV, HIDV, QCV };
        gemm_tc<<<dim3(16, NTOK/BM), 128, GEMM_SMEM>>>(ja, jb, jb, 4, 16);
    }

    // L2: k (K=512) + v (K=512) + q (K=1536), all N=2048.  grid.x = 48
    {
        Job ja = { c_kv, Wuk, buk, pK, KVC, KVC, KVC, HIDV };
        Job jb = { c_kv, Wuv, buv, pV, KVC, KVC, KVC, HIDV };
        Job jc = { pCQ,  Wuq, buq, pQ, QCV, QCV, QCV, HIDV };
        gemm_tc<<<dim3(48, NTOK/BM), 128, GEMM_SMEM>>>(ja, jb, jc, 16, 32);
    }

    // kr_rope (+RoPE) -> d_out section
    kr_rope<<<NTOK * NH, 64>>>(pK, Wkr, bkr, kr);

    // fused flash attention -> g_A
    flash_attn<<<dim3(S_LEN/128, BATCH*NH), 256, SM_WORDS * 4>>>(
        pQ, pK, pV, pA, scale);

    // L4: output = attn @ W_O^T + b
    {
        Job ja = { pA, Wo, bo, out, HIDV, HIDV, HIDV, HIDV };
        gemm_tc<<<dim3(16, NTOK/BM), 128, GEMM_SMEM>>>(ja, ja, ja, 16, 16);
    }
}

// round 6
// speedup vs baseline: 3.0007x; 1.1487x over previous
#include <cuda_runtime.h>
#include <cuda_fp16.h>
#include <math.h>

#define S_LEN 1024
#define BATCH 2
#define HIDV  2048
#define NH    16
#define HD    128
#define RR    64
#define KVC   512
#define QCV   1536
#define NTOK  (BATCH*S_LEN)   /* 2048 */

// ---------------- scratch (static device globals; no allocation) ----------------
__device__ __align__(256) __half g_h16 [NTOK*(size_t)HIDV];   // hidden fp16
__device__ __align__(256) __half g_ckv16[NTOK*(size_t)KVC];
__device__ __align__(256) __half g_cq16 [NTOK*(size_t)QCV];
__device__ __align__(256) __half g_k16 [NTOK*(size_t)HIDV];
__device__ __align__(256) __half g_v16 [NTOK*(size_t)HIDV];
__device__ __align__(256) __half g_q16 [NTOK*(size_t)HIDV];
__device__ __align__(256) __half g_a16 [NTOK*(size_t)HIDV];
// weight pool (fp16): dkv | uk | uv | dq | uq | o
#define OFF_DKV 0
#define OFF_UK  (OFF_DKV + KVC*HIDV)
#define OFF_UV  (OFF_UK  + HIDV*KVC)
#define OFF_DQ  (OFF_UV  + HIDV*KVC)
#define OFF_UQ  (OFF_DQ  + QCV*HIDV)
#define OFF_O   (OFF_UQ  + HIDV*QCV)
#define W16_TOTAL (OFF_O + HIDV*HIDV)
__device__ __align__(256) __half g_w16[W16_TOTAL];

// ---------------- PTX helpers ----------------
#define MMA_F16(d, a, b) \
    asm volatile("mma.sync.aligned.m16n8k16.row.col.f32.f16.f16.f32 " \
        "{%0,%1,%2,%3}, {%4,%5,%6,%7}, {%8,%9}, {%0,%1,%2,%3};" \
        : "+f"(d[0]), "+f"(d[1]), "+f"(d[2]), "+f"(d[3]) \
        : "r"(a[0]), "r"(a[1]), "r"(a[2]), "r"(a[3]), "r"(b[0]), "r"(b[1]))

#define LDSM_X4(r0,r1,r2,r3,addr) \
    asm volatile("ldmatrix.sync.aligned.m8n8.x4.shared.b16 {%0,%1,%2,%3}, [%4];" \
        : "=r"(r0),"=r"(r1),"=r"(r2),"=r"(r3) : "r"(addr))
#define LDSM_X4_T(r0,r1,r2,r3,addr) \
    asm volatile("ldmatrix.sync.aligned.m8n8.x4.trans.shared.b16 {%0,%1,%2,%3}, [%4];" \
        : "=r"(r0),"=r"(r1),"=r"(r2),"=r"(r3) : "r"(addr))

#define CP_ASYNC16(dst_sm, src) \
    asm volatile("cp.async.cg.shared.global [%0], [%1], 16;" \
        :: "r"(dst_sm), "l"(src))
#define CP_COMMIT() asm volatile("cp.async.commit_group;" ::: "memory")
#define CP_WAIT(n)  asm volatile("cp.async.wait_group %0;" :: "n"(n) : "memory")

// ---------------------------------------------------------------------------
// fp32 -> fp16 conversion (vectorized by 4)
// ---------------------------------------------------------------------------
__global__ void __launch_bounds__(256)
cvt_f2h(const float4* __restrict__ src, __half2* __restrict__ dst, int n4)
{
    int i = blockIdx.x * 256 + threadIdx.x;
    if (i < n4) {
        float4 v = src[i];
        dst[2*i]   = __floats2half2_rn(v.x, v.y);
        dst[2*i+1] = __floats2half2_rn(v.z, v.w);
    }
}

// ---------------------------------------------------------------------------
// Multi-job fp16 GEMM:  C = A @ B^T + bias (fp32 acc)
// Tile 128x128x64, 128 threads (4 warps, warp tile 64x64), 3-stage cp.async,
// ldmatrix fragment loads, m16n8k16 MMA. Optional fp32 and fp16 outputs.
// ---------------------------------------------------------------------------
#define BM 128
#define BN 128
#define BK 64
#define ASTR 72                       /* smem row stride in halves (144B) */
#define ST_HALVES (128*ASTR)          /* per operand per stage */
#define GEMM_SMEM (3*2*ST_HALVES*2)   /* 110592 B */

struct Job {
    const __half* A; const __half* B; const float* bias;
    float* C; __half* C16;
    int K, lda, ldb, ldc;
};

__global__ void __launch_bounds__(128, 2)
gemm_h(Job j0, Job j1, Job j2, int b1, int b2)
{
    extern __shared__ __half smh[];

    int bx = blockIdx.x;
    Job jb; int nOff;
    if (bx < b1)      { jb = j0; nOff = 0;  }
    else if (bx < b2) { jb = j1; nOff = b1; }
    else              { jb = j2; nOff = b2; }

    int K = jb.K, lda = jb.lda, ldb = jb.ldb, ldc = jb.ldc;

    int tid  = threadIdx.x;
    int warp = tid >> 5, lane = tid & 31;
    int wm = (warp >> 1) * 64;
    int wn = (warp & 1) * 64;
    int g  = lane >> 2, tg = lane & 3;

    int m0 = blockIdx.y * BM, n0 = (bx - nOff) * BN;

    const __half* Ag = jb.A + (long)(m0 + tid) * lda;
    const __half* Bg = jb.B + (long)(n0 + tid) * ldb;

    float acc[4][8][4];
    #pragma unroll
    for (int i = 0; i < 4; i++)
        #pragma unroll
        for (int j = 0; j < 8; j++)
            #pragma unroll
            for (int r = 0; r < 4; r++) acc[i][j][r] = 0.f;

    int nk = K / BK;
    unsigned uBase = (unsigned)__cvta_generic_to_shared(smh);

    auto issue = [&](int stage, int k0) {
        unsigned dA = uBase + stage * 2 * ST_HALVES * 2 + tid * ASTR * 2;
        unsigned dB = dA + ST_HALVES * 2;
        #pragma unroll
        for (int c = 0; c < 8; c++) {
            CP_ASYNC16(dA + c * 16, Ag + k0 + c * 8);
            CP_ASYNC16(dB + c * 16, Bg + k0 + c * 8);
        }
        CP_COMMIT();
    };

    issue(0, 0);
    if (nk > 1) issue(1, BK);
    if (nk > 1) CP_WAIT(1); else CP_WAIT(0);
    __syncthreads();

    // fragment address components (in halves)
    int aRow = lane & 15;                 // A/B ldmatrix row within 16
    int aK   = (lane >> 4) * 8;           // A k offset
    int bRow = (lane & 7) + ((lane >> 4) & 1) * 8;
    int bK   = ((lane >> 3) & 1) * 8;

    for (int t = 0; t < nk; t++) {
        bool more = (t + 2 < nk);
        if (more) issue((t + 2) % 3, (t + 2) * BK);

        unsigned uA = uBase + (t % 3) * 2 * ST_HALVES * 2;
        unsigned uB = uA + ST_HALVES * 2;

        #pragma unroll
        for (int ks = 0; ks < 4; ks++) {
            int kb = ks * 16;
            unsigned a[4][4], b[8][2];
            #pragma unroll
            for (int i = 0; i < 4; i++) {
                unsigned ad = uA + ((wm + i*16 + aRow) * ASTR + kb + aK) * 2;
                LDSM_X4(a[i][0], a[i][1], a[i][2], a[i][3], ad);
            }
            #pragma unroll
            for (int jg = 0; jg < 4; jg++) {
                unsigned bd = uB + ((wn + jg*16 + bRow) * ASTR + kb + bK) * 2;
                LDSM_X4(b[2*jg][0], b[2*jg][1], b[2*jg+1][0], b[2*jg+1][1], bd);
            }
            #pragma unroll
            for (int i = 0; i < 4; i++)
                #pragma unroll
                for (int j = 0; j < 8; j++)
                    MMA_F16(acc[i][j], a[i], b[j]);
        }

        if (more) CP_WAIT(1); else CP_WAIT(0);
        __syncthreads();
    }

    // ---- epilogue: fp32 and/or fp16 outputs ----
    #pragma unroll
    for (int i = 0; i < 4; i++) {
        int row0 = m0 + wm + i * 16 + g;
        #pragma unroll
        for (int j = 0; j < 8; j++) {
            int col = n0 + wn + j * 8 + tg * 2;
            float b0 = jb.bias ? jb.bias[col] : 0.f;
            float b1 = jb.bias ? jb.bias[col + 1] : 0.f;
            float v00 = acc[i][j][0] + b0, v01 = acc[i][j][1] + b1;
            float v10 = acc[i][j][2] + b0, v11 = acc[i][j][3] + b1;
            if (jb.C) {
                *(float2*)&jb.C[(long)row0 * ldc + col]       = make_float2(v00, v01);
                *(float2*)&jb.C[(long)(row0 + 8) * ldc + col] = make_float2(v10, v11);
            }
            if (jb.C16) {
                *(__half2*)&jb.C16[(long)row0 * ldc + col]       = __floats2half2_rn(v00, v01);
                *(__half2*)&jb.C16[(long)(row0 + 8) * ldc + col] = __floats2half2_rn(v10, v11);
            }
        }
    }
}

// ---------------------------------------------------------------------------
// Fused fp16 flash attention. Block = 128 q rows x one (b,h), 256 threads.
// K/V tiles of 64, 2-stage cp.async, ldmatrix fragments, fp32 softmax.
// smem halves: Q[128][136] | K[2][64][136] | V[2][64][136] | P[128][72]
// ---------------------------------------------------------------------------
#define QSTR 136
#define PSTR 72
#define FK 64
#define SH_Q 0
#define SH_K (SH_Q + 128*QSTR)            /* 17408 */
#define SH_V (SH_K + 2*FK*QSTR)           /* 34816 */
#define SH_P (SH_V + 2*FK*QSTR)           /* 52224 */
#define FLASH_SMEM ((SH_P + 128*PSTR) * 2)  /* 122880 B */

__global__ void __launch_bounds__(256)
flash_attn(const __half* __restrict__ Qg, const __half* __restrict__ Kg,
           const __half* __restrict__ Vg, __half* __restrict__ Og, float scale)
{
    extern __shared__ __half smh[];
    unsigned uS = (unsigned)__cvta_generic_to_shared(smh);

    int tid = threadIdx.x;
    int warp = tid >> 5, lane = tid & 31;
    int g = lane >> 2, tg = lane & 3;
    int wm = warp * 16;

    int z  = blockIdx.y;
    int bb = z / NH, hh = z % NH;
    long tok0 = (long)bb * S_LEN + blockIdx.x * 128;
    const __half* Qb = Qg + tok0 * HIDV + hh * HD;
    const __half* Kb = Kg + (long)bb * S_LEN * HIDV + hh * HD;
    const __half* Vb = Vg + (long)bb * S_LEN * HIDV + hh * HD;

    // Q: 128 rows x 128 halves = 2048 x 16B chunks
    #pragma unroll
    for (int i = 0; i < 8; i++) {
        int s = tid + i * 256;
        int row = s >> 4, ch = s & 15;
        CP_ASYNC16(uS + (SH_Q + row * QSTR + ch * 8) * 2,
                   Qb + (long)row * HIDV + ch * 8);
    }
    CP_COMMIT();

    auto issueKV = [&](int st, int kt) {
        #pragma unroll
        for (int i = 0; i < 4; i++) {
            int s = tid + i * 256;
            int row = s >> 4, ch = s & 15;
            long goff = (long)(kt * FK + row) * HIDV + ch * 8;
            CP_ASYNC16(uS + (SH_K + st * FK * QSTR + row * QSTR + ch * 8) * 2, Kb + goff);
            CP_ASYNC16(uS + (SH_V + st * FK * QSTR + row * QSTR + ch * 8) * 2, Vb + goff);
        }
        CP_COMMIT();
    };
    issueKV(0, 0);

    float m0 = -1e30f, m1 = -1e30f, l0 = 0.f, l1 = 0.f;
    float o[16][4];
    #pragma unroll
    for (int j = 0; j < 16; j++)
        #pragma unroll
        for (int r = 0; r < 4; r++) o[j][r] = 0.f;

    int aRow = lane & 15;
    int aK   = (lane >> 4) * 8;
    int bRow = (lane & 7) + ((lane >> 4) & 1) * 8;
    int bK   = ((lane >> 3) & 1) * 8;
    int vK   = (lane & 7) + ((lane >> 3) & 1) * 8;   // trans: k-row within 16
    int vN   = ((lane >> 4) & 1) * 8;                // trans: n offset

    for (int kt = 0; kt < S_LEN / FK; kt++) {
        CP_WAIT(0);
        __syncthreads();
        if (kt + 1 < S_LEN / FK) issueKV((kt + 1) & 1, kt + 1);

        int kOff = SH_K + (kt & 1) * FK * QSTR;
        int vOff = SH_V + (kt & 1) * FK * QSTR;

        // ---- S = Q @ K^T (warp: 16 rows x 64 cols), 8 k-steps of 16 ----
        float s_acc[8][4];
        #pragma unroll
        for (int j = 0; j < 8; j++)
            #pragma unroll
            for (int r = 0; r < 4; r++) s_acc[j][r] = 0.f;

        #pragma unroll
        for (int ks = 0; ks < 8; ks++) {
            int kb = ks * 16;
            unsigned a[4];
            LDSM_X4(a[0], a[1], a[2], a[3],
                uS + (SH_Q + (wm + aRow) * QSTR + kb + aK) * 2);
            #pragma unroll
            for (int jg = 0; jg < 4; jg++) {
                unsigned b0[2], b1[2];
                LDSM_X4(b0[0], b0[1], b1[0], b1[1],
                    uS + (kOff + (jg*16 + bRow) * QSTR + kb + bK) * 2);
                MMA_F16(s_acc[2*jg],   a, b0);
                MMA_F16(s_acc[2*jg+1], a, b1);
            }
        }

        // ---- online softmax ----
        #pragma unroll
        for (int j = 0; j < 8; j++)
            #pragma unroll
            for (int r = 0; r < 4; r++) s_acc[j][r] *= scale;

        float mx0 = -1e30f, mx1 = -1e30f;
        #pragma unroll
        for (int j = 0; j < 8; j++) {
            mx0 = fmaxf(mx0, fmaxf(s_acc[j][0], s_acc[j][1]));
            mx1 = fmaxf(mx1, fmaxf(s_acc[j][2], s_acc[j][3]));
        }
        mx0 = fmaxf(mx0, __shfl_xor_sync(0xffffffffu, mx0, 1));
        mx0 = fmaxf(mx0, __shfl_xor_sync(0xffffffffu, mx0, 2));
        mx1 = fmaxf(mx1, __shfl_xor_sync(0xffffffffu, mx1, 1));
        mx1 = fmaxf(mx1, __shfl_xor_sync(0xffffffffu, mx1, 2));

        float mn0 = fmaxf(m0, mx0), mn1 = fmaxf(m1, mx1);
        float al0 = __expf(m0 - mn0), al1 = __expf(m1 - mn1);
        float sum0 = 0.f, sum1 = 0.f;
        #pragma unroll
        for (int j = 0; j < 8; j++) {
            float p00 = __expf(s_acc[j][0] - mn0);
            float p01 = __expf(s_acc[j][1] - mn0);
            float p10 = __expf(s_acc[j][2] - mn1);
            float p11 = __expf(s_acc[j][3] - mn1);
            sum0 += p00 + p01; sum1 += p10 + p11;
            int col = j * 8 + tg * 2;
            *(__half2*)&smh[SH_P + (wm + g) * PSTR + col]     = __floats2half2_rn(p00, p01);
            *(__half2*)&smh[SH_P + (wm + 8 + g) * PSTR + col] = __floats2half2_rn(p10, p11);
        }
        sum0 += __shfl_xor_sync(0xffffffffu, sum0, 1);
        sum0 += __shfl_xor_sync(0xffffffffu, sum0, 2);
        sum1 += __shfl_xor_sync(0xffffffffu, sum1, 1);
        sum1 += __shfl_xor_sync(0xffffffffu, sum1, 2);
        l0 = l0 * al0 + sum0;
        l1 = l1 * al1 + sum1;
        m0 = mn0; m1 = mn1;
        #pragma unroll
        for (int j = 0; j < 16; j++) {
            o[j][0] *= al0; o[j][1] *= al0;
            o[j][2] *= al1; o[j][3] *= al1;
        }
        __syncwarp();   // P rows are warp-private

        // ---- O += P @ V : 4 k-steps of 16, n = 128 ----
        #pragma unroll
        for (int ks = 0; ks < 4; ks++) {
            int kb = ks * 16;
            unsigned a[4];
            LDSM_X4(a[0], a[1], a[2], a[3],
                uS + (SH_P + (wm + aRow) * PSTR + kb + aK) * 2);
            #pragma unroll
            for (int ng = 0; ng < 8; ng++) {
                unsigned b0[2], b1[2];
                LDSM_X4_T(b0[0], b0[1], b1[0], b1[1],
                    uS + (vOff + (kb + vK) * QSTR + ng*16 + vN) * 2);
                MMA_F16(o[2*ng],   a, b0);
                MMA_F16(o[2*ng+1], a, b1);
            }
        }
    }

    // ---- finalize -> fp16 attn buffer ----
    float inv0 = 1.0f / l0, inv1 = 1.0f / l1;
    __half* Ob = Og + tok0 * HIDV + hh * HD;
    #pragma unroll
    for (int j = 0; j < 16; j++) {
        int col = j * 8 + tg * 2;
        *(__half2*)&Ob[(long)(wm + g) * HIDV + col] =
            __floats2half2_rn(o[j][0] * inv0, o[j][1] * inv0);
        *(__half2*)&Ob[(long)(wm + 8 + g) * HIDV + col] =
            __floats2half2_rn(o[j][2] * inv1, o[j][3] * inv1);
    }
}

// ---------------------------------------------------------------------------
// k_r = RoPE( k[t,h,:] @ W_KR^T + b_KR ), k read as fp16.
// ---------------------------------------------------------------------------
__global__ void __launch_bounds__(64)
kr_rope(const __half* __restrict__ Kbuf, const float* __restrict__ Wkr,
        const float* __restrict__ bkr, float* __restrict__ out)
{
    int bid = blockIdx.x;
    int t = bid / NH, h = bid % NH;
    int s = t % S_LEN;
    __shared__ float kv[128];
    __shared__ float kr[64];
    int tid = threadIdx.x;

    kv[tid]      = __half2float(Kbuf[(long)t * HIDV + h * HD + tid]);
    kv[tid + 64] = __half2float(Kbuf[(long)t * HIDV + h * HD + tid + 64]);
    __syncthreads();

    float acc = bkr[tid];
    #pragma unroll 4
    for (int c = 0; c < 128; c++)
        acc += Wkr[tid * 128 + c] * kv[c];
    kr[tid] = acc;
    __syncthreads();

    int j = tid & 31;
    float inv_freq = expf(-(float)j * 0.28782313662425573f); // ln(10000)/32
    float f = (float)s * inv_freq;
    float sn, cs;
    sincosf(f, &sn, &cs);
    float rot = (tid < 32) ? -kr[tid + 32] : kr[tid - 32];
    out[(long)t * (NH * RR) + h * RR + tid] = kr[tid] * cs + rot * sn;
}

// ---------------------------------------------------------------------------
extern "C" void kernel_launch(void* const* d_in, const int* in_sizes, int n_in,
                              void* d_out, int out_size)
{
    const float* hid  = (const float*)d_in[0];
    const float* Wdkv = (const float*)d_in[1];
    const float* bdkv = (const float*)d_in[2];
    const float* Wuk  = (const float*)d_in[3];
    const float* buk  = (const float*)d_in[4];
    const float* Wuv  = (const float*)d_in[5];
    const float* buv  = (const float*)d_in[6];
    const float* Wkr  = (const float*)d_in[7];
    const float* bkr  = (const float*)d_in[8];
    const float* Wdq  = (const float*)d_in[9];
    const float* bdq  = (const float*)d_in[10];
    const float* Wuq  = (const float*)d_in[11];
    const float* buq  = (const float*)d_in[12];
    // d_in[13..14] = W_QR — dead (q_r unused in reference)
    const float* Wo   = (const float*)d_in[15];
    const float* bo   = (const float*)d_in[16];

    float* out  = (float*)d_out;
    float* c_kv = out  + (long)NTOK * HIDV;
    float* kr   = c_kv + (long)NTOK * KVC;

    __half *h16, *ckv16, *cq16, *k16, *v16, *q16, *a16, *w16;
    cudaGetSymbolAddress((void**)&h16,   g_h16);
    cudaGetSymbolAddress((void**)&ckv16, g_ckv16);
    cudaGetSymbolAddress((void**)&cq16,  g_cq16);
    cudaGetSymbolAddress((void**)&k16,   g_k16);
    cudaGetSymbolAddress((void**)&v16,   g_v16);
    cudaGetSymbolAddress((void**)&q16,   g_q16);
    cudaGetSymbolAddress((void**)&a16,   g_a16);
    cudaGetSymbolAddress((void**)&w16,   g_w16);

    const float scale = 0.08838834764831845f;  // 1/sqrt(128)
    static int attr_set = 0;
    if (!attr_set) {
        cudaFuncSetAttribute(gemm_h,
            cudaFuncAttributeMaxDynamicSharedMemorySize, GEMM_SMEM);
        cudaFuncSetAttribute(flash_attn,
            cudaFuncAttributeMaxDynamicSharedMemorySize, FLASH_SMEM);
        attr_set = 1;
    }

    // 0. fp32 -> fp16 conversions (hidden + weights)
    auto cvt = [&](const float* s, __half* d, int n) {
        int n4 = n / 4;
        cvt_f2h<<<(n4 + 255) / 256, 256>>>((const float4*)s, (__half2*)d, n4);
    };
    cvt(hid,  h16,            NTOK * HIDV);
    cvt(Wdkv, w16 + OFF_DKV,  KVC * HIDV);
    cvt(Wuk,  w16 + OFF_UK,   HIDV * KVC);
    cvt(Wuv,  w16 + OFF_UV,   HIDV * KVC);
    cvt(Wdq,  w16 + OFF_DQ,   QCV * HIDV);
    cvt(Wuq,  w16 + OFF_UQ,   HIDV * QCV);
    cvt(Wo,   w16 + OFF_O,    HIDV * HIDV);

    // L1: c_kv (N=512, fp32 out + fp16) + c_q (N=1536, fp16 only). K=2048.
    {
        Job ja = { h16, w16 + OFF_DKV, bdkv, c_kv,   ckv16, HIDV, HIDV, HIDV, KVC };
        Job jb = { h16, w16 + OFF_DQ,  bdq,  nullptr, cq16, HIDV, HIDV, HIDV, QCV };
        gemm_h<<<dim3(16, NTOK/BM), 128, GEMM_SMEM>>>(ja, jb, jb, 4, 16);
    }

    // L2: k (K=512) + v (K=512) + q (K=1536), all N=2048, fp16 only.
    {
        Job ja = { ckv16, w16 + OFF_UK, buk, nullptr, k16, KVC, KVC, KVC, HIDV };
        Job jb = { ckv16, w16 + OFF_UV, buv, nullptr, v16, KVC, KVC, KVC, HIDV };
        Job jc = { cq16,  w16 + OFF_UQ, buq, nullptr, q16, QCV, QCV, QCV, HIDV };
        gemm_h<<<dim3(48, NTOK/BM), 128, GEMM_SMEM>>>(ja, jb, jc, 16, 32);
    }

    // k_r (+RoPE) -> d_out section
    kr_rope<<<NTOK * NH, 64>>>(k16, Wkr, bkr, kr);

    // fused flash attention -> a16
    flash_attn<<<dim3(S_LEN/128, BATCH*NH), 256, FLASH_SMEM>>>(
        q16, k16, v16, a16, scale);

    // L4: output = attn @ W_O^T + b -> fp32 d_out
    {
        Job ja = { a16, w16 + OFF_O, bo, out, nullptr, HIDV, HIDV, HIDV, HIDV };
        gemm_h<<<dim3(16, NTOK/BM), 128, GEMM_SMEM>>>(ja, ja, ja, 16, 16);
    }
}

// round 8
// speedup vs baseline: 3.0281x; 1.0091x over previous
#include <cuda_runtime.h>
#include <cuda_fp16.h>
#include <math.h>
#include <stdint.h>

#define S_LEN 1024
#define BATCH 2
#define HIDV  2048
#define NH    16
#define HD    128
#define RR    64
#define KVC   512
#define QCV   1536
#define NTOK  (BATCH*S_LEN)   /* 2048 */

// ---------------- scratch (static device globals; no allocation) ----------------
__device__ __align__(256) __half g_h16 [NTOK*(size_t)HIDV];
__device__ __align__(256) __half g_ckv16[NTOK*(size_t)KVC];
__device__ __align__(256) __half g_cq16 [NTOK*(size_t)QCV];
__device__ __align__(256) __half g_k16 [NTOK*(size_t)HIDV];
__device__ __align__(256) __half g_v16 [NTOK*(size_t)HIDV];
__device__ __align__(256) __half g_q16 [NTOK*(size_t)HIDV];
__device__ __align__(256) __half g_a16 [NTOK*(size_t)HIDV];
#define OFF_DKV 0
#define OFF_UK  (OFF_DKV + KVC*HIDV)
#define OFF_UV  (OFF_UK  + HIDV*KVC)
#define OFF_DQ  (OFF_UV  + HIDV*KVC)
#define OFF_UQ  (OFF_DQ  + QCV*HIDV)
#define OFF_O   (OFF_UQ  + HIDV*QCV)
#define W16_TOTAL (OFF_O + HIDV*HIDV)
__device__ __align__(256) __half g_w16[W16_TOTAL];

// ---------------- PTX helpers ----------------
#define MMA_F16(d, a, b) \
    asm volatile("mma.sync.aligned.m16n8k16.row.col.f32.f16.f16.f32 " \
        "{%0,%1,%2,%3}, {%4,%5,%6,%7}, {%8,%9}, {%0,%1,%2,%3};" \
        : "+f"(d[0]), "+f"(d[1]), "+f"(d[2]), "+f"(d[3]) \
        : "r"(a[0]), "r"(a[1]), "r"(a[2]), "r"(a[3]), "r"(b[0]), "r"(b[1]))

#define LDSM_X4(r0,r1,r2,r3,addr) \
    asm volatile("ldmatrix.sync.aligned.m8n8.x4.shared.b16 {%0,%1,%2,%3}, [%4];" \
        : "=r"(r0),"=r"(r1),"=r"(r2),"=r"(r3) : "r"(addr))
#define LDSM_X4_T(r0,r1,r2,r3,addr) \
    asm volatile("ldmatrix.sync.aligned.m8n8.x4.trans.shared.b16 {%0,%1,%2,%3}, [%4];" \
        : "=r"(r0),"=r"(r1),"=r"(r2),"=r"(r3) : "r"(addr))

#define CP_ASYNC16(dst_sm, src) \
    asm volatile("cp.async.cg.shared.global [%0], [%1], 16;" \
        :: "r"(dst_sm), "l"(src))
#define CP_COMMIT() asm volatile("cp.async.commit_group;" ::: "memory")
#define CP_WAIT(n)  asm volatile("cp.async.wait_group %0;" :: "n"(n) : "memory")

__device__ __forceinline__ uint32_t pack_h2(float a, float b) {
    __half2 h = __floats2half2_rn(a, b);
    return *reinterpret_cast<uint32_t*>(&h);
}

// ---------------------------------------------------------------------------
// fp32 -> fp16 conversion (vectorized by 4)
// ---------------------------------------------------------------------------
__global__ void __launch_bounds__(256)
cvt_f2h(const float4* __restrict__ src, __half2* __restrict__ dst, int n4)
{
    int i = blockIdx.x * 256 + threadIdx.x;
    if (i < n4) {
        float4 v = src[i];
        dst[2*i]   = __floats2half2_rn(v.x, v.y);
        dst[2*i+1] = __floats2half2_rn(v.z, v.w);
    }
}

// ---------------------------------------------------------------------------
// Multi-job fp16 GEMM:  C = A @ B^T + bias (fp32 acc)  — unchanged from R6.
// Tile 128x128x64, 128 threads (4 warps, warp tile 64x64), 3-stage cp.async.
// ---------------------------------------------------------------------------
#define BM 128
#define BN 128
#define BK 64
#define ASTR 72
#define ST_HALVES (128*ASTR)
#define GEMM_SMEM (3*2*ST_HALVES*2)

struct Job {
    const __half* A; const __half* B; const float* bias;
    float* C; __half* C16;
    int K, lda, ldb, ldc;
};

__global__ void __launch_bounds__(128, 2)
gemm_h(Job j0, Job j1, Job j2, int b1, int b2)
{
    extern __shared__ __half smh[];

    int bx = blockIdx.x;
    Job jb; int nOff;
    if (bx < b1)      { jb = j0; nOff = 0;  }
    else if (bx < b2) { jb = j1; nOff = b1; }
    else              { jb = j2; nOff = b2; }

    int K = jb.K, lda = jb.lda, ldb = jb.ldb, ldc = jb.ldc;

    int tid  = threadIdx.x;
    int warp = tid >> 5, lane = tid & 31;
    int wm = (warp >> 1) * 64;
    int wn = (warp & 1) * 64;
    int g  = lane >> 2, tg = lane & 3;

    int m0 = blockIdx.y * BM, n0 = (bx - nOff) * BN;

    const __half* Ag = jb.A + (long)(m0 + tid) * lda;
    const __half* Bg = jb.B + (long)(n0 + tid) * ldb;

    float acc[4][8][4];
    #pragma unroll
    for (int i = 0; i < 4; i++)
        #pragma unroll
        for (int j = 0; j < 8; j++)
            #pragma unroll
            for (int r = 0; r < 4; r++) acc[i][j][r] = 0.f;

    int nk = K / BK;
    unsigned uBase = (unsigned)__cvta_generic_to_shared(smh);

    auto issue = [&](int stage, int k0) {
        unsigned dA = uBase + stage * 2 * ST_HALVES * 2 + tid * ASTR * 2;
        unsigned dB = dA + ST_HALVES * 2;
        #pragma unroll
        for (int c = 0; c < 8; c++) {
            CP_ASYNC16(dA + c * 16, Ag + k0 + c * 8);
            CP_ASYNC16(dB + c * 16, Bg + k0 + c * 8);
        }
        CP_COMMIT();
    };

    issue(0, 0);
    if (nk > 1) issue(1, BK);
    if (nk > 1) CP_WAIT(1); else CP_WAIT(0);
    __syncthreads();

    int aRow = lane & 15;
    int aK   = (lane >> 4) * 8;
    int bRow = (lane & 7) + ((lane >> 4) & 1) * 8;
    int bK   = ((lane >> 3) & 1) * 8;

    for (int t = 0; t < nk; t++) {
        bool more = (t + 2 < nk);
        if (more) issue((t + 2) % 3, (t + 2) * BK);

        unsigned uA = uBase + (t % 3) * 2 * ST_HALVES * 2;
        unsigned uB = uA + ST_HALVES * 2;

        #pragma unroll
        for (int ks = 0; ks < 4; ks++) {
            int kb = ks * 16;
            unsigned a[4][4], b[8][2];
            #pragma unroll
            for (int i = 0; i < 4; i++) {
                unsigned ad = uA + ((wm + i*16 + aRow) * ASTR + kb + aK) * 2;
                LDSM_X4(a[i][0], a[i][1], a[i][2], a[i][3], ad);
            }
            #pragma unroll
            for (int jg = 0; jg < 4; jg++) {
                unsigned bd = uB + ((wn + jg*16 + bRow) * ASTR + kb + bK) * 2;
                LDSM_X4(b[2*jg][0], b[2*jg][1], b[2*jg+1][0], b[2*jg+1][1], bd);
            }
            #pragma unroll
            for (int i = 0; i < 4; i++)
                #pragma unroll
                for (int j = 0; j < 8; j++)
                    MMA_F16(acc[i][j], a[i], b[j]);
        }

        if (more) CP_WAIT(1); else CP_WAIT(0);
        __syncthreads();
    }

    #pragma unroll
    for (int i = 0; i < 4; i++) {
        int row0 = m0 + wm + i * 16 + g;
        #pragma unroll
        for (int j = 0; j < 8; j++) {
            int col = n0 + wn + j * 8 + tg * 2;
            float b0 = jb.bias ? jb.bias[col] : 0.f;
            float b1 = jb.bias ? jb.bias[col + 1] : 0.f;
            float v00 = acc[i][j][0] + b0, v01 = acc[i][j][1] + b1;
            float v10 = acc[i][j][2] + b0, v11 = acc[i][j][3] + b1;
            if (jb.C) {
                *(float2*)&jb.C[(long)row0 * ldc + col]       = make_float2(v00, v01);
                *(float2*)&jb.C[(long)(row0 + 8) * ldc + col] = make_float2(v10, v11);
            }
            if (jb.C16) {
                *(__half2*)&jb.C16[(long)row0 * ldc + col]       = __floats2half2_rn(v00, v01);
                *(__half2*)&jb.C16[(long)(row0 + 8) * ldc + col] = __floats2half2_rn(v10, v11);
            }
        }
    }
}

// ---------------------------------------------------------------------------
// Fused fp16 flash attention, P kept in registers (C-frag == A-frag layout).
// Block = 128 q rows x one (b,h), 256 threads, 2 CTAs/SM.
// smem halves: Q[128][136] | K[2][64][136] | V[2][64][136]   (no P buffer)
// ---------------------------------------------------------------------------
#define QSTR 136
#define FK 64
#define SH_Q 0
#define SH_K (SH_Q + 128*QSTR)
#define SH_V (SH_K + 2*FK*QSTR)
#define FLASH_SMEM ((SH_V + 2*FK*QSTR) * 2)   /* 104448 B -> 2 CTAs/SM */

__global__ void __launch_bounds__(256, 2)
flash_attn(const __half* __restrict__ Qg, const __half* __restrict__ Kg,
           const __half* __restrict__ Vg, __half* __restrict__ Og, float scale)
{
    extern __shared__ __half smh[];
    unsigned uS = (unsigned)__cvta_generic_to_shared(smh);

    int tid = threadIdx.x;
    int warp = tid >> 5, lane = tid & 31;
    int g = lane >> 2, tg = lane & 3;
    int wm = warp * 16;

    int z  = blockIdx.y;
    int bb = z / NH, hh = z % NH;
    long tok0 = (long)bb * S_LEN + blockIdx.x * 128;
    const __half* Qb = Qg + tok0 * HIDV + hh * HD;
    const __half* Kb = Kg + (long)bb * S_LEN * HIDV + hh * HD;
    const __half* Vb = Vg + (long)bb * S_LEN * HIDV + hh * HD;

    #pragma unroll
    for (int i = 0; i < 8; i++) {
        int s = tid + i * 256;
        int row = s >> 4, ch = s & 15;
        CP_ASYNC16(uS + (SH_Q + row * QSTR + ch * 8) * 2,
                   Qb + (long)row * HIDV + ch * 8);
    }
    CP_COMMIT();

    auto issueKV = [&](int st, int kt) {
        #pragma unroll
        for (int i = 0; i < 4; i++) {
            int s = tid + i * 256;
            int row = s >> 4, ch = s & 15;
            long goff = (long)(kt * FK + row) * HIDV + ch * 8;
            CP_ASYNC16(uS + (SH_K + st * FK * QSTR + row * QSTR + ch * 8) * 2, Kb + goff);
            CP_ASYNC16(uS + (SH_V + st * FK * QSTR + row * QSTR + ch * 8) * 2, Vb + goff);
        }
        CP_COMMIT();
    };
    issueKV(0, 0);

    float m0 = -1e30f, m1 = -1e30f, l0 = 0.f, l1 = 0.f;
    float o[16][4];
    #pragma unroll
    for (int j = 0; j < 16; j++)
        #pragma unroll
        for (int r = 0; r < 4; r++) o[j][r] = 0.f;

    int aRow = lane & 15;
    int aK   = (lane >> 4) * 8;
    int bRow = (lane & 7) + ((lane >> 4) & 1) * 8;
    int bK   = ((lane >> 3) & 1) * 8;
    int vK   = (lane & 7) + ((lane >> 3) & 1) * 8;
    int vN   = ((lane >> 4) & 1) * 8;

    for (int kt = 0; kt < S_LEN / FK; kt++) {
        CP_WAIT(0);
        __syncthreads();
        if (kt + 1 < S_LEN / FK) issueKV((kt + 1) & 1, kt + 1);

        int kOff = SH_K + (kt & 1) * FK * QSTR;
        int vOff = SH_V + (kt & 1) * FK * QSTR;

        // ---- S = Q @ K^T ----
        float s_acc[8][4];
        #pragma unroll
        for (int j = 0; j < 8; j++)
            #pragma unroll
            for (int r = 0; r < 4; r++) s_acc[j][r] = 0.f;

        #pragma unroll
        for (int ks = 0; ks < 8; ks++) {
            int kb = ks * 16;
            unsigned a[4];
            LDSM_X4(a[0], a[1], a[2], a[3],
                uS + (SH_Q + (wm + aRow) * QSTR + kb + aK) * 2);
            #pragma unroll
            for (int jg = 0; jg < 4; jg++) {
                unsigned b0[2], b1[2];
                LDSM_X4(b0[0], b0[1], b1[0], b1[1],
                    uS + (kOff + (jg*16 + bRow) * QSTR + kb + bK) * 2);
                MMA_F16(s_acc[2*jg],   a, b0);
                MMA_F16(s_acc[2*jg+1], a, b1);
            }
        }

        // ---- online softmax, P packed in-place into s_acc registers ----
        #pragma unroll
        for (int j = 0; j < 8; j++)
            #pragma unroll
            for (int r = 0; r < 4; r++) s_acc[j][r] *= scale;

        float mx0 = -1e30f, mx1 = -1e30f;
        #pragma unroll
        for (int j = 0; j < 8; j++) {
            mx0 = fmaxf(mx0, fmaxf(s_acc[j][0], s_acc[j][1]));
            mx1 = fmaxf(mx1, fmaxf(s_acc[j][2], s_acc[j][3]));
        }
        mx0 = fmaxf(mx0, __shfl_xor_sync(0xffffffffu, mx0, 1));
        mx0 = fmaxf(mx0, __shfl_xor_sync(0xffffffffu, mx0, 2));
        mx1 = fmaxf(mx1, __shfl_xor_sync(0xffffffffu, mx1, 1));
        mx1 = fmaxf(mx1, __shfl_xor_sync(0xffffffffu, mx1, 2));

        float mn0 = fmaxf(m0, mx0), mn1 = fmaxf(m1, mx1);
        float al0 = __expf(m0 - mn0), al1 = __expf(m1 - mn1);
        float sum0 = 0.f, sum1 = 0.f;
        #pragma unroll
        for (int j = 0; j < 8; j++) {
            float p00 = __expf(s_acc[j][0] - mn0);
            float p01 = __expf(s_acc[j][1] - mn0);
            float p10 = __expf(s_acc[j][2] - mn1);
            float p11 = __expf(s_acc[j][3] - mn1);
            sum0 += p00 + p01; sum1 += p10 + p11;
            // C-frag -> A-frag identity: (c0,c1)=row g -> a_even, (c2,c3)=row g+8 -> a_odd
            s_acc[j][0] = __uint_as_float(pack_h2(p00, p01));
            s_acc[j][1] = __uint_as_float(pack_h2(p10, p11));
        }
        sum0 += __shfl_xor_sync(0xffffffffu, sum0, 1);
        sum0 += __shfl_xor_sync(0xffffffffu, sum0, 2);
        sum1 += __shfl_xor_sync(0xffffffffu, sum1, 1);
        sum1 += __shfl_xor_sync(0xffffffffu, sum1, 2);
        l0 = l0 * al0 + sum0;
        l1 = l1 * al1 + sum1;
        m0 = mn0; m1 = mn1;
        #pragma unroll
        for (int j = 0; j < 16; j++) {
            o[j][0] *= al0; o[j][1] *= al0;
            o[j][2] *= al1; o[j][3] *= al1;
        }

        // ---- O += P @ V : P A-fragments straight from registers ----
        #pragma unroll
        for (int ks = 0; ks < 4; ks++) {
            int kb = ks * 16;
            unsigned a[4];
            a[0] = __float_as_uint(s_acc[2*ks][0]);
            a[1] = __float_as_uint(s_acc[2*ks][1]);
            a[2] = __float_as_uint(s_acc[2*ks+1][0]);
            a[3] = __float_as_uint(s_acc[2*ks+1][1]);
            #pragma unroll
            for (int ng = 0; ng < 8; ng++) {
                unsigned b0[2], b1[2];
                LDSM_X4_T(b0[0], b0[1], b1[0], b1[1],
                    uS + (vOff + (kb + vK) * QSTR + ng*16 + vN) * 2);
                MMA_F16(o[2*ng],   a, b0);
                MMA_F16(o[2*ng+1], a, b1);
            }
        }
    }

    float inv0 = 1.0f / l0, inv1 = 1.0f / l1;
    __half* Ob = Og + tok0 * HIDV + hh * HD;
    #pragma unroll
    for (int j = 0; j < 16; j++) {
        int col = j * 8 + tg * 2;
        *(__half2*)&Ob[(long)(wm + g) * HIDV + col] =
            __floats2half2_rn(o[j][0] * inv0, o[j][1] * inv0);
        *(__half2*)&Ob[(long)(wm + 8 + g) * HIDV + col] =
            __floats2half2_rn(o[j][2] * inv1, o[j][3] * inv1);
    }
}

// ---------------------------------------------------------------------------
__global__ void __launch_bounds__(64)
kr_rope(const __half* __restrict__ Kbuf, const float* __restrict__ Wkr,
        const float* __restrict__ bkr, float* __restrict__ out)
{
    int bid = blockIdx.x;
    int t = bid / NH, h = bid % NH;
    int s = t % S_LEN;
    __shared__ float kv[128];
    __shared__ float kr[64];
    int tid = threadIdx.x;

    kv[tid]      = __half2float(Kbuf[(long)t * HIDV + h * HD + tid]);
    kv[tid + 64] = __half2float(Kbuf[(long)t * HIDV + h * HD + tid + 64]);
    __syncthreads();

    float acc = bkr[tid];
    #pragma unroll 4
    for (int c = 0; c < 128; c++)
        acc += Wkr[tid * 128 + c] * kv[c];
    kr[tid] = acc;
    __syncthreads();

    int j = tid & 31;
    float inv_freq = expf(-(float)j * 0.28782313662425573f);
    float f = (float)s * inv_freq;
    float sn, cs;
    sincosf(f, &sn, &cs);
    float rot = (tid < 32) ? -kr[tid + 32] : kr[tid - 32];
    out[(long)t * (NH * RR) + h * RR + tid] = kr[tid] * cs + rot * sn;
}

// ---------------------------------------------------------------------------
extern "C" void kernel_launch(void* const* d_in, const int* in_sizes, int n_in,
                              void* d_out, int out_size)
{
    const float* hid  = (const float*)d_in[0];
    const float* Wdkv = (const float*)d_in[1];
    const float* bdkv = (const float*)d_in[2];
    const float* Wuk  = (const float*)d_in[3];
    const float* buk  = (const float*)d_in[4];
    const float* Wuv  = (const float*)d_in[5];
    const float* buv  = (const float*)d_in[6];
    const float* Wkr  = (const float*)d_in[7];
    const float* bkr  = (const float*)d_in[8];
    const float* Wdq  = (const float*)d_in[9];
    const float* bdq  = (const float*)d_in[10];
    const float* Wuq  = (const float*)d_in[11];
    const float* buq  = (const float*)d_in[12];
    // d_in[13..14] = W_QR — dead (q_r unused in reference)
    const float* Wo   = (const float*)d_in[15];
    const float* bo   = (const float*)d_in[16];

    float* out  = (float*)d_out;
    float* c_kv = out  + (long)NTOK * HIDV;
    float* kr   = c_kv + (long)NTOK * KVC;

    __half *h16, *ckv16, *cq16, *k16, *v16, *q16, *a16, *w16;
    cudaGetSymbolAddress((void**)&h16,   g_h16);
    cudaGetSymbolAddress((void**)&ckv16, g_ckv16);
    cudaGetSymbolAddress((void**)&cq16,  g_cq16);
    cudaGetSymbolAddress((void**)&k16,   g_k16);
    cudaGetSymbolAddress((void**)&v16,   g_v16);
    cudaGetSymbolAddress((void**)&q16,   g_q16);
    cudaGetSymbolAddress((void**)&a16,   g_a16);
    cudaGetSymbolAddress((void**)&w16,   g_w16);

    const float scale = 0.08838834764831845f;
    static int attr_set = 0;
    if (!attr_set) {
        cudaFuncSetAttribute(gemm_h,
            cudaFuncAttributeMaxDynamicSharedMemorySize, GEMM_SMEM);
        cudaFuncSetAttribute(flash_attn,
            cudaFuncAttributeMaxDynamicSharedMemorySize, FLASH_SMEM);
        attr_set = 1;
    }

    auto cvt = [&](const float* s, __half* d, int n) {
        int n4 = n / 4;
        cvt_f2h<<<(n4 + 255) / 256, 256>>>((const float4*)s, (__half2*)d, n4);
    };
    cvt(hid,  h16,            NTOK * HIDV);
    cvt(Wdkv, w16 + OFF_DKV,  KVC * HIDV);
    cvt(Wuk,  w16 + OFF_UK,   HIDV * KVC);
    cvt(Wuv,  w16 + OFF_UV,   HIDV * KVC);
    cvt(Wdq,  w16 + OFF_DQ,   QCV * HIDV);
    cvt(Wuq,  w16 + OFF_UQ,   HIDV * QCV);
    cvt(Wo,   w16 + OFF_O,    HIDV * HIDV);

    // L1: c_kv (N=512, fp32+fp16 out) + c_q (N=1536, fp16). K=2048.
    {
        Job ja = { h16, w16 + OFF_DKV, bdkv, c_kv,   ckv16, HIDV, HIDV, HIDV, KVC };
        Job jb = { h16, w16 + OFF_DQ,  bdq,  nullptr, cq16, HIDV, HIDV, HIDV, QCV };
        gemm_h<<<dim3(16, NTOK/BM), 128, GEMM_SMEM>>>(ja, jb, jb, 4, 16);
    }

    // L2: k (K=512) + v (K=512) + q (K=1536), all N=2048, fp16 out.
    {
        Job ja = { ckv16, w16 + OFF_UK, buk, nullptr, k16, KVC, KVC, KVC, HIDV };
        Job jb = { ckv16, w16 + OFF_UV, buv, nullptr, v16, KVC, KVC, KVC, HIDV };
        Job jc = { cq16,  w16 + OFF_UQ, buq, nullptr, q16, QCV, QCV, QCV, HIDV };
        gemm_h<<<dim3(48, NTOK/BM), 128, GEMM_SMEM>>>(ja, jb, jc, 16, 32);
    }

    // k_r (+RoPE) -> d_out section
    kr_rope<<<NTOK * NH, 64>>>(k16, Wkr, bkr, kr);

    // fused flash attention -> a16
    flash_attn<<<dim3(S_LEN/128, BATCH*NH), 256, FLASH_SMEM>>>(
        q16, k16, v16, a16, scale);

    // L4: output = attn @ W_O^T + b -> fp32 d_out
    {
        Job ja = { a16, w16 + OFF_O, bo, out, nullptr, HIDV, HIDV, HIDV, HIDV };
        gemm_h<<<dim3(16, NTOK/BM), 128, GEMM_SMEM>>>(ja, ja, ja, 16, 16);
    }
}

// round 9
// speedup vs baseline: 8.2228x; 2.7155x over previous
#include <cuda_runtime.h>
#include <cuda_fp16.h>
#include <math.h>
#include <stdint.h>

#define S_LEN 1024
#define BATCH 2
#define HIDV  2048
#define NH    16
#define HD    128
#define RR    64
#define KVC   512
#define QCV   1536
#define NTOK  (BATCH*S_LEN)   /* 2048 */

// ---------------- scratch (static device globals; no allocation) ----------------
__device__ __align__(256) __half g_h16 [NTOK*(size_t)HIDV];
__device__ __align__(256) __half g_ckv16[NTOK*(size_t)KVC];
__device__ __align__(256) __half g_cq16 [NTOK*(size_t)QCV];
__device__ __align__(256) __half g_k16 [NTOK*(size_t)HIDV];
__device__ __align__(256) __half g_v16 [NTOK*(size_t)HIDV];
__device__ __align__(256) __half g_q16 [NTOK*(size_t)HIDV];
__device__ __align__(256) __half g_a16 [NTOK*(size_t)HIDV];
__device__ __align__(256) float  g_wkrT[HD*RR];      // transposed W_KR
#define OFF_DKV 0
#define OFF_UK  (OFF_DKV + KVC*HIDV)
#define OFF_UV  (OFF_UK  + HIDV*KVC)
#define OFF_DQ  (OFF_UV  + HIDV*KVC)
#define OFF_UQ  (OFF_DQ  + QCV*HIDV)
#define OFF_O   (OFF_UQ  + HIDV*QCV)
#define W16_TOTAL (OFF_O + HIDV*HIDV)
__device__ __align__(256) __half g_w16[W16_TOTAL];

// ---------------- PTX helpers ----------------
#define MMA_F16(d, a, b) \
    asm volatile("mma.sync.aligned.m16n8k16.row.col.f32.f16.f16.f32 " \
        "{%0,%1,%2,%3}, {%4,%5,%6,%7}, {%8,%9}, {%0,%1,%2,%3};" \
        : "+f"(d[0]), "+f"(d[1]), "+f"(d[2]), "+f"(d[3]) \
        : "r"(a[0]), "r"(a[1]), "r"(a[2]), "r"(a[3]), "r"(b[0]), "r"(b[1]))

#define LDSM_X4(r0,r1,r2,r3,addr) \
    asm volatile("ldmatrix.sync.aligned.m8n8.x4.shared.b16 {%0,%1,%2,%3}, [%4];" \
        : "=r"(r0),"=r"(r1),"=r"(r2),"=r"(r3) : "r"(addr))
#define LDSM_X4_T(r0,r1,r2,r3,addr) \
    asm volatile("ldmatrix.sync.aligned.m8n8.x4.trans.shared.b16 {%0,%1,%2,%3}, [%4];" \
        : "=r"(r0),"=r"(r1),"=r"(r2),"=r"(r3) : "r"(addr))

#define CP_ASYNC16(dst_sm, src) \
    asm volatile("cp.async.cg.shared.global [%0], [%1], 16;" \
        :: "r"(dst_sm), "l"(src))
#define CP_COMMIT() asm volatile("cp.async.commit_group;" ::: "memory")
#define CP_WAIT(n)  asm volatile("cp.async.wait_group %0;" :: "n"(n) : "memory")

__device__ __forceinline__ uint32_t pack_h2(float a, float b) {
    __half2 h = __floats2half2_rn(a, b);
    return *reinterpret_cast<uint32_t*>(&h);
}

// ---------------------------------------------------------------------------
// Merged fp32 -> fp16 conversion over 7 segments (single launch)
// ---------------------------------------------------------------------------
struct C7 {
    const float4* s[7];
    __half2*      d[7];
    int cum[8];   // cumulative n4 boundaries
};

__global__ void __launch_bounds__(256)
cvt_multi(C7 j)
{
    int i = blockIdx.x * 256 + threadIdx.x;
    if (i >= j.cum[7]) return;
    int k = 0;
    #pragma unroll
    for (int q = 1; q < 7; q++) if (i >= j.cum[q]) k = q;
    int loc = i - j.cum[k];
    float4 v = j.s[k][loc];
    j.d[k][2*loc]   = __floats2half2_rn(v.x, v.y);
    j.d[k][2*loc+1] = __floats2half2_rn(v.z, v.w);
}

// ---------------------------------------------------------------------------
// W_KR transpose: WkrT[c*64 + r] = Wkr[r*128 + c]
// ---------------------------------------------------------------------------
__global__ void __launch_bounds__(256)
wkr_t(const float* __restrict__ Wkr, float* __restrict__ WkrT)
{
    int i = blockIdx.x * 256 + threadIdx.x;   // i over 8192
    if (i < HD * RR) {
        int c = i >> 6, r = i & 63;
        WkrT[i] = Wkr[r * HD + c];
    }
}

// ---------------------------------------------------------------------------
// Multi-job fp16 GEMM (unchanged from R8 — passing)
// ---------------------------------------------------------------------------
#define BM 128
#define BN 128
#define BK 64
#define ASTR 72
#define ST_HALVES (128*ASTR)
#define GEMM_SMEM (3*2*ST_HALVES*2)

struct Job {
    const __half* A; const __half* B; const float* bias;
    float* C; __half* C16;
    int K, lda, ldb, ldc;
};

__global__ void __launch_bounds__(128, 2)
gemm_h(Job j0, Job j1, Job j2, int b1, int b2)
{
    extern __shared__ __half smh[];

    int bx = blockIdx.x;
    Job jb; int nOff;
    if (bx < b1)      { jb = j0; nOff = 0;  }
    else if (bx < b2) { jb = j1; nOff = b1; }
    else              { jb = j2; nOff = b2; }

    int K = jb.K, lda = jb.lda, ldb = jb.ldb, ldc = jb.ldc;

    int tid  = threadIdx.x;
    int warp = tid >> 5, lane = tid & 31;
    int wm = (warp >> 1) * 64;
    int wn = (warp & 1) * 64;
    int g  = lane >> 2, tg = lane & 3;

    int m0 = blockIdx.y * BM, n0 = (bx - nOff) * BN;

    const __half* Ag = jb.A + (long)(m0 + tid) * lda;
    const __half* Bg = jb.B + (long)(n0 + tid) * ldb;

    float acc[4][8][4];
    #pragma unroll
    for (int i = 0; i < 4; i++)
        #pragma unroll
        for (int j = 0; j < 8; j++)
            #pragma unroll
            for (int r = 0; r < 4; r++) acc[i][j][r] = 0.f;

    int nk = K / BK;
    unsigned uBase = (unsigned)__cvta_generic_to_shared(smh);

    auto issue = [&](int stage, int k0) {
        unsigned dA = uBase + stage * 2 * ST_HALVES * 2 + tid * ASTR * 2;
        unsigned dB = dA + ST_HALVES * 2;
        #pragma unroll
        for (int c = 0; c < 8; c++) {
            CP_ASYNC16(dA + c * 16, Ag + k0 + c * 8);
            CP_ASYNC16(dB + c * 16, Bg + k0 + c * 8);
        }
        CP_COMMIT();
    };

    issue(0, 0);
    if (nk > 1) issue(1, BK);
    if (nk > 1) CP_WAIT(1); else CP_WAIT(0);
    __syncthreads();

    int aRow = lane & 15;
    int aK   = (lane >> 4) * 8;
    int bRow = (lane & 7) + ((lane >> 4) & 1) * 8;
    int bK   = ((lane >> 3) & 1) * 8;

    for (int t = 0; t < nk; t++) {
        bool more = (t + 2 < nk);
        if (more) issue((t + 2) % 3, (t + 2) * BK);

        unsigned uA = uBase + (t % 3) * 2 * ST_HALVES * 2;
        unsigned uB = uA + ST_HALVES * 2;

        #pragma unroll
        for (int ks = 0; ks < 4; ks++) {
            int kb = ks * 16;
            unsigned a[4][4], b[8][2];
            #pragma unroll
            for (int i = 0; i < 4; i++) {
                unsigned ad = uA + ((wm + i*16 + aRow) * ASTR + kb + aK) * 2;
                LDSM_X4(a[i][0], a[i][1], a[i][2], a[i][3], ad);
            }
            #pragma unroll
            for (int jg = 0; jg < 4; jg++) {
                unsigned bd = uB + ((wn + jg*16 + bRow) * ASTR + kb + bK) * 2;
                LDSM_X4(b[2*jg][0], b[2*jg][1], b[2*jg+1][0], b[2*jg+1][1], bd);
            }
            #pragma unroll
            for (int i = 0; i < 4; i++)
                #pragma unroll
                for (int j = 0; j < 8; j++)
                    MMA_F16(acc[i][j], a[i], b[j]);
        }

        if (more) CP_WAIT(1); else CP_WAIT(0);
        __syncthreads();
    }

    #pragma unroll
    for (int i = 0; i < 4; i++) {
        int row0 = m0 + wm + i * 16 + g;
        #pragma unroll
        for (int j = 0; j < 8; j++) {
            int col = n0 + wn + j * 8 + tg * 2;
            float b0 = jb.bias ? jb.bias[col] : 0.f;
            float b1 = jb.bias ? jb.bias[col + 1] : 0.f;
            float v00 = acc[i][j][0] + b0, v01 = acc[i][j][1] + b1;
            float v10 = acc[i][j][2] + b0, v11 = acc[i][j][3] + b1;
            if (jb.C) {
                *(float2*)&jb.C[(long)row0 * ldc + col]       = make_float2(v00, v01);
                *(float2*)&jb.C[(long)(row0 + 8) * ldc + col] = make_float2(v10, v11);
            }
            if (jb.C16) {
                *(__half2*)&jb.C16[(long)row0 * ldc + col]       = __floats2half2_rn(v00, v01);
                *(__half2*)&jb.C16[(long)(row0 + 8) * ldc + col] = __floats2half2_rn(v10, v11);
            }
        }
    }
}

// ---------------------------------------------------------------------------
// kr_rope v2: batched, coalesced, conflict-free.
// Block = 128 threads = 4 warps; each warp owns one (t,h) pair at a time and
// each lane computes outputs (r=lane, r=lane+32) so RoPE is thread-local.
// WkrT cached in smem (32 KB), 32 pairs of k rows staged per block (16 KB).
// ---------------------------------------------------------------------------
#define KR_G 32

__global__ void __launch_bounds__(128)
kr_rope2(const __half* __restrict__ k16, const float* __restrict__ WkrT,
         const float* __restrict__ bkr, float* __restrict__ out)
{
    __shared__ float sW[HD * RR];        // [c][r], 32 KB
    __shared__ float sKV[KR_G * HD];     // 16 KB

    int tid = threadIdx.x;
    int warp = tid >> 5, lane = tid & 31;

    #pragma unroll
    for (int i = tid; i < HD * RR; i += 128) sW[i] = WkrT[i];

    // k rows for pairs [bid*32, bid*32+32): contiguous halves (g*128 + c)
    const __half2* src = (const __half2*)(k16 + (size_t)blockIdx.x * KR_G * HD);
    #pragma unroll
    for (int i = tid; i < KR_G * HD / 2; i += 128) {
        float2 f = __half22float2(src[i]);
        sKV[2*i] = f.x; sKV[2*i + 1] = f.y;
    }
    __syncthreads();

    float b0 = bkr[lane], b1 = bkr[lane + 32];
    float inv_freq = expf(-(float)lane * 0.28782313662425573f); // ln(10000)/32

    for (int p = warp; p < KR_G; p += 4) {
        const float* kv = &sKV[p * HD];
        float a0 = b0, a1 = b1;
        #pragma unroll 8
        for (int c = 0; c < HD; c++) {
            float kvc = kv[c];
            a0 += kvc * sW[c * RR + lane];
            a1 += kvc * sW[c * RR + lane + 32];
        }
        int gidx = blockIdx.x * KR_G + p;
        int t = gidx >> 4, h = gidx & 15;
        int s = t & (S_LEN - 1);
        float sn, cs;
        sincosf((float)s * inv_freq, &sn, &cs);
        long o = (long)t * (NH * RR) + h * RR + lane;
        out[o]      = a0 * cs - a1 * sn;   // r < 32: kr[r]*cos - kr[r+32]*sin
        out[o + 32] = a1 * cs + a0 * sn;   // r >= 32: kr[r]*cos + kr[r-32]*sin
    }
}

// ---------------------------------------------------------------------------
// Fused fp16 flash attention (unchanged from R8 — passing)
// ---------------------------------------------------------------------------
#define QSTR 136
#define FK 64
#define SH_Q 0
#define SH_K (SH_Q + 128*QSTR)
#define SH_V (SH_K + 2*FK*QSTR)
#define FLASH_SMEM ((SH_V + 2*FK*QSTR) * 2)

__global__ void __launch_bounds__(256, 2)
flash_attn(const __half* __restrict__ Qg, const __half* __restrict__ Kg,
           const __half* __restrict__ Vg, __half* __restrict__ Og, float scale)
{
    extern __shared__ __half smh[];
    unsigned uS = (unsigned)__cvta_generic_to_shared(smh);

    int tid = threadIdx.x;
    int warp = tid >> 5, lane = tid & 31;
    int g = lane >> 2, tg = lane & 3;
    int wm = warp * 16;

    int z  = blockIdx.y;
    int bb = z / NH, hh = z % NH;
    long tok0 = (long)bb * S_LEN + blockIdx.x * 128;
    const __half* Qb = Qg + tok0 * HIDV + hh * HD;
    const __half* Kb = Kg + (long)bb * S_LEN * HIDV + hh * HD;
    const __half* Vb = Vg + (long)bb * S_LEN * HIDV + hh * HD;

    #pragma unroll
    for (int i = 0; i < 8; i++) {
        int s = tid + i * 256;
        int row = s >> 4, ch = s & 15;
        CP_ASYNC16(uS + (SH_Q + row * QSTR + ch * 8) * 2,
                   Qb + (long)row * HIDV + ch * 8);
    }
    CP_COMMIT();

    auto issueKV = [&](int st, int kt) {
        #pragma unroll
        for (int i = 0; i < 4; i++) {
            int s = tid + i * 256;
            int row = s >> 4, ch = s & 15;
            long goff = (long)(kt * FK + row) * HIDV + ch * 8;
            CP_ASYNC16(uS + (SH_K + st * FK * QSTR + row * QSTR + ch * 8) * 2, Kb + goff);
            CP_ASYNC16(uS + (SH_V + st * FK * QSTR + row * QSTR + ch * 8) * 2, Vb + goff);
        }
        CP_COMMIT();
    };
    issueKV(0, 0);

    float m0 = -1e30f, m1 = -1e30f, l0 = 0.f, l1 = 0.f;
    float o[16][4];
    #pragma unroll
    for (int j = 0; j < 16; j++)
        #pragma unroll
        for (int r = 0; r < 4; r++) o[j][r] = 0.f;

    int aRow = lane & 15;
    int aK   = (lane >> 4) * 8;
    int bRow = (lane & 7) + ((lane >> 4) & 1) * 8;
    int bK   = ((lane >> 3) & 1) * 8;
    int vK   = (lane & 7) + ((lane >> 3) & 1) * 8;
    int vN   = ((lane >> 4) & 1) * 8;

    for (int kt = 0; kt < S_LEN / FK; kt++) {
        CP_WAIT(0);
        __syncthreads();
        if (kt + 1 < S_LEN / FK) issueKV((kt + 1) & 1, kt + 1);

        int kOff = SH_K + (kt & 1) * FK * QSTR;
        int vOff = SH_V + (kt & 1) * FK * QSTR;

        float s_acc[8][4];
        #pragma unroll
        for (int j = 0; j < 8; j++)
            #pragma unroll
            for (int r = 0; r < 4; r++) s_acc[j][r] = 0.f;

        #pragma unroll
        for (int ks = 0; ks < 8; ks++) {
            int kb = ks * 16;
            unsigned a[4];
            LDSM_X4(a[0], a[1], a[2], a[3],
                uS + (SH_Q + (wm + aRow) * QSTR + kb + aK) * 2);
            #pragma unroll
            for (int jg = 0; jg < 4; jg++) {
                unsigned b0[2], b1[2];
                LDSM_X4(b0[0], b0[1], b1[0], b1[1],
                    uS + (kOff + (jg*16 + bRow) * QSTR + kb + bK) * 2);
                MMA_F16(s_acc[2*jg],   a, b0);
                MMA_F16(s_acc[2*jg+1], a, b1);
            }
        }

        #pragma unroll
        for (int j = 0; j < 8; j++)
            #pragma unroll
            for (int r = 0; r < 4; r++) s_acc[j][r] *= scale;

        float mx0 = -1e30f, mx1 = -1e30f;
        #pragma unroll
        for (int j = 0; j < 8; j++) {
            mx0 = fmaxf(mx0, fmaxf(s_acc[j][0], s_acc[j][1]));
            mx1 = fmaxf(mx1, fmaxf(s_acc[j][2], s_acc[j][3]));
        }
        mx0 = fmaxf(mx0, __shfl_xor_sync(0xffffffffu, mx0, 1));
        mx0 = fmaxf(mx0, __shfl_xor_sync(0xffffffffu, mx0, 2));
        mx1 = fmaxf(mx1, __shfl_xor_sync(0xffffffffu, mx1, 1));
        mx1 = fmaxf(mx1, __shfl_xor_sync(0xffffffffu, mx1, 2));

        float mn0 = fmaxf(m0, mx0), mn1 = fmaxf(m1, mx1);
        float al0 = __expf(m0 - mn0), al1 = __expf(m1 - mn1);
        float sum0 = 0.f, sum1 = 0.f;
        #pragma unroll
        for (int j = 0; j < 8; j++) {
            float p00 = __expf(s_acc[j][0] - mn0);
            float p01 = __expf(s_acc[j][1] - mn0);
            float p10 = __expf(s_acc[j][2] - mn1);
            float p11 = __expf(s_acc[j][3] - mn1);
            sum0 += p00 + p01; sum1 += p10 + p11;
            s_acc[j][0] = __uint_as_float(pack_h2(p00, p01));
            s_acc[j][1] = __uint_as_float(pack_h2(p10, p11));
        }
        sum0 += __shfl_xor_sync(0xffffffffu, sum0, 1);
        sum0 += __shfl_xor_sync(0xffffffffu, sum0, 2);
        sum1 += __shfl_xor_sync(0xffffffffu, sum1, 1);
        sum1 += __shfl_xor_sync(0xffffffffu, sum1, 2);
        l0 = l0 * al0 + sum0;
        l1 = l1 * al1 + sum1;
        m0 = mn0; m1 = mn1;
        #pragma unroll
        for (int j = 0; j < 16; j++) {
            o[j][0] *= al0; o[j][1] *= al0;
            o[j][2] *= al1; o[j][3] *= al1;
        }

        #pragma unroll
        for (int ks = 0; ks < 4; ks++) {
            int kb = ks * 16;
            unsigned a[4];
            a[0] = __float_as_uint(s_acc[2*ks][0]);
            a[1] = __float_as_uint(s_acc[2*ks][1]);
            a[2] = __float_as_uint(s_acc[2*ks+1][0]);
            a[3] = __float_as_uint(s_acc[2*ks+1][1]);
            #pragma unroll
            for (int ng = 0; ng < 8; ng++) {
                unsigned b0[2], b1[2];
                LDSM_X4_T(b0[0], b0[1], b1[0], b1[1],
                    uS + (vOff + (kb + vK) * QSTR + ng*16 + vN) * 2);
                MMA_F16(o[2*ng],   a, b0);
                MMA_F16(o[2*ng+1], a, b1);
            }
        }
    }

    float inv0 = 1.0f / l0, inv1 = 1.0f / l1;
    __half* Ob = Og + tok0 * HIDV + hh * HD;
    #pragma unroll
    for (int j = 0; j < 16; j++) {
        int col = j * 8 + tg * 2;
        *(__half2*)&Ob[(long)(wm + g) * HIDV + col] =
            __floats2half2_rn(o[j][0] * inv0, o[j][1] * inv0);
        *(__half2*)&Ob[(long)(wm + 8 + g) * HIDV + col] =
            __floats2half2_rn(o[j][2] * inv1, o[j][3] * inv1);
    }
}

// ---------------------------------------------------------------------------
extern "C" void kernel_launch(void* const* d_in, const int* in_sizes, int n_in,
                              void* d_out, int out_size)
{
    const float* hid  = (const float*)d_in[0];
    const float* Wdkv = (const float*)d_in[1];
    const float* bdkv = (const float*)d_in[2];
    const float* Wuk  = (const float*)d_in[3];
    const float* buk  = (const float*)d_in[4];
    const float* Wuv  = (const float*)d_in[5];
    const float* buv  = (const float*)d_in[6];
    const float* Wkr  = (const float*)d_in[7];
    const float* bkr  = (const float*)d_in[8];
    const float* Wdq  = (const float*)d_in[9];
    const float* bdq  = (const float*)d_in[10];
    const float* Wuq  = (const float*)d_in[11];
    const float* buq  = (const float*)d_in[12];
    // d_in[13..14] = W_QR — dead (q_r unused in reference)
    const float* Wo   = (const float*)d_in[15];
    const float* bo   = (const float*)d_in[16];

    float* out  = (float*)d_out;
    float* c_kv = out  + (long)NTOK * HIDV;
    float* kr   = c_kv + (long)NTOK * KVC;

    __half *h16, *ckv16, *cq16, *k16, *v16, *q16, *a16, *w16;
    float  *wkrT;
    cudaGetSymbolAddress((void**)&h16,   g_h16);
    cudaGetSymbolAddress((void**)&ckv16, g_ckv16);
    cudaGetSymbolAddress((void**)&cq16,  g_cq16);
    cudaGetSymbolAddress((void**)&k16,   g_k16);
    cudaGetSymbolAddress((void**)&v16,   g_v16);
    cudaGetSymbolAddress((void**)&q16,   g_q16);
    cudaGetSymbolAddress((void**)&a16,   g_a16);
    cudaGetSymbolAddress((void**)&w16,   g_w16);
    cudaGetSymbolAddress((void**)&wkrT,  g_wkrT);

    const float scale = 0.08838834764831845f;
    static int attr_set = 0;
    if (!attr_set) {
        cudaFuncSetAttribute(gemm_h,
            cudaFuncAttributeMaxDynamicSharedMemorySize, GEMM_SMEM);
        cudaFuncSetAttribute(flash_attn,
            cudaFuncAttributeMaxDynamicSharedMemorySize, FLASH_SMEM);
        attr_set = 1;
    }

    // Launch 1: all fp32->fp16 conversions in one kernel
    {
        C7 j;
        const float* srcs[7] = { hid, Wdkv, Wuk, Wuv, Wdq, Wuq, Wo };
        __half* dsts[7] = { h16, w16 + OFF_DKV, w16 + OFF_UK, w16 + OFF_UV,
                            w16 + OFF_DQ, w16 + OFF_UQ, w16 + OFF_O };
        int sizes[7] = { NTOK*HIDV, KVC*HIDV, HIDV*KVC, HIDV*KVC,
                         QCV*HIDV, HIDV*QCV, HIDV*HIDV };
        int cum = 0;
        for (int k = 0; k < 7; k++) {
            j.s[k] = (const float4*)srcs[k];
            j.d[k] = (__half2*)dsts[k];
            j.cum[k] = cum;
            cum += sizes[k] / 4;
        }
        j.cum[7] = cum;
        cvt_multi<<<(cum + 255) / 256, 256>>>(j);
    }

    // Launch 2: W_KR transpose
    wkr_t<<<(HD*RR + 255) / 256, 256>>>(Wkr, wkrT);

    // Launch 3 (L1): c_kv (N=512, fp32+fp16 out) + c_q (N=1536, fp16). K=2048.
    {
        Job ja = { h16, w16 + OFF_DKV, bdkv, c_kv,   ckv16, HIDV, HIDV, HIDV, KVC };
        Job jb = { h16, w16 + OFF_DQ,  bdq,  nullptr, cq16, HIDV, HIDV, HIDV, QCV };
        gemm_h<<<dim3(16, NTOK/BM), 128, GEMM_SMEM>>>(ja, jb, jb, 4, 16);
    }

    // Launch 4 (L2): k + v (K=512) + q (K=1536), all N=2048, fp16 out.
    {
        Job ja = { ckv16, w16 + OFF_UK, buk, nullptr, k16, KVC, KVC, KVC, HIDV };
        Job jb = { ckv16, w16 + OFF_UV, buv, nullptr, v16, KVC, KVC, KVC, HIDV };
        Job jc = { cq16,  w16 + OFF_UQ, buq, nullptr, q16, QCV, QCV, QCV, HIDV };
        gemm_h<<<dim3(48, NTOK/BM), 128, GEMM_SMEM>>>(ja, jb, jc, 16, 32);
    }

    // Launch 5: k_r (+RoPE), batched/coalesced
    kr_rope2<<<NTOK * NH / KR_G, 128>>>(k16, wkrT, bkr, kr);

    // Launch 6: fused flash attention -> a16   (ncu -s 5 captures this)
    flash_attn<<<dim3(S_LEN/128, BATCH*NH), 256, FLASH_SMEM>>>(
        q16, k16, v16, a16, scale);

    // Launch 7 (L4): output = attn @ W_O^T + b -> fp32 d_out
    {
        Job ja = { a16, w16 + OFF_O, bo, out, nullptr, HIDV, HIDV, HIDV, HIDV };
        gemm_h<<<dim3(16, NTOK/BM), 128, GEMM_SMEM>>>(ja, ja, ja, 16, 16);
    }
}

// round 10
// speedup vs baseline: 9.3177x; 1.1332x over previous
#include <cuda_runtime.h>
#include <cuda_fp16.h>
#include <math.h>
#include <stdint.h>

#define S_LEN 1024
#define BATCH 2
#define HIDV  2048
#define NH    16
#define HD    128
#define RR    64
#define KVC   512
#define QCV   1536
#define NTOK  (BATCH*S_LEN)   /* 2048 */

// ---------------- scratch (static device globals; no allocation) ----------------
__device__ __align__(256) __half g_h16 [NTOK*(size_t)HIDV];
__device__ __align__(256) __half g_ckv16[NTOK*(size_t)KVC];
__device__ __align__(256) __half g_cq16 [NTOK*(size_t)QCV];
__device__ __align__(256) __half g_k16 [NTOK*(size_t)HIDV];
__device__ __align__(256) __half g_v16 [NTOK*(size_t)HIDV];
__device__ __align__(256) __half g_q16 [NTOK*(size_t)HIDV];
__device__ __align__(256) __half g_a16 [NTOK*(size_t)HIDV];
__device__ __align__(256) float  g_wkrT[HD*RR];
#define OFF_DKV 0
#define OFF_UK  (OFF_DKV + KVC*HIDV)
#define OFF_UV  (OFF_UK  + HIDV*KVC)
#define OFF_DQ  (OFF_UV  + HIDV*KVC)
#define OFF_UQ  (OFF_DQ  + QCV*HIDV)
#define OFF_O   (OFF_UQ  + HIDV*QCV)
#define W16_TOTAL (OFF_O + HIDV*HIDV)
__device__ __align__(256) __half g_w16[W16_TOTAL];

// ---------------- PTX helpers ----------------
#define MMA_F16(d, a, b) \
    asm volatile("mma.sync.aligned.m16n8k16.row.col.f32.f16.f16.f32 " \
        "{%0,%1,%2,%3}, {%4,%5,%6,%7}, {%8,%9}, {%0,%1,%2,%3};" \
        : "+f"(d[0]), "+f"(d[1]), "+f"(d[2]), "+f"(d[3]) \
        : "r"(a[0]), "r"(a[1]), "r"(a[2]), "r"(a[3]), "r"(b[0]), "r"(b[1]))

#define LDSM_X4(r0,r1,r2,r3,addr) \
    asm volatile("ldmatrix.sync.aligned.m8n8.x4.shared.b16 {%0,%1,%2,%3}, [%4];" \
        : "=r"(r0),"=r"(r1),"=r"(r2),"=r"(r3) : "r"(addr))
#define LDSM_X4_T(r0,r1,r2,r3,addr) \
    asm volatile("ldmatrix.sync.aligned.m8n8.x4.trans.shared.b16 {%0,%1,%2,%3}, [%4];" \
        : "=r"(r0),"=r"(r1),"=r"(r2),"=r"(r3) : "r"(addr))

#define CP_ASYNC16(dst_sm, src) \
    asm volatile("cp.async.cg.shared.global [%0], [%1], 16;" \
        :: "r"(dst_sm), "l"(src))
#define CP_COMMIT() asm volatile("cp.async.commit_group;" ::: "memory")
#define CP_WAIT(n)  asm volatile("cp.async.wait_group %0;" :: "n"(n) : "memory")

__device__ __forceinline__ uint32_t pack_h2(float a, float b) {
    __half2 h = __floats2half2_rn(a, b);
    return *reinterpret_cast<uint32_t*>(&h);
}

// ---------------------------------------------------------------------------
// Merged fp32 -> fp16 conversion over 7 segments
// ---------------------------------------------------------------------------
struct C7 {
    const float4* s[7];
    __half2*      d[7];
    int cum[8];
};

__global__ void __launch_bounds__(256)
cvt_multi(C7 j)
{
    int i = blockIdx.x * 256 + threadIdx.x;
    if (i >= j.cum[7]) return;
    int k = 0;
    #pragma unroll
    for (int q = 1; q < 7; q++) if (i >= j.cum[q]) k = q;
    int loc = i - j.cum[k];
    float4 v = j.s[k][loc];
    j.d[k][2*loc]   = __floats2half2_rn(v.x, v.y);
    j.d[k][2*loc+1] = __floats2half2_rn(v.z, v.w);
}

// ---------------------------------------------------------------------------
__global__ void __launch_bounds__(256)
wkr_t(const float* __restrict__ Wkr, float* __restrict__ WkrT)
{
    int i = blockIdx.x * 256 + threadIdx.x;
    if (i < HD * RR) {
        int c = i >> 6, r = i & 63;
        WkrT[i] = Wkr[r * HD + c];
    }
}

// ---------------------------------------------------------------------------
// Multi-job fp16 GEMM:  C = A @ B^T + bias (fp32 acc)
// Tile 128x128x64, 256 threads (8 warps, warp tile 32x64), 3-stage cp.async.
// ---------------------------------------------------------------------------
#define BM 128
#define BN 128
#define BK 64
#define ASTR 72
#define ST_HALVES (128*ASTR)
#define GEMM_SMEM (3*2*ST_HALVES*2)   /* 110592 B, 2 CTAs/SM */

struct Job {
    const __half* A; const __half* B; const float* bias;
    float* C; __half* C16;
    int K, lda, ldb, ldc;
};

__global__ void __launch_bounds__(256, 2)
gemm_h(Job j0, Job j1, Job j2, int b1, int b2)
{
    extern __shared__ __half smh[];

    int bx = blockIdx.x;
    Job jb; int nOff;
    if (bx < b1)      { jb = j0; nOff = 0;  }
    else if (bx < b2) { jb = j1; nOff = b1; }
    else              { jb = j2; nOff = b2; }

    int K = jb.K, lda = jb.lda, ldb = jb.ldb, ldc = jb.ldc;

    int tid  = threadIdx.x;
    int warp = tid >> 5, lane = tid & 31;
    int wm = (warp >> 1) * 32;      // 4 m-warps of 32 rows
    int wn = (warp & 1) * 64;       // 2 n-warps of 64 cols
    int g  = lane >> 2, tg = lane & 3;

    int m0 = blockIdx.y * BM, n0 = (bx - nOff) * BN;

    // cp.async mapping: 256 threads; thread -> (row = tid>>1, half-row half)
    int prow = tid >> 1;
    int pcol = (tid & 1) * 32;      // halves
    const __half* Ag = jb.A + (long)(m0 + prow) * lda + pcol;
    const __half* Bg = jb.B + (long)(n0 + prow) * ldb + pcol;
    unsigned uBase = (unsigned)__cvta_generic_to_shared(smh);
    unsigned dBase = uBase + (prow * ASTR + pcol) * 2;

    float acc[2][8][4];
    #pragma unroll
    for (int i = 0; i < 2; i++)
        #pragma unroll
        for (int j = 0; j < 8; j++)
            #pragma unroll
            for (int r = 0; r < 4; r++) acc[i][j][r] = 0.f;

    int nk = K / BK;

    auto issue = [&](int stage, int k0) {
        unsigned dA = dBase + stage * 2 * ST_HALVES * 2;
        unsigned dB = dA + ST_HALVES * 2;
        #pragma unroll
        for (int c = 0; c < 4; c++) {
            CP_ASYNC16(dA + c * 16, Ag + k0 + c * 8);
            CP_ASYNC16(dB + c * 16, Bg + k0 + c * 8);
        }
        CP_COMMIT();
    };

    issue(0, 0);
    if (nk > 1) issue(1, BK);
    if (nk > 1) CP_WAIT(1); else CP_WAIT(0);
    __syncthreads();

    int aRow = lane & 15;
    int aK   = (lane >> 4) * 8;
    int bRow = (lane & 7) + ((lane >> 4) & 1) * 8;
    int bK   = ((lane >> 3) & 1) * 8;

    for (int t = 0; t < nk; t++) {
        bool more = (t + 2 < nk);
        if (more) issue((t + 2) % 3, (t + 2) * BK);

        unsigned uA = uBase + (t % 3) * 2 * ST_HALVES * 2;
        unsigned uB = uA + ST_HALVES * 2;

        #pragma unroll
        for (int ks = 0; ks < 4; ks++) {
            int kb = ks * 16;
            unsigned a[2][4], b[8][2];
            #pragma unroll
            for (int i = 0; i < 2; i++) {
                unsigned ad = uA + ((wm + i*16 + aRow) * ASTR + kb + aK) * 2;
                LDSM_X4(a[i][0], a[i][1], a[i][2], a[i][3], ad);
            }
            #pragma unroll
            for (int jg = 0; jg < 4; jg++) {
                unsigned bd = uB + ((wn + jg*16 + bRow) * ASTR + kb + bK) * 2;
                LDSM_X4(b[2*jg][0], b[2*jg][1], b[2*jg+1][0], b[2*jg+1][1], bd);
            }
            #pragma unroll
            for (int i = 0; i < 2; i++)
                #pragma unroll
                for (int j = 0; j < 8; j++)
                    MMA_F16(acc[i][j], a[i], b[j]);
        }

        if (more) CP_WAIT(1); else CP_WAIT(0);
        __syncthreads();
    }

    #pragma unroll
    for (int i = 0; i < 2; i++) {
        int row0 = m0 + wm + i * 16 + g;
        #pragma unroll
        for (int j = 0; j < 8; j++) {
            int col = n0 + wn + j * 8 + tg * 2;
            float b0 = jb.bias ? jb.bias[col] : 0.f;
            float b1 = jb.bias ? jb.bias[col + 1] : 0.f;
            float v00 = acc[i][j][0] + b0, v01 = acc[i][j][1] + b1;
            float v10 = acc[i][j][2] + b0, v11 = acc[i][j][3] + b1;
            if (jb.C) {
                *(float2*)&jb.C[(long)row0 * ldc + col]       = make_float2(v00, v01);
                *(float2*)&jb.C[(long)(row0 + 8) * ldc + col] = make_float2(v10, v11);
            }
            if (jb.C16) {
                *(__half2*)&jb.C16[(long)row0 * ldc + col]       = __floats2half2_rn(v00, v01);
                *(__half2*)&jb.C16[(long)(row0 + 8) * ldc + col] = __floats2half2_rn(v10, v11);
            }
        }
    }
}

// ---------------------------------------------------------------------------
// kr_rope v2 (unchanged from R9 — the big win)
// ---------------------------------------------------------------------------
#define KR_G 32

__global__ void __launch_bounds__(128)
kr_rope2(const __half* __restrict__ k16, const float* __restrict__ WkrT,
         const float* __restrict__ bkr, float* __restrict__ out)
{
    __shared__ float sW[HD * RR];
    __shared__ float sKV[KR_G * HD];

    int tid = threadIdx.x;
    int warp = tid >> 5, lane = tid & 31;

    #pragma unroll
    for (int i = tid; i < HD * RR; i += 128) sW[i] = WkrT[i];

    const __half2* src = (const __half2*)(k16 + (size_t)blockIdx.x * KR_G * HD);
    #pragma unroll
    for (int i = tid; i < KR_G * HD / 2; i += 128) {
        float2 f = __half22float2(src[i]);
        sKV[2*i] = f.x; sKV[2*i + 1] = f.y;
    }
    __syncthreads();

    float b0 = bkr[lane], b1 = bkr[lane + 32];
    float inv_freq = expf(-(float)lane * 0.28782313662425573f);

    for (int p = warp; p < KR_G; p += 4) {
        const float* kv = &sKV[p * HD];
        float a0 = b0, a1 = b1;
        #pragma unroll 8
        for (int c = 0; c < HD; c++) {
            float kvc = kv[c];
            a0 += kvc * sW[c * RR + lane];
            a1 += kvc * sW[c * RR + lane + 32];
        }
        int gidx = blockIdx.x * KR_G + p;
        int t = gidx >> 4, h = gidx & 15;
        int s = t & (S_LEN - 1);
        float sn, cs;
        sincosf((float)s * inv_freq, &sn, &cs);
        long o = (long)t * (NH * RR) + h * RR + lane;
        out[o]      = a0 * cs - a1 * sn;
        out[o + 32] = a1 * cs + a0 * sn;
    }
}

// ---------------------------------------------------------------------------
// Fused fp16 flash attention (unchanged from R8/R9 — passing)
// ---------------------------------------------------------------------------
#define QSTR 136
#define FK 64
#define SH_Q 0
#define SH_K (SH_Q + 128*QSTR)
#define SH_V (SH_K + 2*FK*QSTR)
#define FLASH_SMEM ((SH_V + 2*FK*QSTR) * 2)

__global__ void __launch_bounds__(256, 2)
flash_attn(const __half* __restrict__ Qg, const __half* __restrict__ Kg,
           const __half* __restrict__ Vg, __half* __restrict__ Og, float scale)
{
    extern __shared__ __half smh[];
    unsigned uS = (unsigned)__cvta_generic_to_shared(smh);

    int tid = threadIdx.x;
    int warp = tid >> 5, lane = tid & 31;
    int g = lane >> 2, tg = lane & 3;
    int wm = warp * 16;

    int z  = blockIdx.y;
    int bb = z / NH, hh = z % NH;
    long tok0 = (long)bb * S_LEN + blockIdx.x * 128;
    const __half* Qb = Qg + tok0 * HIDV + hh * HD;
    const __half* Kb = Kg + (long)bb * S_LEN * HIDV + hh * HD;
    const __half* Vb = Vg + (long)bb * S_LEN * HIDV + hh * HD;

    #pragma unroll
    for (int i = 0; i < 8; i++) {
        int s = tid + i * 256;
        int row = s >> 4, ch = s & 15;
        CP_ASYNC16(uS + (SH_Q + row * QSTR + ch * 8) * 2,
                   Qb + (long)row * HIDV + ch * 8);
    }
    CP_COMMIT();

    auto issueKV = [&](int st, int kt) {
        #pragma unroll
        for (int i = 0; i < 4; i++) {
            int s = tid + i * 256;
            int row = s >> 4, ch = s & 15;
            long goff = (long)(kt * FK + row) * HIDV + ch * 8;
            CP_ASYNC16(uS + (SH_K + st * FK * QSTR + row * QSTR + ch * 8) * 2, Kb + goff);
            CP_ASYNC16(uS + (SH_V + st * FK * QSTR + row * QSTR + ch * 8) * 2, Vb + goff);
        }
        CP_COMMIT();
    };
    issueKV(0, 0);

    float m0 = -1e30f, m1 = -1e30f, l0 = 0.f, l1 = 0.f;
    float o[16][4];
    #pragma unroll
    for (int j = 0; j < 16; j++)
        #pragma unroll
        for (int r = 0; r < 4; r++) o[j][r] = 0.f;

    int aRow = lane & 15;
    int aK   = (lane >> 4) * 8;
    int bRow = (lane & 7) + ((lane >> 4) & 1) * 8;
    int bK   = ((lane >> 3) & 1) * 8;
    int vK   = (lane & 7) + ((lane >> 3) & 1) * 8;
    int vN   = ((lane >> 4) & 1) * 8;

    for (int kt = 0; kt < S_LEN / FK; kt++) {
        CP_WAIT(0);
        __syncthreads();
        if (kt + 1 < S_LEN / FK) issueKV((kt + 1) & 1, kt + 1);

        int kOff = SH_K + (kt & 1) * FK * QSTR;
        int vOff = SH_V + (kt & 1) * FK * QSTR;

        float s_acc[8][4];
        #pragma unroll
        for (int j = 0; j < 8; j++)
            #pragma unroll
            for (int r = 0; r < 4; r++) s_acc[j][r] = 0.f;

        #pragma unroll
        for (int ks = 0; ks < 8; ks++) {
            int kb = ks * 16;
            unsigned a[4];
            LDSM_X4(a[0], a[1], a[2], a[3],
                uS + (SH_Q + (wm + aRow) * QSTR + kb + aK) * 2);
            #pragma unroll
            for (int jg = 0; jg < 4; jg++) {
                unsigned b0[2], b1[2];
                LDSM_X4(b0[0], b0[1], b1[0], b1[1],
                    uS + (kOff + (jg*16 + bRow) * QSTR + kb + bK) * 2);
                MMA_F16(s_acc[2*jg],   a, b0);
                MMA_F16(s_acc[2*jg+1], a, b1);
            }
        }

        #pragma unroll
        for (int j = 0; j < 8; j++)
            #pragma unroll
            for (int r = 0; r < 4; r++) s_acc[j][r] *= scale;

        float mx0 = -1e30f, mx1 = -1e30f;
        #pragma unroll
        for (int j = 0; j < 8; j++) {
            mx0 = fmaxf(mx0, fmaxf(s_acc[j][0], s_acc[j][1]));
            mx1 = fmaxf(mx1, fmaxf(s_acc[j][2], s_acc[j][3]));
        }
        mx0 = fmaxf(mx0, __shfl_xor_sync(0xffffffffu, mx0, 1));
        mx0 = fmaxf(mx0, __shfl_xor_sync(0xffffffffu, mx0, 2));
        mx1 = fmaxf(mx1, __shfl_xor_sync(0xffffffffu, mx1, 1));
        mx1 = fmaxf(mx1, __shfl_xor_sync(0xffffffffu, mx1, 2));

        float mn0 = fmaxf(m0, mx0), mn1 = fmaxf(m1, mx1);
        float al0 = __expf(m0 - mn0), al1 = __expf(m1 - mn1);
        float sum0 = 0.f, sum1 = 0.f;
        #pragma unroll
        for (int j = 0; j < 8; j++) {
            float p00 = __expf(s_acc[j][0] - mn0);
            float p01 = __expf(s_acc[j][1] - mn0);
            float p10 = __expf(s_acc[j][2] - mn1);
            float p11 = __expf(s_acc[j][3] - mn1);
            sum0 += p00 + p01; sum1 += p10 + p11;
            s_acc[j][0] = __uint_as_float(pack_h2(p00, p01));
            s_acc[j][1] = __uint_as_float(pack_h2(p10, p11));
        }
        sum0 += __shfl_xor_sync(0xffffffffu, sum0, 1);
        sum0 += __shfl_xor_sync(0xffffffffu, sum0, 2);
        sum1 += __shfl_xor_sync(0xffffffffu, sum1, 1);
        sum1 += __shfl_xor_sync(0xffffffffu, sum1, 2);
        l0 = l0 * al0 + sum0;
        l1 = l1 * al1 + sum1;
        m0 = mn0; m1 = mn1;
        #pragma unroll
        for (int j = 0; j < 16; j++) {
            o[j][0] *= al0; o[j][1] *= al0;
            o[j][2] *= al1; o[j][3] *= al1;
        }

        #pragma unroll
        for (int ks = 0; ks < 4; ks++) {
            int kb = ks * 16;
            unsigned a[4];
            a[0] = __float_as_uint(s_acc[2*ks][0]);
            a[1] = __float_as_uint(s_acc[2*ks][1]);
            a[2] = __float_as_uint(s_acc[2*ks+1][0]);
            a[3] = __float_as_uint(s_acc[2*ks+1][1]);
            #pragma unroll
            for (int ng = 0; ng < 8; ng++) {
                unsigned b0[2], b1[2];
                LDSM_X4_T(b0[0], b0[1], b1[0], b1[1],
                    uS + (vOff + (kb + vK) * QSTR + ng*16 + vN) * 2);
                MMA_F16(o[2*ng],   a, b0);
                MMA_F16(o[2*ng+1], a, b1);
            }
        }
    }

    float inv0 = 1.0f / l0, inv1 = 1.0f / l1;
    __half* Ob = Og + tok0 * HIDV + hh * HD;
    #pragma unroll
    for (int j = 0; j < 16; j++) {
        int col = j * 8 + tg * 2;
        *(__half2*)&Ob[(long)(wm + g) * HIDV + col] =
            __floats2half2_rn(o[j][0] * inv0, o[j][1] * inv0);
        *(__half2*)&Ob[(long)(wm + 8 + g) * HIDV + col] =
            __floats2half2_rn(o[j][2] * inv1, o[j][3] * inv1);
    }
}

// ---------------------------------------------------------------------------
extern "C" void kernel_launch(void* const* d_in, const int* in_sizes, int n_in,
                              void* d_out, int out_size)
{
    const float* hid  = (const float*)d_in[0];
    const float* Wdkv = (const float*)d_in[1];
    const float* bdkv = (const float*)d_in[2];
    const float* Wuk  = (const float*)d_in[3];
    const float* buk  = (const float*)d_in[4];
    const float* Wuv  = (const float*)d_in[5];
    const float* buv  = (const float*)d_in[6];
    const float* Wkr  = (const float*)d_in[7];
    const float* bkr  = (const float*)d_in[8];
    const float* Wdq  = (const float*)d_in[9];
    const float* bdq  = (const float*)d_in[10];
    const float* Wuq  = (const float*)d_in[11];
    const float* buq  = (const float*)d_in[12];
    // d_in[13..14] = W_QR — dead (q_r unused in reference)
    const float* Wo   = (const float*)d_in[15];
    const float* bo   = (const float*)d_in[16];

    float* out  = (float*)d_out;
    float* c_kv = out  + (long)NTOK * HIDV;
    float* kr   = c_kv + (long)NTOK * KVC;

    __half *h16, *ckv16, *cq16, *k16, *v16, *q16, *a16, *w16;
    float  *wkrT;
    cudaGetSymbolAddress((void**)&h16,   g_h16);
    cudaGetSymbolAddress((void**)&ckv16, g_ckv16);
    cudaGetSymbolAddress((void**)&cq16,  g_cq16);
    cudaGetSymbolAddress((void**)&k16,   g_k16);
    cudaGetSymbolAddress((void**)&v16,   g_v16);
    cudaGetSymbolAddress((void**)&q16,   g_q16);
    cudaGetSymbolAddress((void**)&a16,   g_a16);
    cudaGetSymbolAddress((void**)&w16,   g_w16);
    cudaGetSymbolAddress((void**)&wkrT,  g_wkrT);

    const float scale = 0.08838834764831845f;
    static int attr_set = 0;
    if (!attr_set) {
        cudaFuncSetAttribute(gemm_h,
            cudaFuncAttributeMaxDynamicSharedMemorySize, GEMM_SMEM);
        cudaFuncSetAttribute(flash_attn,
            cudaFuncAttributeMaxDynamicSharedMemorySize, FLASH_SMEM);
        attr_set = 1;
    }

    // Launch 1: all fp32->fp16 conversions
    {
        C7 j;
        const float* srcs[7] = { hid, Wdkv, Wuk, Wuv, Wdq, Wuq, Wo };
        __half* dsts[7] = { h16, w16 + OFF_DKV, w16 + OFF_UK, w16 + OFF_UV,
                            w16 + OFF_DQ, w16 + OFF_UQ, w16 + OFF_O };
        int sizes[7] = { NTOK*HIDV, KVC*HIDV, HIDV*KVC, HIDV*KVC,
                         QCV*HIDV, HIDV*QCV, HIDV*HIDV };
        int cum = 0;
        for (int k = 0; k < 7; k++) {
            j.s[k] = (const float4*)srcs[k];
            j.d[k] = (__half2*)dsts[k];
            j.cum[k] = cum;
            cum += sizes[k] / 4;
        }
        j.cum[7] = cum;
        cvt_multi<<<(cum + 255) / 256, 256>>>(j);
    }

    // Launch 2: W_KR transpose
    wkr_t<<<(HD*RR + 255) / 256, 256>>>(Wkr, wkrT);

    // Launch 3 (L1): c_kv + c_q, K=2048
    {
        Job ja = { h16, w16 + OFF_DKV, bdkv, c_kv,   ckv16, HIDV, HIDV, HIDV, KVC };
        Job jb = { h16, w16 + OFF_DQ,  bdq,  nullptr, cq16, HIDV, HIDV, HIDV, QCV };
        gemm_h<<<dim3(16, NTOK/BM), 256, GEMM_SMEM>>>(ja, jb, jb, 4, 16);
    }

    // Launch 4 (L2): k + v (K=512) + q (K=1536)
    {
        Job ja = { ckv16, w16 + OFF_UK, buk, nullptr, k16, KVC, KVC, KVC, HIDV };
        Job jb = { ckv16, w16 + OFF_UV, buv, nullptr, v16, KVC, KVC, KVC, HIDV };
        Job jc = { cq16,  w16 + OFF_UQ, buq, nullptr, q16, QCV, QCV, QCV, HIDV };
        gemm_h<<<dim3(48, NTOK/BM), 256, GEMM_SMEM>>>(ja, jb, jc, 16, 32);
    }

    // Launch 5: k_r (+RoPE)
    kr_rope2<<<NTOK * NH / KR_G, 128>>>(k16, wkrT, bkr, kr);

    // Launch 6: fused flash attention
    flash_attn<<<dim3(S_LEN/128, BATCH*NH), 256, FLASH_SMEM>>>(
        q16, k16, v16, a16, scale);

    // Launch 7 (L4): output = attn @ W_O^T + b
    {
        Job ja = { a16, w16 + OFF_O, bo, out, nullptr, HIDV, HIDV, HIDV, HIDV };
        gemm_h<<<dim3(16, NTOK/BM), 256, GEMM_SMEM>>>(ja, ja, ja, 16, 16);
    }
}

// round 12
// speedup vs baseline: 11.2090x; 1.2030x over previous
#include <cuda_runtime.h>
#include <cuda_fp16.h>
#include <math.h>
#include <stdint.h>

#define S_LEN 1024
#define BATCH 2
#define HIDV  2048
#define NH    16
#define HD    128
#define RR    64
#define KVC   512
#define QCV   1536
#define NTOK  (BATCH*S_LEN)   /* 2048 */

// ---------------- scratch (static device globals; no allocation) ----------------
__device__ __align__(256) __half g_h16 [NTOK*(size_t)HIDV];
__device__ __align__(256) __half g_ckv16[NTOK*(size_t)KVC];
__device__ __align__(256) __half g_cq16 [NTOK*(size_t)QCV];
__device__ __align__(256) __half g_k16 [NTOK*(size_t)HIDV];
__device__ __align__(256) __half g_v16 [NTOK*(size_t)HIDV];
__device__ __align__(256) __half g_q16 [NTOK*(size_t)HIDV];
__device__ __align__(256) __half g_a16 [NTOK*(size_t)HIDV];
__device__ __align__(256) float  g_wkrT[HD*RR];
#define OFF_DKV 0
#define OFF_UK  (OFF_DKV + KVC*HIDV)
#define OFF_UV  (OFF_UK  + HIDV*KVC)
#define OFF_DQ  (OFF_UV  + HIDV*KVC)
#define OFF_UQ  (OFF_DQ  + QCV*HIDV)
#define OFF_O   (OFF_UQ  + HIDV*QCV)
#define W16_TOTAL (OFF_O + HIDV*HIDV)
__device__ __align__(256) __half g_w16[W16_TOTAL];

// ---------------- PTX helpers ----------------
#define MMA_F16(d, a, b) \
    asm volatile("mma.sync.aligned.m16n8k16.row.col.f32.f16.f16.f32 " \
        "{%0,%1,%2,%3}, {%4,%5,%6,%7}, {%8,%9}, {%0,%1,%2,%3};" \
        : "+f"(d[0]), "+f"(d[1]), "+f"(d[2]), "+f"(d[3]) \
        : "r"(a[0]), "r"(a[1]), "r"(a[2]), "r"(a[3]), "r"(b[0]), "r"(b[1]))

#define LDSM_X4(r0,r1,r2,r3,addr) \
    asm volatile("ldmatrix.sync.aligned.m8n8.x4.shared.b16 {%0,%1,%2,%3}, [%4];" \
        : "=r"(r0),"=r"(r1),"=r"(r2),"=r"(r3) : "r"(addr))
#define LDSM_X4_T(r0,r1,r2,r3,addr) \
    asm volatile("ldmatrix.sync.aligned.m8n8.x4.trans.shared.b16 {%0,%1,%2,%3}, [%4];" \
        : "=r"(r0),"=r"(r1),"=r"(r2),"=r"(r3) : "r"(addr))

#define CP_ASYNC16(dst_sm, src) \
    asm volatile("cp.async.cg.shared.global [%0], [%1], 16;" \
        :: "r"(dst_sm), "l"(src))
#define CP_COMMIT() asm volatile("cp.async.commit_group;" ::: "memory")
#define CP_WAIT(n)  asm volatile("cp.async.wait_group %0;" :: "n"(n) : "memory")

__device__ __forceinline__ uint32_t pack_h2(float a, float b) {
    __half2 h = __floats2half2_rn(a, b);
    return *reinterpret_cast<uint32_t*>(&h);
}

// ---------------------------------------------------------------------------
// Merged fp32 -> fp16 conversion over 7 segments
// ---------------------------------------------------------------------------
struct C7 {
    const float4* s[7];
    __half2*      d[7];
    int cum[8];
};

__global__ void __launch_bounds__(256)
cvt_multi(C7 j)
{
    int i = blockIdx.x * 256 + threadIdx.x;
    if (i >= j.cum[7]) return;
    int k = 0;
    #pragma unroll
    for (int q = 1; q < 7; q++) if (i >= j.cum[q]) k = q;
    int loc = i - j.cum[k];
    float4 v = j.s[k][loc];
    j.d[k][2*loc]   = __floats2half2_rn(v.x, v.y);
    j.d[k][2*loc+1] = __floats2half2_rn(v.z, v.w);
}

// ---------------------------------------------------------------------------
__global__ void __launch_bounds__(256)
wkr_t(const float* __restrict__ Wkr, float* __restrict__ WkrT)
{
    int i = blockIdx.x * 256 + threadIdx.x;
    if (i < HD * RR) {
        int c = i >> 6, r = i & 63;
        WkrT[i] = Wkr[r * HD + c];
    }
}

// ---------------------------------------------------------------------------
// Multi-job fp16 GEMM:  C = A @ B^T + bias (fp32 acc)
// CTA tile 256x128x64, 256 threads (8 warps as 4m x 2n, warp tile 64x64),
// 3-stage cp.async, 1 CTA/SM.
// ---------------------------------------------------------------------------
#define BM 256
#define BN 128
#define BK 64
#define ASTR 72
#define A_HALVES (BM*ASTR)              /* 18432 */
#define B_HALVES (BN*ASTR)              /* 9216 */
#define STG_HALVES (A_HALVES + B_HALVES)
#define GEMM_SMEM (3*STG_HALVES*2)      /* 165888 B, 1 CTA/SM */

struct Job {
    const __half* A; const __half* B; const float* bias;
    float* C; __half* C16;
    int K, lda, ldb, ldc;
};

__global__ void __launch_bounds__(256, 1)
gemm_h(Job j0, Job j1, Job j2, int b1, int b2)
{
    extern __shared__ __half smh[];

    int bx = blockIdx.x;
    Job jb; int nOff;
    if (bx < b1)      { jb = j0; nOff = 0;  }
    else if (bx < b2) { jb = j1; nOff = b1; }
    else              { jb = j2; nOff = b2; }

    int K = jb.K, lda = jb.lda, ldb = jb.ldb, ldc = jb.ldc;

    int tid  = threadIdx.x;
    int warp = tid >> 5, lane = tid & 31;
    int wm = (warp >> 1) * 64;      // 4 m-warps x 64 rows
    int wn = (warp & 1) * 64;       // 2 n-warps x 64 cols
    int g  = lane >> 2, tg = lane & 3;

    int m0 = blockIdx.y * BM, n0 = (bx - nOff) * BN;

    // cp.async mapping: thread -> row (tid>>3: 0..31), chunk (tid&7: full row)
    int arow = tid >> 3;            // 0..31
    int acol = (tid & 7) * 8;       // halves, 8 chunks cover BK=64
    const __half* Ag = jb.A + (long)(m0 + arow) * lda + acol;
    const __half* Bg = jb.B + (long)(n0 + arow) * ldb + acol;
    unsigned uBase = (unsigned)__cvta_generic_to_shared(smh);
    unsigned dOff  = (arow * ASTR + acol) * 2;

    float acc[4][8][4];
    #pragma unroll
    for (int i = 0; i < 4; i++)
        #pragma unroll
        for (int j = 0; j < 8; j++)
            #pragma unroll
            for (int r = 0; r < 4; r++) acc[i][j][r] = 0.f;

    int nk = K / BK;

    auto issue = [&](int stage, int k0) {
        unsigned dA = uBase + stage * STG_HALVES * 2 + dOff;
        unsigned dB = dA + A_HALVES * 2;
        #pragma unroll
        for (int i = 0; i < 8; i++)   // A: 8 x 32 rows = 256
            CP_ASYNC16(dA + i * 32 * ASTR * 2, Ag + k0 + (long)i * 32 * lda);
        #pragma unroll
        for (int i = 0; i < 4; i++)   // B: 4 x 32 rows = 128
            CP_ASYNC16(dB + i * 32 * ASTR * 2, Bg + k0 + (long)i * 32 * ldb);
        CP_COMMIT();
    };

    issue(0, 0);
    if (nk > 1) issue(1, BK);
    if (nk > 1) CP_WAIT(1); else CP_WAIT(0);
    __syncthreads();

    int aRow = lane & 15;
    int aK   = (lane >> 4) * 8;
    int bRow = (lane & 7) + ((lane >> 4) & 1) * 8;
    int bK   = ((lane >> 3) & 1) * 8;

    for (int t = 0; t < nk; t++) {
        bool more = (t + 2 < nk);
        if (more) issue((t + 2) % 3, (t + 2) * BK);

        unsigned uA = uBase + (t % 3) * STG_HALVES * 2;
        unsigned uB = uA + A_HALVES * 2;

        #pragma unroll
        for (int ks = 0; ks < 4; ks++) {
            int kb = ks * 16;
            unsigned a[4][4], b[8][2];
            #pragma unroll
            for (int i = 0; i < 4; i++) {
                unsigned ad = uA + ((wm + i*16 + aRow) * ASTR + kb + aK) * 2;
                LDSM_X4(a[i][0], a[i][1], a[i][2], a[i][3], ad);
            }
            #pragma unroll
            for (int jg = 0; jg < 4; jg++) {
                unsigned bd = uB + ((wn + jg*16 + bRow) * ASTR + kb + bK) * 2;
                LDSM_X4(b[2*jg][0], b[2*jg][1], b[2*jg+1][0], b[2*jg+1][1], bd);
            }
            #pragma unroll
            for (int i = 0; i < 4; i++)
                #pragma unroll
                for (int j = 0; j < 8; j++)
                    MMA_F16(acc[i][j], a[i], b[j]);
        }

        if (more) CP_WAIT(1); else CP_WAIT(0);
        __syncthreads();
    }

    #pragma unroll
    for (int i = 0; i < 4; i++) {
        int row0 = m0 + wm + i * 16 + g;
        #pragma unroll
        for (int j = 0; j < 8; j++) {
            int col = n0 + wn + j * 8 + tg * 2;
            float b0 = jb.bias ? jb.bias[col] : 0.f;
            float b1 = jb.bias ? jb.bias[col + 1] : 0.f;
            float v00 = acc[i][j][0] + b0, v01 = acc[i][j][1] + b1;
            float v10 = acc[i][j][2] + b0, v11 = acc[i][j][3] + b1;
            if (jb.C) {
                *(float2*)&jb.C[(long)row0 * ldc + col]       = make_float2(v00, v01);
                *(float2*)&jb.C[(long)(row0 + 8) * ldc + col] = make_float2(v10, v11);
            }
            if (jb.C16) {
                *(__half2*)&jb.C16[(long)row0 * ldc + col]       = __floats2half2_rn(v00, v01);
                *(__half2*)&jb.C16[(long)(row0 + 8) * ldc + col] = __floats2half2_rn(v10, v11);
            }
        }
    }
}

// ---------------------------------------------------------------------------
// kr_rope v2 (unchanged)
// ---------------------------------------------------------------------------
#define KR_G 32

__global__ void __launch_bounds__(128)
kr_rope2(const __half* __restrict__ k16, const float* __restrict__ WkrT,
         const float* __restrict__ bkr, float* __restrict__ out)
{
    __shared__ float sW[HD * RR];
    __shared__ float sKV[KR_G * HD];

    int tid = threadIdx.x;
    int warp = tid >> 5, lane = tid & 31;

    #pragma unroll
    for (int i = tid; i < HD * RR; i += 128) sW[i] = WkrT[i];

    const __half2* src = (const __half2*)(k16 + (size_t)blockIdx.x * KR_G * HD);
    #pragma unroll
    for (int i = tid; i < KR_G * HD / 2; i += 128) {
        float2 f = __half22float2(src[i]);
        sKV[2*i] = f.x; sKV[2*i + 1] = f.y;
    }
    __syncthreads();

    float b0 = bkr[lane], b1 = bkr[lane + 32];
    float inv_freq = expf(-(float)lane * 0.28782313662425573f);

    for (int p = warp; p < KR_G; p += 4) {
        const float* kv = &sKV[p * HD];
        float a0 = b0, a1 = b1;
        #pragma unroll 8
        for (int c = 0; c < HD; c++) {
            float kvc = kv[c];
            a0 += kvc * sW[c * RR + lane];
            a1 += kvc * sW[c * RR + lane + 32];
        }
        int gidx = blockIdx.x * KR_G + p;
        int t = gidx >> 4, h = gidx & 15;
        int s = t & (S_LEN - 1);
        float sn, cs;
        sincosf((float)s * inv_freq, &sn, &cs);
        long o = (long)t * (NH * RR) + h * RR + lane;
        out[o]      = a0 * cs - a1 * sn;
        out[o + 32] = a1 * cs + a0 * sn;
    }
}

// ---------------------------------------------------------------------------
// Fused fp16 flash attention (unchanged — passing)
// ---------------------------------------------------------------------------
#define QSTR 136
#define FK 64
#define SH_Q 0
#define SH_K (SH_Q + 128*QSTR)
#define SH_V (SH_K + 2*FK*QSTR)
#define FLASH_SMEM ((SH_V + 2*FK*QSTR) * 2)

__global__ void __launch_bounds__(256, 2)
flash_attn(const __half* __restrict__ Qg, const __half* __restrict__ Kg,
           const __half* __restrict__ Vg, __half* __restrict__ Og, float scale)
{
    extern __shared__ __half smh[];
    unsigned uS = (unsigned)__cvta_generic_to_shared(smh);

    int tid = threadIdx.x;
    int warp = tid >> 5, lane = tid & 31;
    int g = lane >> 2, tg = lane & 3;
    int wm = warp * 16;

    int z  = blockIdx.y;
    int bb = z / NH, hh = z % NH;
    long tok0 = (long)bb * S_LEN + blockIdx.x * 128;
    const __half* Qb = Qg + tok0 * HIDV + hh * HD;
    const __half* Kb = Kg + (long)bb * S_LEN * HIDV + hh * HD;
    const __half* Vb = Vg + (long)bb * S_LEN * HIDV + hh * HD;

    #pragma unroll
    for (int i = 0; i < 8; i++) {
        int s = tid + i * 256;
        int row = s >> 4, ch = s & 15;
        CP_ASYNC16(uS + (SH_Q + row * QSTR + ch * 8) * 2,
                   Qb + (long)row * HIDV + ch * 8);
    }
    CP_COMMIT();

    auto issueKV = [&](int st, int kt) {
        #pragma unroll
        for (int i = 0; i < 4; i++) {
            int s = tid + i * 256;
            int row = s >> 4, ch = s & 15;
            long goff = (long)(kt * FK + row) * HIDV + ch * 8;
            CP_ASYNC16(uS + (SH_K + st * FK * QSTR + row * QSTR + ch * 8) * 2, Kb + goff);
            CP_ASYNC16(uS + (SH_V + st * FK * QSTR + row * QSTR + ch * 8) * 2, Vb + goff);
        }
        CP_COMMIT();
    };
    issueKV(0, 0);

    float m0 = -1e30f, m1 = -1e30f, l0 = 0.f, l1 = 0.f;
    float o[16][4];
    #pragma unroll
    for (int j = 0; j < 16; j++)
        #pragma unroll
        for (int r = 0; r < 4; r++) o[j][r] = 0.f;

    int aRow = lane & 15;
    int aK   = (lane >> 4) * 8;
    int bRow = (lane & 7) + ((lane >> 4) & 1) * 8;
    int bK   = ((lane >> 3) & 1) * 8;
    int vK   = (lane & 7) + ((lane >> 3) & 1) * 8;
    int vN   = ((lane >> 4) & 1) * 8;

    for (int kt = 0; kt < S_LEN / FK; kt++) {
        CP_WAIT(0);
        __syncthreads();
        if (kt + 1 < S_LEN / FK) issueKV((kt + 1) & 1, kt + 1);

        int kOff = SH_K + (kt & 1) * FK * QSTR;
        int vOff = SH_V + (kt & 1) * FK * QSTR;

        float s_acc[8][4];
        #pragma unroll
        for (int j = 0; j < 8; j++)
            #pragma unroll
            for (int r = 0; r < 4; r++) s_acc[j][r] = 0.f;

        #pragma unroll
        for (int ks = 0; ks < 8; ks++) {
            int kb = ks * 16;
            unsigned a[4];
            LDSM_X4(a[0], a[1], a[2], a[3],
                uS + (SH_Q + (wm + aRow) * QSTR + kb + aK) * 2);
            #pragma unroll
            for (int jg = 0; jg < 4; jg++) {
                unsigned b0[2], b1[2];
                LDSM_X4(b0[0], b0[1], b1[0], b1[1],
                    uS + (kOff + (jg*16 + bRow) * QSTR + kb + bK) * 2);
                MMA_F16(s_acc[2*jg],   a, b0);
                MMA_F16(s_acc[2*jg+1], a, b1);
            }
        }

        #pragma unroll
        for (int j = 0; j < 8; j++)
            #pragma unroll
            for (int r = 0; r < 4; r++) s_acc[j][r] *= scale;

        float mx0 = -1e30f, mx1 = -1e30f;
        #pragma unroll
        for (int j = 0; j < 8; j++) {
            mx0 = fmaxf(mx0, fmaxf(s_acc[j][0], s_acc[j][1]));
            mx1 = fmaxf(mx1, fmaxf(s_acc[j][2], s_acc[j][3]));
        }
        mx0 = fmaxf(mx0, __shfl_xor_sync(0xffffffffu, mx0, 1));
        mx0 = fmaxf(mx0, __shfl_xor_sync(0xffffffffu, mx0, 2));
        mx1 = fmaxf(mx1, __shfl_xor_sync(0xffffffffu, mx1, 1));
        mx1 = fmaxf(mx1, __shfl_xor_sync(0xffffffffu, mx1, 2));

        float mn0 = fmaxf(m0, mx0), mn1 = fmaxf(m1, mx1);
        float al0 = __expf(m0 - mn0), al1 = __expf(m1 - mn1);
        float sum0 = 0.f, sum1 = 0.f;
        #pragma unroll
        for (int j = 0; j < 8; j++) {
            float p00 = __expf(s_acc[j][0] - mn0);
            float p01 = __expf(s_acc[j][1] - mn0);
            float p10 = __expf(s_acc[j][2] - mn1);
            float p11 = __expf(s_acc[j][3] - mn1);
            sum0 += p00 + p01; sum1 += p10 + p11;
            s_acc[j][0] = __uint_as_float(pack_h2(p00, p01));
            s_acc[j][1] = __uint_as_float(pack_h2(p10, p11));
        }
        sum0 += __shfl_xor_sync(0xffffffffu, sum0, 1);
        sum0 += __shfl_xor_sync(0xffffffffu, sum0, 2);
        sum1 += __shfl_xor_sync(0xffffffffu, sum1, 1);
        sum1 += __shfl_xor_sync(0xffffffffu, sum1, 2);
        l0 = l0 * al0 + sum0;
        l1 = l1 * al1 + sum1;
        m0 = mn0; m1 = mn1;
        #pragma unroll
        for (int j = 0; j < 16; j++) {
            o[j][0] *= al0; o[j][1] *= al0;
            o[j][2] *= al1; o[j][3] *= al1;
        }

        #pragma unroll
        for (int ks = 0; ks < 4; ks++) {
            int kb = ks * 16;
            unsigned a[4];
            a[0] = __float_as_uint(s_acc[2*ks][0]);
            a[1] = __float_as_uint(s_acc[2*ks][1]);
            a[2] = __float_as_uint(s_acc[2*ks+1][0]);
            a[3] = __float_as_uint(s_acc[2*ks+1][1]);
            #pragma unroll
            for (int ng = 0; ng < 8; ng++) {
                unsigned b0[2], b1[2];
                LDSM_X4_T(b0[0], b0[1], b1[0], b1[1],
                    uS + (vOff + (kb + vK) * QSTR + ng*16 + vN) * 2);
                MMA_F16(o[2*ng],   a, b0);
                MMA_F16(o[2*ng+1], a, b1);
            }
        }
    }

    float inv0 = 1.0f / l0, inv1 = 1.0f / l1;
    __half* Ob = Og + tok0 * HIDV + hh * HD;
    #pragma unroll
    for (int j = 0; j < 16; j++) {
        int col = j * 8 + tg * 2;
        *(__half2*)&Ob[(long)(wm + g) * HIDV + col] =
            __floats2half2_rn(o[j][0] * inv0, o[j][1] * inv0);
        *(__half2*)&Ob[(long)(wm + 8 + g) * HIDV + col] =
            __floats2half2_rn(o[j][2] * inv1, o[j][3] * inv1);
    }
}

// ---------------------------------------------------------------------------
extern "C" void kernel_launch(void* const* d_in, const int* in_sizes, int n_in,
                              void* d_out, int out_size)
{
    const float* hid  = (const float*)d_in[0];
    const float* Wdkv = (const float*)d_in[1];
    const float* bdkv = (const float*)d_in[2];
    const float* Wuk  = (const float*)d_in[3];
    const float* buk  = (const float*)d_in[4];
    const float* Wuv  = (const float*)d_in[5];
    const float* buv  = (const float*)d_in[6];
    const float* Wkr  = (const float*)d_in[7];
    const float* bkr  = (const float*)d_in[8];
    const float* Wdq  = (const float*)d_in[9];
    const float* bdq  = (const float*)d_in[10];
    const float* Wuq  = (const float*)d_in[11];
    const float* buq  = (const float*)d_in[12];
    // d_in[13..14] = W_QR — dead (q_r unused in reference)
    const float* Wo   = (const float*)d_in[15];
    const float* bo   = (const float*)d_in[16];

    float* out  = (float*)d_out;
    float* c_kv = out  + (long)NTOK * HIDV;
    float* kr   = c_kv + (long)NTOK * KVC;

    __half *h16, *ckv16, *cq16, *k16, *v16, *q16, *a16, *w16;
    float  *wkrT;
    cudaGetSymbolAddress((void**)&h16,   g_h16);
    cudaGetSymbolAddress((void**)&ckv16, g_ckv16);
    cudaGetSymbolAddress((void**)&cq16,  g_cq16);
    cudaGetSymbolAddress((void**)&k16,   g_k16);
    cudaGetSymbolAddress((void**)&v16,   g_v16);
    cudaGetSymbolAddress((void**)&q16,   g_q16);
    cudaGetSymbolAddress((void**)&a16,   g_a16);
    cudaGetSymbolAddress((void**)&w16,   g_w16);
    cudaGetSymbolAddress((void**)&wkrT,  g_wkrT);

    const float scale = 0.08838834764831845f;
    static int attr_set = 0;
    if (!attr_set) {
        cudaFuncSetAttribute(gemm_h,
            cudaFuncAttributeMaxDynamicSharedMemorySize, GEMM_SMEM);
        cudaFuncSetAttribute(flash_attn,
            cudaFuncAttributeMaxDynamicSharedMemorySize, FLASH_SMEM);
        attr_set = 1;
    }

    // Launch 1: all fp32->fp16 conversions
    {
        C7 j;
        const float* srcs[7] = { hid, Wdkv, Wuk, Wuv, Wdq, Wuq, Wo };
        __half* dsts[7] = { h16, w16 + OFF_DKV, w16 + OFF_UK, w16 + OFF_UV,
                            w16 + OFF_DQ, w16 + OFF_UQ, w16 + OFF_O };
        int sizes[7] = { NTOK*HIDV, KVC*HIDV, HIDV*KVC, HIDV*KVC,
                         QCV*HIDV, HIDV*QCV, HIDV*HIDV };
        int cum = 0;
        for (int k = 0; k < 7; k++) {
            j.s[k] = (const float4*)srcs[k];
            j.d[k] = (__half2*)dsts[k];
            j.cum[k] = cum;
            cum += sizes[k] / 4;
        }
        j.cum[7] = cum;
        cvt_multi<<<(cum + 255) / 256, 256>>>(j);
    }

    // Launch 2: W_KR transpose
    wkr_t<<<(HD*RR + 255) / 256, 256>>>(Wkr, wkrT);

    // Launch 3 (L1): c_kv (4 n-tiles) + c_q (12 n-tiles), K=2048. grid 16 x 8
    {
        Job ja = { h16, w16 + OFF_DKV, bdkv, c_kv,   ckv16, HIDV, HIDV, HIDV, KVC };
        Job jb = { h16, w16 + OFF_DQ,  bdq,  nullptr, cq16, HIDV, HIDV, HIDV, QCV };
        gemm_h<<<dim3(16, NTOK/BM), 256, GEMM_SMEM>>>(ja, jb, jb, 4, 16);
    }

    // Launch 4 (L2): k + v (K=512) + q (K=1536), 16 n-tiles each. grid 48 x 8
    {
        Job ja = { ckv16, w16 + OFF_UK, buk, nullptr, k16, KVC, KVC, KVC, HIDV };
        Job jb = { ckv16, w16 + OFF_UV, buv, nullptr, v16, KVC, KVC, KVC, HIDV };
        Job jc = { cq16,  w16 + OFF_UQ, buq, nullptr, q16, QCV, QCV, QCV, HIDV };
        gemm_h<<<dim3(48, NTOK/BM), 256, GEMM_SMEM>>>(ja, jb, jc, 16, 32);
    }

    // Launch 5: k_r (+RoPE)
    kr_rope2<<<NTOK * NH / KR_G, 128>>>(k16, wkrT, bkr, kr);

    // Launch 6: fused flash attention
    flash_attn<<<dim3(S_LEN/128, BATCH*NH), 256, FLASH_SMEM>>>(
        q16, k16, v16, a16, scale);

    // Launch 7 (L4): output = attn @ W_O^T + b. grid 16 x 8
    {
        Job ja = { a16, w16 + OFF_O, bo, out, nullptr, HIDV, HIDV, HIDV, HIDV };
        gemm_h<<<dim3(16, NTOK/BM), 256, GEMM_SMEM>>>(ja, ja, ja, 16, 16);
    }
}